// round 1
// baseline (speedup 1.0000x reference)
#include <cuda_runtime.h>
#include <math.h>

// Problem constants
#define Bb 2
#define Ss 2048
#define Dd 1024
#define Hh 16
#define HDh 64
#define Mm (Bb*Ss)   // 4096

// Scratch (device globals: allocation-free rule)
__device__ float g_q[Mm*Dd];
__device__ float g_k[Mm*Dd];
__device__ float g_v[Mm*Dd];
__device__ float g_o[Mm*Dd];

// ======================================================================
// GEMM: C[m][n] = sum_k A[m][k] * W[n][k]   (A: [M,K] row-major, W: [N,K] row-major)
// Block tile 128x128, K-tile 16, 256 threads, 8x8 per thread.
// blockIdx.z selects (W,C) pair so q/k/v projections run in one launch.
// ======================================================================
#define BM 128
#define BN 128
#define BKk 16

__global__ void __launch_bounds__(256, 2) sgemm_nt(
    const float* __restrict__ A,
    const float* __restrict__ W0, const float* __restrict__ W1, const float* __restrict__ W2,
    float* __restrict__ C0, float* __restrict__ C1, float* __restrict__ C2)
{
    const int K = Dd, N = Dd;
    const float* W = (blockIdx.z == 0) ? W0 : (blockIdx.z == 1) ? W1 : W2;
    float*       C = (blockIdx.z == 0) ? C0 : (blockIdx.z == 1) ? C1 : C2;

    __shared__ float As[BKk][BM];
    __shared__ float Ws[BKk][BN];

    const int tid = threadIdx.x;
    const int tx = tid & 15;
    const int ty = tid >> 4;
    const int row0 = blockIdx.y * BM;
    const int col0 = blockIdx.x * BN;

    float acc[8][8];
#pragma unroll
    for (int i = 0; i < 8; i++)
#pragma unroll
        for (int j = 0; j < 8; j++) acc[i][j] = 0.0f;

    for (int kk = 0; kk < K; kk += BKk) {
        // Load 128x16 tiles of A and W, transposed into smem.
        // 512 float4 per tile / 256 threads = 2 float4 each.
#pragma unroll
        for (int jj = 0; jj < 2; jj++) {
            int f  = tid + jj * 256;       // float4 index in [0,512)
            int r  = f >> 2;               // row within tile
            int c4 = (f & 3) << 2;         // k offset within tile
            float4 av = *(const float4*)(A + (size_t)(row0 + r) * K + kk + c4);
            As[c4 + 0][r] = av.x; As[c4 + 1][r] = av.y;
            As[c4 + 2][r] = av.z; As[c4 + 3][r] = av.w;
            float4 wv = *(const float4*)(W + (size_t)(col0 + r) * K + kk + c4);
            Ws[c4 + 0][r] = wv.x; Ws[c4 + 1][r] = wv.y;
            Ws[c4 + 2][r] = wv.z; Ws[c4 + 3][r] = wv.w;
        }
        __syncthreads();

#pragma unroll
        for (int k = 0; k < BKk; k++) {
            float a[8], b[8];
            *(float4*)&a[0] = *(const float4*)&As[k][ty * 8];
            *(float4*)&a[4] = *(const float4*)&As[k][ty * 8 + 4];
            *(float4*)&b[0] = *(const float4*)&Ws[k][tx * 8];
            *(float4*)&b[4] = *(const float4*)&Ws[k][tx * 8 + 4];
#pragma unroll
            for (int i = 0; i < 8; i++)
#pragma unroll
                for (int j = 0; j < 8; j++)
                    acc[i][j] = fmaf(a[i], b[j], acc[i][j]);
        }
        __syncthreads();
    }

#pragma unroll
    for (int i = 0; i < 8; i++) {
        float4 v0 = make_float4(acc[i][0], acc[i][1], acc[i][2], acc[i][3]);
        float4 v1 = make_float4(acc[i][4], acc[i][5], acc[i][6], acc[i][7]);
        size_t off = (size_t)(row0 + ty * 8 + i) * N + col0 + tx * 8;
        *(float4*)(C + off)     = v0;
        *(float4*)(C + off + 4) = v1;
    }
}

// ======================================================================
// RoPE (in-place on q and k, [M, D] layout with n = h*64 + hd)
// angles in double for accuracy; one thread per (m, h, pair i)
// ======================================================================
__global__ void rope_kernel(float* __restrict__ q, float* __restrict__ k)
{
    int idx = blockIdx.x * blockDim.x + threadIdx.x;   // [0, Mm*Hh*32)
    int i = idx & 31;
    int h = (idx >> 5) & (Hh - 1);
    int m = idx >> 9;            // / (32*16)
    int s = m & (Ss - 1);

    double inv = pow(10000.0, -((double)(2 * i)) / (double)HDh);
    double ang = (double)s * inv;
    double sd, cd;
    sincos(ang, &sd, &cd);
    float c  = (float)cd;
    float sn = (float)sd;

    size_t base = (size_t)m * Dd + h * HDh + i;
    float q1 = q[base], q2 = q[base + 32];
    q[base]      = q1 * c - q2 * sn;
    q[base + 32] = q2 * c + q1 * sn;
    float k1 = k[base], k2 = k[base + 32];
    k[base]      = k1 * c - k2 * sn;
    k[base + 32] = k2 * c + k1 * sn;
}

// ======================================================================
// Flash attention, fp32, causal. One CTA = 64 query rows of one (b,h).
// 256 threads: 16x16 grid, each thread 4x4 of the 64x64 score/O tiles.
// Smem: Qs (natural), KVs (d-swizzled, reused for K then V), Ps. 48KB exactly.
// ======================================================================
__device__ __forceinline__ int swz(int r) {
    return (((r & 15) ^ ((r >> 4) & 3)) << 2);
}

__global__ void __launch_bounds__(256, 2) flash_attn(
    const float* __restrict__ Q, const float* __restrict__ Kg,
    const float* __restrict__ Vg, float* __restrict__ O)
{
    __shared__ float Qs[64][64];
    __shared__ float KVs[64][64];
    __shared__ float Ps[64][64];

    const int tid = threadIdx.x;
    const int tx = tid & 15;
    const int ty = tid >> 4;
    const int tx4 = tx * 4, ty4 = ty * 4;

    const int bh = blockIdx.y;
    const int b = bh >> 4;          // / Hh
    const int h = bh & (Hh - 1);
    const int qb = gridDim.x - 1 - blockIdx.x;   // heavy blocks scheduled first
    const int q0 = qb * 64;

    const size_t hoff = (size_t)h * HDh;
    const float* Qb = Q + ((size_t)b * Ss + q0) * Dd + hoff;

    // Load Q tile (natural layout)
#pragma unroll
    for (int jj = 0; jj < 4; jj++) {
        int f = tid + jj * 256;
        int r = f >> 4, d4 = (f & 15) << 2;
        *(float4*)&Qs[r][d4] = *(const float4*)(Qb + (size_t)r * Dd + d4);
    }
    __syncthreads();

    float m_i[4], l_i[4], acc_o[4][4];
#pragma unroll
    for (int i = 0; i < 4; i++) {
        m_i[i] = -1e30f; l_i[i] = 0.0f;
#pragma unroll
        for (int j = 0; j < 4; j++) acc_o[i][j] = 0.0f;
    }

    for (int kb = 0; kb <= qb; kb++) {
        const int k0 = kb * 64;

        // ---- load K tile (swizzled along d) ----
        const float* Kb = Kg + ((size_t)b * Ss + k0) * Dd + hoff;
#pragma unroll
        for (int jj = 0; jj < 4; jj++) {
            int f = tid + jj * 256;
            int r = f >> 4, d4 = (f & 15) << 2;
            *(float4*)&KVs[r][d4 ^ swz(r)] = *(const float4*)(Kb + (size_t)r * Dd + d4);
        }
        __syncthreads();

        // ---- scores S = Q K^T ----
        float s[4][4];
#pragma unroll
        for (int i = 0; i < 4; i++)
#pragma unroll
            for (int j = 0; j < 4; j++) s[i][j] = 0.0f;

#pragma unroll
        for (int d4 = 0; d4 < 64; d4 += 4) {
            float4 qa[4], kv[4];
#pragma unroll
            for (int i = 0; i < 4; i++) qa[i] = *(const float4*)&Qs[ty4 + i][d4];
#pragma unroll
            for (int j = 0; j < 4; j++) kv[j] = *(const float4*)&KVs[tx4 + j][d4 ^ swz(tx4 + j)];
#pragma unroll
            for (int i = 0; i < 4; i++)
#pragma unroll
                for (int j = 0; j < 4; j++) {
                    s[i][j] = fmaf(qa[i].x, kv[j].x, s[i][j]);
                    s[i][j] = fmaf(qa[i].y, kv[j].y, s[i][j]);
                    s[i][j] = fmaf(qa[i].z, kv[j].z, s[i][j]);
                    s[i][j] = fmaf(qa[i].w, kv[j].w, s[i][j]);
                }
        }

        // ---- scale + causal mask ----
        const bool diag = (kb == qb);
#pragma unroll
        for (int i = 0; i < 4; i++)
#pragma unroll
            for (int j = 0; j < 4; j++) {
                s[i][j] *= 0.125f;   // 1/sqrt(64)
                if (diag && (k0 + tx4 + j > q0 + ty4 + i)) s[i][j] = -1e30f;
            }

        // ---- online softmax (row stats across 16 tx lanes via shfl) ----
        float rmax[4];
#pragma unroll
        for (int i = 0; i < 4; i++)
            rmax[i] = fmaxf(fmaxf(s[i][0], s[i][1]), fmaxf(s[i][2], s[i][3]));
#pragma unroll
        for (int o = 8; o; o >>= 1)
#pragma unroll
            for (int i = 0; i < 4; i++)
                rmax[i] = fmaxf(rmax[i], __shfl_xor_sync(0xffffffffu, rmax[i], o));

        float p[4][4], rsum[4];
#pragma unroll
        for (int i = 0; i < 4; i++) {
            float mnew = fmaxf(m_i[i], rmax[i]);
            float corr = __expf(m_i[i] - mnew);
            m_i[i] = mnew;
            float sum = 0.0f;
#pragma unroll
            for (int j = 0; j < 4; j++) {
                p[i][j] = __expf(s[i][j] - mnew);
                sum += p[i][j];
            }
            rsum[i] = sum;
            l_i[i] *= corr;
#pragma unroll
            for (int j = 0; j < 4; j++) acc_o[i][j] *= corr;
        }
#pragma unroll
        for (int o = 8; o; o >>= 1)
#pragma unroll
            for (int i = 0; i < 4; i++)
                rsum[i] += __shfl_xor_sync(0xffffffffu, rsum[i], o);
#pragma unroll
        for (int i = 0; i < 4; i++) l_i[i] += rsum[i];

        // ---- store P tile ----
#pragma unroll
        for (int i = 0; i < 4; i++)
            *(float4*)&Ps[ty4 + i][tx4] = make_float4(p[i][0], p[i][1], p[i][2], p[i][3]);
        __syncthreads();   // Ps visible; K reads of KVs done

        // ---- load V tile (swizzled along d, same buffer) ----
        const float* Vb = Vg + ((size_t)b * Ss + k0) * Dd + hoff;
#pragma unroll
        for (int jj = 0; jj < 4; jj++) {
            int f = tid + jj * 256;
            int r = f >> 4, d4 = (f & 15) << 2;
            *(float4*)&KVs[r][d4 ^ swz(r)] = *(const float4*)(Vb + (size_t)r * Dd + d4);
        }
        __syncthreads();

        // ---- O += P V ----
#pragma unroll
        for (int k4 = 0; k4 < 64; k4 += 4) {
            float4 pa[4];
            float vrow[4][4];
#pragma unroll
            for (int i = 0; i < 4; i++) pa[i] = *(const float4*)&Ps[ty4 + i][k4];
#pragma unroll
            for (int c = 0; c < 4; c++) {
                float4 vv = *(const float4*)&KVs[k4 + c][tx4 ^ swz(k4 + c)];
                vrow[c][0] = vv.x; vrow[c][1] = vv.y; vrow[c][2] = vv.z; vrow[c][3] = vv.w;
            }
#pragma unroll
            for (int i = 0; i < 4; i++) {
                float av[4] = {pa[i].x, pa[i].y, pa[i].z, pa[i].w};
#pragma unroll
                for (int c = 0; c < 4; c++)
#pragma unroll
                    for (int j = 0; j < 4; j++)
                        acc_o[i][j] = fmaf(av[c], vrow[c][j], acc_o[i][j]);
            }
        }
        __syncthreads();   // KVs reads done before next K overwrite
    }

    // ---- normalize and write O in [b, s, h*64+hd] layout ----
    float* Ob = O + ((size_t)b * Ss + q0) * Dd + hoff;
#pragma unroll
    for (int i = 0; i < 4; i++) {
        float invl = 1.0f / l_i[i];
        float4 v = make_float4(acc_o[i][0] * invl, acc_o[i][1] * invl,
                               acc_o[i][2] * invl, acc_o[i][3] * invl);
        *(float4*)(Ob + (size_t)(ty4 + i) * Dd + tx4) = v;
    }
}

// ======================================================================
// Launch
// ======================================================================
extern "C" void kernel_launch(void* const* d_in, const int* in_sizes, int n_in,
                              void* d_out, int out_size)
{
    const float* x  = (const float*)d_in[0];
    const float* wq = (const float*)d_in[1];
    const float* wk = (const float*)d_in[2];
    const float* wv = (const float*)d_in[3];
    const float* wo = (const float*)d_in[4];
    float* out = (float*)d_out;

    float *q, *k, *v, *o;
    cudaGetSymbolAddress((void**)&q, g_q);
    cudaGetSymbolAddress((void**)&k, g_k);
    cudaGetSymbolAddress((void**)&v, g_v);
    cudaGetSymbolAddress((void**)&o, g_o);

    // 1) fused q/k/v projections
    sgemm_nt<<<dim3(Dd / BN, Mm / BM, 3), 256>>>(x, wq, wk, wv, q, k, v);

    // 2) RoPE on q and k
    rope_kernel<<<(Mm * Hh * 32) / 256, 256>>>(q, k);

    // 3) causal flash attention
    flash_attn<<<dim3(Ss / 64, Bb * Hh), 256>>>(q, k, v, o);

    // 4) output projection
    sgemm_nt<<<dim3(Dd / BN, Mm / BM, 1), 256>>>(o, wo, wo, wo, out, out, out);
}

// round 3
// speedup vs baseline: 1.3714x; 1.3714x over previous
#include <cuda_runtime.h>
#include <math.h>
#include <stdint.h>

// Problem constants
#define Bb 2
#define Ss 2048
#define Dd 1024
#define Hh 16
#define HDh 64
#define Mm (Bb*Ss)   // 4096

// Scratch (device globals: allocation-free rule)
__device__ float g_q[Mm*Dd];
__device__ float g_k[Mm*Dd];
__device__ float g_v[Mm*Dd];
__device__ float g_o[Mm*Dd];

// ======================================================================
// Helpers
// ======================================================================
__device__ __forceinline__ uint32_t smem_u32(const void* p) {
    uint32_t a;
    asm("{ .reg .u64 t; cvta.to.shared.u64 t, %1; cvt.u32.u64 %0, t; }"
        : "=r"(a) : "l"(p));
    return a;
}

// fp32 -> tf32 round-to-nearest (bit pattern as u32)
__device__ __forceinline__ uint32_t tf32rn(float x) {
    uint32_t u;
    asm("cvt.rna.tf32.f32 %0, %1;" : "=r"(u) : "f"(x));
    return u;
}

// D += A*B, m16n8k8 tf32 (A row-major 16x8, B col-major 8x8, C fp32)
__device__ __forceinline__ void mma8(float* d, const uint32_t* a,
                                     uint32_t b0, uint32_t b1) {
    asm volatile(
        "mma.sync.aligned.m16n8k8.row.col.f32.tf32.tf32.f32 "
        "{%0,%1,%2,%3}, {%4,%5,%6,%7}, {%8,%9}, {%0,%1,%2,%3};"
        : "+f"(d[0]), "+f"(d[1]), "+f"(d[2]), "+f"(d[3])
        : "r"(a[0]), "r"(a[1]), "r"(a[2]), "r"(a[3]), "r"(b0), "r"(b1));
}

__device__ __forceinline__ void cp16(uint32_t dst, const void* src) {
    asm volatile("cp.async.cg.shared.global [%0], [%1], 16;"
                 :: "r"(dst), "l"(src) : "memory");
}
#define CP_COMMIT() asm volatile("cp.async.commit_group;" ::: "memory")
#define CP_WAIT0()  asm volatile("cp.async.wait_group 0;" ::: "memory")

// ======================================================================
// GEMM: C[m][n] = sum_k A[m][k] * W[n][k]  via tf32 mma.sync
// CTA 128x128, K-tile 32, 256 thr (8 warps, 64x32 warp tiles),
// cp.async double-buffered smem (raw fp32; cvt.rna at frag load).
// ======================================================================
#define GPAD 36
#define GTW (128*GPAD)            // words per tile buffer
#define GEMM_SMEM (4*GTW*4)       // As0,As1,Ws0,Ws1 = 73728 B

__global__ void __launch_bounds__(256, 2) gemm_tc(
    const float* __restrict__ A,
    const float* __restrict__ W0, const float* __restrict__ W1, const float* __restrict__ W2,
    float* __restrict__ C0, float* __restrict__ C1, float* __restrict__ C2)
{
    extern __shared__ float smf[];
    const uint32_t sb = smem_u32(smf);

    const int tid = threadIdx.x;
    const int w = tid >> 5, lane = tid & 31;
    const int gid = lane >> 2, sub = lane & 3;
    const int wm = (w & 1) * 64, wn = (w >> 1) * 32;

    const float* Wt = (blockIdx.z == 0) ? W0 : (blockIdx.z == 1) ? W1 : W2;
    float*       C  = (blockIdx.z == 0) ? C0 : (blockIdx.z == 1) ? C1 : C2;
    const int row0 = blockIdx.y * 128, col0 = blockIdx.x * 128;

    // per-thread copy geometry: 8x cp.async of 16B; i<4 -> A, i>=4 -> W
    const float* src[8];
    uint32_t dstw[8];
#pragma unroll
    for (int i = 0; i < 8; i++) {
        int f  = tid + i * 256;
        int r  = (f & 1023) >> 3;
        int c4 = (f & 7) << 2;
        src[i]  = ((i < 4) ? (A + (size_t)(row0 + r) * Dd)
                           : (Wt + (size_t)(col0 + r) * Dd)) + c4;
        dstw[i] = ((i < 4) ? 0u : 2u * GTW) + (uint32_t)(r * GPAD + c4);
    }

    float acc[4][4][4];
#pragma unroll
    for (int mi = 0; mi < 4; mi++)
#pragma unroll
        for (int ni = 0; ni < 4; ni++)
#pragma unroll
            for (int cc = 0; cc < 4; cc++) acc[mi][ni][cc] = 0.0f;

    // prolog: tile 0 -> buf 0
#pragma unroll
    for (int i = 0; i < 8; i++) cp16(sb + dstw[i] * 4, src[i]);
    CP_COMMIT(); CP_WAIT0();
    __syncthreads();

    for (int c = 0; c < 32; c++) {
        const int b = c & 1;
        if (c + 1 < 32) {
#pragma unroll
            for (int i = 0; i < 8; i++)
                cp16(sb + (dstw[i] + (uint32_t)(b ^ 1) * GTW) * 4,
                     src[i] + (c + 1) * 32);
            CP_COMMIT();
        }
        const float* As = smf + b * GTW;
        const float* Ws = smf + (2 + b) * GTW;
#pragma unroll
        for (int ks = 0; ks < 4; ks++) {
            uint32_t a[4][4];
#pragma unroll
            for (int mi = 0; mi < 4; mi++) {
                const float* p = As + (wm + 16 * mi + gid) * GPAD + ks * 8 + sub;
                a[mi][0] = tf32rn(p[0]);
                a[mi][1] = tf32rn(p[8 * GPAD]);
                a[mi][2] = tf32rn(p[4]);
                a[mi][3] = tf32rn(p[8 * GPAD + 4]);
            }
#pragma unroll
            for (int ni = 0; ni < 4; ni++) {
                const float* p = Ws + (wn + 8 * ni + gid) * GPAD + ks * 8 + sub;
                uint32_t b0 = tf32rn(p[0]), b1 = tf32rn(p[4]);
#pragma unroll
                for (int mi = 0; mi < 4; mi++) mma8(acc[mi][ni], a[mi], b0, b1);
            }
        }
        if (c + 1 < 32) CP_WAIT0();
        __syncthreads();
    }

    // epilogue
#pragma unroll
    for (int mi = 0; mi < 4; mi++) {
        int row = row0 + wm + 16 * mi + gid;
#pragma unroll
        for (int ni = 0; ni < 4; ni++) {
            int col = col0 + wn + 8 * ni + 2 * sub;
            *(float2*)(C + (size_t)row * Dd + col) =
                make_float2(acc[mi][ni][0], acc[mi][ni][1]);
            *(float2*)(C + (size_t)(row + 8) * Dd + col) =
                make_float2(acc[mi][ni][2], acc[mi][ni][3]);
        }
    }
}

// ======================================================================
// RoPE (in-place on q and k; double-precision angles)
// ======================================================================
__global__ void rope_kernel(float* __restrict__ q, float* __restrict__ k)
{
    int idx = blockIdx.x * blockDim.x + threadIdx.x;
    int i = idx & 31;
    int h = (idx >> 5) & (Hh - 1);
    int m = idx >> 9;
    int s = m & (Ss - 1);

    double inv = pow(10000.0, -((double)(2 * i)) / (double)HDh);
    double ang = (double)s * inv;
    double sd, cd;
    sincos(ang, &sd, &cd);
    float c  = (float)cd;
    float sn = (float)sd;

    size_t base = (size_t)m * Dd + h * HDh + i;
    float q1 = q[base], q2 = q[base + 32];
    q[base]      = q1 * c - q2 * sn;
    q[base + 32] = q2 * c + q1 * sn;
    float k1 = k[base], k2 = k[base + 32];
    k[base]      = k1 * c - k2 * sn;
    k[base + 32] = k2 * c + k1 * sn;
}

// ======================================================================
// Flash attention, causal, tf32 mma.sync.
// CTA: 128 q-rows of one (b,h); 8 warps, each owns 16 q-rows x all 64 cols.
// k-tile 64. Smem (tf32-converted): Qs[128][68], Ks[64][68], Vs[64][72],
// Ps[128][68]  -> 105472 B, 2 CTAs/SM.
// ======================================================================
#define FPADQ 68
#define FPADV 72
#define QS_OFF 0
#define KS_OFF (128*FPADQ)
#define VS_OFF (KS_OFF + 64*FPADQ)
#define PS_OFF (VS_OFF + 64*FPADV)
#define FA_SMEM ((PS_OFF + 128*FPADQ)*4)

__global__ void __launch_bounds__(256, 2) flash_tc(
    const float* __restrict__ Q, const float* __restrict__ K,
    const float* __restrict__ V, float* __restrict__ O)
{
    extern __shared__ float smf[];
    float* Qs = smf + QS_OFF;
    float* Ks = smf + KS_OFF;
    float* Vs = smf + VS_OFF;
    float* Ps = smf + PS_OFF;

    const int tid = threadIdx.x;
    const int w = tid >> 5, lane = tid & 31;
    const int gid = lane >> 2, sub = lane & 3;

    const int bh = blockIdx.y;
    const int bb = bh >> 4, h = bh & 15;
    const int qt = gridDim.x - 1 - blockIdx.x;   // heavy tiles first
    const int q0 = qt * 128;
    const size_t hoff = (size_t)h * HDh;

    // load Q tile (cvt to tf32)
    const float* Qg = Q + ((size_t)bb * Ss + q0) * Dd + hoff;
#pragma unroll
    for (int i = 0; i < 8; i++) {
        int f = tid + i * 256;
        int r = f >> 4, c4 = (f & 15) << 2;
        float4 v = *(const float4*)(Qg + (size_t)r * Dd + c4);
        float* p = Qs + r * FPADQ + c4;
        p[0] = __uint_as_float(tf32rn(v.x));
        p[1] = __uint_as_float(tf32rn(v.y));
        p[2] = __uint_as_float(tf32rn(v.z));
        p[3] = __uint_as_float(tf32rn(v.w));
    }

    float m_i[2] = {-1e30f, -1e30f};
    float l_i[2] = {0.0f, 0.0f};
    float acc[8][4];
#pragma unroll
    for (int ni = 0; ni < 8; ni++)
#pragma unroll
        for (int cc = 0; cc < 4; cc++) acc[ni][cc] = 0.0f;

    const int nkt = 2 * qt + 2;
    const float* Kg = K + (size_t)bb * Ss * Dd + hoff;
    const float* Vg = V + (size_t)bb * Ss * Dd + hoff;

    for (int kb = 0; kb < nkt; kb++) {
        const int k0 = kb * 64;

        // K tile -> Ks (cvt); stage V tile in regs (LDG early)
        float4 vst[4];
#pragma unroll
        for (int i = 0; i < 4; i++) {
            int f = tid + i * 256;
            int r = f >> 4, c4 = (f & 15) << 2;
            float4 kv = *(const float4*)(Kg + (size_t)(k0 + r) * Dd + c4);
            float* p = Ks + r * FPADQ + c4;
            p[0] = __uint_as_float(tf32rn(kv.x));
            p[1] = __uint_as_float(tf32rn(kv.y));
            p[2] = __uint_as_float(tf32rn(kv.z));
            p[3] = __uint_as_float(tf32rn(kv.w));
            vst[i] = *(const float4*)(Vg + (size_t)(k0 + r) * Dd + c4);
        }
        __syncthreads();   // Ks ready; prev-iter Ps/Vs readers done

        // ---- S = Q K^T (16 q-rows x 64 cols per warp) ----
        float s[8][4];
#pragma unroll
        for (int ni = 0; ni < 8; ni++)
#pragma unroll
            for (int cc = 0; cc < 4; cc++) s[ni][cc] = 0.0f;

#pragma unroll
        for (int ks = 0; ks < 8; ks++) {
            uint32_t a[4];
            const float* qp = Qs + (w * 16 + gid) * FPADQ + ks * 8 + sub;
            a[0] = __float_as_uint(qp[0]);
            a[1] = __float_as_uint(qp[8 * FPADQ]);
            a[2] = __float_as_uint(qp[4]);
            a[3] = __float_as_uint(qp[8 * FPADQ + 4]);
#pragma unroll
            for (int ni = 0; ni < 8; ni++) {
                const float* kp = Ks + (ni * 8 + gid) * FPADQ + ks * 8 + sub;
                mma8(s[ni], a, __float_as_uint(kp[0]), __float_as_uint(kp[4]));
            }
        }

        // ---- scale + causal mask + online softmax ----
        const bool mt = (kb >= 2 * qt);
        const int r0g = q0 + w * 16 + gid;
        float rmax[2] = {-1e30f, -1e30f};
#pragma unroll
        for (int ni = 0; ni < 8; ni++) {
            int colb = k0 + ni * 8 + 2 * sub;
#pragma unroll
            for (int cc = 0; cc < 4; cc++) {
                float sv = s[ni][cc] * 0.125f;
                if (mt) {
                    int row = r0g + ((cc >> 1) << 3);
                    int col = colb + (cc & 1);
                    if (col > row) sv = -1e30f;
                }
                s[ni][cc] = sv;
                rmax[cc >> 1] = fmaxf(rmax[cc >> 1], sv);
            }
        }
#pragma unroll
        for (int o = 1; o <= 2; o <<= 1) {
            rmax[0] = fmaxf(rmax[0], __shfl_xor_sync(0xffffffffu, rmax[0], o));
            rmax[1] = fmaxf(rmax[1], __shfl_xor_sync(0xffffffffu, rmax[1], o));
        }
        float mnew0 = fmaxf(m_i[0], rmax[0]);
        float mnew1 = fmaxf(m_i[1], rmax[1]);
        float corr0 = __expf(m_i[0] - mnew0);
        float corr1 = __expf(m_i[1] - mnew1);
        m_i[0] = mnew0; m_i[1] = mnew1;

        float rsum[2] = {0.0f, 0.0f};
#pragma unroll
        for (int ni = 0; ni < 8; ni++) {
            s[ni][0] = __expf(s[ni][0] - mnew0);
            s[ni][1] = __expf(s[ni][1] - mnew0);
            s[ni][2] = __expf(s[ni][2] - mnew1);
            s[ni][3] = __expf(s[ni][3] - mnew1);
            rsum[0] += s[ni][0] + s[ni][1];
            rsum[1] += s[ni][2] + s[ni][3];
            acc[ni][0] *= corr0; acc[ni][1] *= corr0;
            acc[ni][2] *= corr1; acc[ni][3] *= corr1;
        }
#pragma unroll
        for (int o = 1; o <= 2; o <<= 1) {
            rsum[0] += __shfl_xor_sync(0xffffffffu, rsum[0], o);
            rsum[1] += __shfl_xor_sync(0xffffffffu, rsum[1], o);
        }
        l_i[0] = l_i[0] * corr0 + rsum[0];
        l_i[1] = l_i[1] * corr1 + rsum[1];

        // ---- store P (tf32) and V (tf32) tiles ----
        {
            float* pp = Ps + (w * 16 + gid) * FPADQ + 2 * sub;
#pragma unroll
            for (int ni = 0; ni < 8; ni++) {
                *(float2*)(pp + ni * 8) = make_float2(
                    __uint_as_float(tf32rn(s[ni][0])),
                    __uint_as_float(tf32rn(s[ni][1])));
                *(float2*)(pp + 8 * FPADQ + ni * 8) = make_float2(
                    __uint_as_float(tf32rn(s[ni][2])),
                    __uint_as_float(tf32rn(s[ni][3])));
            }
        }
#pragma unroll
        for (int i = 0; i < 4; i++) {
            int f = tid + i * 256;
            int r = f >> 4, c4 = (f & 15) << 2;
            float* p = Vs + r * FPADV + c4;
            p[0] = __uint_as_float(tf32rn(vst[i].x));
            p[1] = __uint_as_float(tf32rn(vst[i].y));
            p[2] = __uint_as_float(tf32rn(vst[i].z));
            p[3] = __uint_as_float(tf32rn(vst[i].w));
        }
        __syncthreads();

        // ---- O += P V ----
#pragma unroll
        for (int ks = 0; ks < 8; ks++) {
            uint32_t a[4];
            const float* pr = Ps + (w * 16 + gid) * FPADQ + ks * 8 + sub;
            a[0] = __float_as_uint(pr[0]);
            a[1] = __float_as_uint(pr[8 * FPADQ]);
            a[2] = __float_as_uint(pr[4]);
            a[3] = __float_as_uint(pr[8 * FPADQ + 4]);
#pragma unroll
            for (int ni = 0; ni < 8; ni++) {
                const float* vp = Vs + (ks * 8 + sub) * FPADV + ni * 8 + gid;
                mma8(acc[ni], a, __float_as_uint(vp[0]),
                     __float_as_uint(vp[4 * FPADV]));
            }
        }
    }

    // ---- normalize and write O ----
#pragma unroll
    for (int rr = 0; rr < 2; rr++) {
        float inv = 1.0f / l_i[rr];
        int row = q0 + w * 16 + gid + rr * 8;
        float* Og = O + ((size_t)bb * Ss + row) * Dd + hoff + 2 * sub;
#pragma unroll
        for (int ni = 0; ni < 8; ni++)
            *(float2*)(Og + ni * 8) = make_float2(acc[ni][2 * rr] * inv,
                                                  acc[ni][2 * rr + 1] * inv);
    }
}

// ======================================================================
// Launch
// ======================================================================
extern "C" void kernel_launch(void* const* d_in, const int* in_sizes, int n_in,
                              void* d_out, int out_size)
{
    const float* x  = (const float*)d_in[0];
    const float* wq = (const float*)d_in[1];
    const float* wk = (const float*)d_in[2];
    const float* wv = (const float*)d_in[3];
    const float* wo = (const float*)d_in[4];
    float* out = (float*)d_out;

    float *q, *k, *v, *o;
    cudaGetSymbolAddress((void**)&q, g_q);
    cudaGetSymbolAddress((void**)&k, g_k);
    cudaGetSymbolAddress((void**)&v, g_v);
    cudaGetSymbolAddress((void**)&o, g_o);

    cudaFuncSetAttribute(gemm_tc,  cudaFuncAttributeMaxDynamicSharedMemorySize, GEMM_SMEM);
    cudaFuncSetAttribute(flash_tc, cudaFuncAttributeMaxDynamicSharedMemorySize, FA_SMEM);

    // 1) fused q/k/v projections (tf32 mma.sync)
    gemm_tc<<<dim3(Dd / 128, Mm / 128, 3), 256, GEMM_SMEM>>>(x, wq, wk, wv, q, k, v);

    // 2) RoPE
    rope_kernel<<<(Mm * Hh * 32) / 256, 256>>>(q, k);

    // 3) causal flash attention (tf32 mma.sync)
    flash_tc<<<dim3(Ss / 128, Bb * Hh), 256, FA_SMEM>>>(q, k, v, o);

    // 4) output projection
    gemm_tc<<<dim3(Dd / 128, Mm / 128, 1), 256, GEMM_SMEM>>>(o, wo, wo, wo, out, out, out);
}

// round 4
// speedup vs baseline: 2.1755x; 1.5863x over previous
#include <cuda_runtime.h>
#include <math.h>
#include <stdint.h>

// Problem constants
#define Bb 2
#define Ss 2048
#define Dd 1024
#define Hh 16
#define HDh 64
#define Mm (Bb*Ss)   // 4096

// Scratch (device globals: allocation-free rule)
__device__ float g_q[Mm*Dd];
__device__ float g_k[Mm*Dd];
__device__ float g_v[Mm*Dd];
__device__ float g_o[Mm*Dd];

// ======================================================================
// Helpers
// ======================================================================
__device__ __forceinline__ uint32_t smem_u32(const void* p) {
    uint32_t a;
    asm("{ .reg .u64 t; cvta.to.shared.u64 t, %1; cvt.u32.u64 %0, t; }"
        : "=r"(a) : "l"(p));
    return a;
}

// fp32 -> tf32 round-to-nearest (bit pattern as u32)
__device__ __forceinline__ uint32_t tf32rn(float x) {
    uint32_t u;
    asm("cvt.rna.tf32.f32 %0, %1;" : "=r"(u) : "f"(x));
    return u;
}

// D += A*B, m16n8k8 tf32 (A row-major 16x8, B col-major 8x8, C fp32)
__device__ __forceinline__ void mma8(float* d, const uint32_t* a,
                                     uint32_t b0, uint32_t b1) {
    asm volatile(
        "mma.sync.aligned.m16n8k8.row.col.f32.tf32.tf32.f32 "
        "{%0,%1,%2,%3}, {%4,%5,%6,%7}, {%8,%9}, {%0,%1,%2,%3};"
        : "+f"(d[0]), "+f"(d[1]), "+f"(d[2]), "+f"(d[3])
        : "r"(a[0]), "r"(a[1]), "r"(a[2]), "r"(a[3]), "r"(b0), "r"(b1));
}

__device__ __forceinline__ void cp16(uint32_t dst, const void* src) {
    asm volatile("cp.async.cg.shared.global [%0], [%1], 16;"
                 :: "r"(dst), "l"(src) : "memory");
}
#define CP_COMMIT() asm volatile("cp.async.commit_group;" ::: "memory")
#define CP_WAIT0()  asm volatile("cp.async.wait_group 0;" ::: "memory")
#define CP_WAIT1()  asm volatile("cp.async.wait_group 1;" ::: "memory")

// ======================================================================
// GEMM: C[m][n] = sum_k A[m][k] * W[n][k]  via tf32 mma.sync
// CTA 128x128, K-tile 32, 256 thr (8 warps, 64x32 warp tiles),
// cp.async double-buffered smem (raw fp32; cvt.rna at frag load).
// ======================================================================
#define GPAD 36
#define GTW (128*GPAD)
#define GEMM_SMEM (4*GTW*4)

__global__ void __launch_bounds__(256, 2) gemm_tc(
    const float* __restrict__ A,
    const float* __restrict__ W0, const float* __restrict__ W1, const float* __restrict__ W2,
    float* __restrict__ C0, float* __restrict__ C1, float* __restrict__ C2)
{
    extern __shared__ float smf[];
    const uint32_t sb = smem_u32(smf);

    const int tid = threadIdx.x;
    const int w = tid >> 5, lane = tid & 31;
    const int gid = lane >> 2, sub = lane & 3;
    const int wm = (w & 1) * 64, wn = (w >> 1) * 32;

    const float* Wt = (blockIdx.z == 0) ? W0 : (blockIdx.z == 1) ? W1 : W2;
    float*       C  = (blockIdx.z == 0) ? C0 : (blockIdx.z == 1) ? C1 : C2;
    const int row0 = blockIdx.y * 128, col0 = blockIdx.x * 128;

    const float* src[8];
    uint32_t dstw[8];
#pragma unroll
    for (int i = 0; i < 8; i++) {
        int f  = tid + i * 256;
        int r  = (f & 1023) >> 3;
        int c4 = (f & 7) << 2;
        src[i]  = ((i < 4) ? (A + (size_t)(row0 + r) * Dd)
                           : (Wt + (size_t)(col0 + r) * Dd)) + c4;
        dstw[i] = ((i < 4) ? 0u : 2u * GTW) + (uint32_t)(r * GPAD + c4);
    }

    float acc[4][4][4];
#pragma unroll
    for (int mi = 0; mi < 4; mi++)
#pragma unroll
        for (int ni = 0; ni < 4; ni++)
#pragma unroll
            for (int cc = 0; cc < 4; cc++) acc[mi][ni][cc] = 0.0f;

#pragma unroll
    for (int i = 0; i < 8; i++) cp16(sb + dstw[i] * 4, src[i]);
    CP_COMMIT(); CP_WAIT0();
    __syncthreads();

    for (int c = 0; c < 32; c++) {
        const int b = c & 1;
        if (c + 1 < 32) {
#pragma unroll
            for (int i = 0; i < 8; i++)
                cp16(sb + (dstw[i] + (uint32_t)(b ^ 1) * GTW) * 4,
                     src[i] + (c + 1) * 32);
            CP_COMMIT();
        }
        const float* As = smf + b * GTW;
        const float* Ws = smf + (2 + b) * GTW;
#pragma unroll
        for (int ks = 0; ks < 4; ks++) {
            uint32_t a[4][4];
#pragma unroll
            for (int mi = 0; mi < 4; mi++) {
                const float* p = As + (wm + 16 * mi + gid) * GPAD + ks * 8 + sub;
                a[mi][0] = tf32rn(p[0]);
                a[mi][1] = tf32rn(p[8 * GPAD]);
                a[mi][2] = tf32rn(p[4]);
                a[mi][3] = tf32rn(p[8 * GPAD + 4]);
            }
#pragma unroll
            for (int ni = 0; ni < 4; ni++) {
                const float* p = Ws + (wn + 8 * ni + gid) * GPAD + ks * 8 + sub;
                uint32_t b0 = tf32rn(p[0]), b1 = tf32rn(p[4]);
#pragma unroll
                for (int mi = 0; mi < 4; mi++) mma8(acc[mi][ni], a[mi], b0, b1);
            }
        }
        if (c + 1 < 32) CP_WAIT0();
        __syncthreads();
    }

#pragma unroll
    for (int mi = 0; mi < 4; mi++) {
        int row = row0 + wm + 16 * mi + gid;
#pragma unroll
        for (int ni = 0; ni < 4; ni++) {
            int col = col0 + wn + 8 * ni + 2 * sub;
            *(float2*)(C + (size_t)row * Dd + col) =
                make_float2(acc[mi][ni][0], acc[mi][ni][1]);
            *(float2*)(C + (size_t)(row + 8) * Dd + col) =
                make_float2(acc[mi][ni][2], acc[mi][ni][3]);
        }
    }
}

// ======================================================================
// RoPE on q,k (double-precision angles) + tf32-RN pre-round of q,k,v.
// ======================================================================
__global__ void rope_kernel(float* __restrict__ q, float* __restrict__ k,
                            float* __restrict__ v)
{
    int idx = blockIdx.x * blockDim.x + threadIdx.x;
    int i = idx & 31;
    int h = (idx >> 5) & (Hh - 1);
    int m = idx >> 9;
    int s = m & (Ss - 1);

    double inv = pow(10000.0, -((double)(2 * i)) / (double)HDh);
    double ang = (double)s * inv;
    double sd, cd;
    sincos(ang, &sd, &cd);
    float c  = (float)cd;
    float sn = (float)sd;

    size_t base = (size_t)m * Dd + h * HDh + i;
    float q1 = q[base], q2 = q[base + 32];
    q[base]      = __uint_as_float(tf32rn(q1 * c - q2 * sn));
    q[base + 32] = __uint_as_float(tf32rn(q2 * c + q1 * sn));
    float k1 = k[base], k2 = k[base + 32];
    k[base]      = __uint_as_float(tf32rn(k1 * c - k2 * sn));
    k[base + 32] = __uint_as_float(tf32rn(k2 * c + k1 * sn));
    v[base]      = __uint_as_float(tf32rn(v[base]));
    v[base + 32] = __uint_as_float(tf32rn(v[base + 32]));
}

// ======================================================================
// Flash attention, causal, tf32 mma.sync, pipelined.
// CTA: 128 q-rows of one (b,h); 8 warps x (16 q-rows, all 64 cols).
// Q frags live in registers; Q smem region reused for P.
// K,V double-buffered via cp.async (prefetch next k-tile).
// Smem: QP[128][68] | K[2][64][68] | V[2][64][72] = 104 KB -> 2 CTA/SM.
// ======================================================================
#define QPAD 68
#define KPAD 68
#define VPAD 72
#define QP_OFF 0
#define KB_OFF (128*QPAD)                 // 8704
#define VB_OFF (KB_OFF + 2*64*KPAD)       // 17408
#define FA_WORDS (VB_OFF + 2*64*VPAD)     // 26624
#define FA_SMEM (FA_WORDS*4)              // 106496

__global__ void __launch_bounds__(256, 2) flash_tc(
    const float* __restrict__ Q, const float* __restrict__ K,
    const float* __restrict__ V, float* __restrict__ O)
{
    extern __shared__ float smf[];
    float* QP = smf + QP_OFF;
    const uint32_t sb = smem_u32(smf);

    const int tid = threadIdx.x;
    const int w = tid >> 5, lane = tid & 31;
    const int gid = lane >> 2, sub = lane & 3;

    const int bh = blockIdx.y;
    const int bb = bh >> 4, h = bh & 15;
    const int qt = gridDim.x - 1 - blockIdx.x;   // heavy tiles first
    const int q0 = qt * 128;
    const size_t hoff = (size_t)h * HDh;

    const float* Qg = Q + ((size_t)bb * Ss + q0) * Dd + hoff;
    const float* Kg = K + (size_t)bb * Ss * Dd + hoff;
    const float* Vg = V + (size_t)bb * Ss * Dd + hoff;
    const int nkt = 2 * qt + 2;

    // per-thread cp.async geometry for a 64x64 tile (4 x 16B per thread)
    int cr[4], cc4[4];
#pragma unroll
    for (int i = 0; i < 4; i++) {
        int f = tid + i * 256;
        cr[i] = f >> 4;
        cc4[i] = (f & 15) << 2;
    }

    // ---- prolog: Q tile (group), then K0+V0 (group) ----
#pragma unroll
    for (int i = 0; i < 8; i++) {
        int f = tid + i * 256;
        int r = f >> 4, c4 = (f & 15) << 2;
        cp16(sb + (QP_OFF + r * QPAD + c4) * 4, Qg + (size_t)r * Dd + c4);
    }
    CP_COMMIT();
#pragma unroll
    for (int i = 0; i < 4; i++) {
        cp16(sb + (KB_OFF + cr[i] * KPAD + cc4[i]) * 4,
             Kg + (size_t)cr[i] * Dd + cc4[i]);
        cp16(sb + (VB_OFF + cr[i] * VPAD + cc4[i]) * 4,
             Vg + (size_t)cr[i] * Dd + cc4[i]);
    }
    CP_COMMIT();

    CP_WAIT1();          // Q arrived
    __syncthreads();

    // Q fragments -> registers (32 regs), then QP region becomes P storage
    uint32_t qf[8][4];
#pragma unroll
    for (int ks = 0; ks < 8; ks++) {
        const float* qp = QP + (w * 16 + gid) * QPAD + ks * 8 + sub;
        qf[ks][0] = __float_as_uint(qp[0]);
        qf[ks][1] = __float_as_uint(qp[8 * QPAD]);
        qf[ks][2] = __float_as_uint(qp[4]);
        qf[ks][3] = __float_as_uint(qp[8 * QPAD + 4]);
    }

    float m_i[2] = {-1e30f, -1e30f};
    float l_i[2] = {0.0f, 0.0f};
    float acc[8][4];
#pragma unroll
    for (int ni = 0; ni < 8; ni++)
#pragma unroll
        for (int cc = 0; cc < 4; cc++) acc[ni][cc] = 0.0f;

    float* Pw = QP + (w * 16) * QPAD;     // this warp's private P rows

    for (int kb = 0; kb < nkt; kb++) {
        const int b = kb & 1;
        const float* Ks = smf + KB_OFF + b * 64 * KPAD;
        const float* Vs = smf + VB_OFF + b * 64 * VPAD;

        CP_WAIT0();          // K_b, V_b resident
        __syncthreads();     // visible to all; everyone done reading b^1

        // prefetch next tile into b^1
        if (kb + 1 < nkt) {
            const int k1 = (kb + 1) * 64;
#pragma unroll
            for (int i = 0; i < 4; i++) {
                cp16(sb + (KB_OFF + (b ^ 1) * 64 * KPAD + cr[i] * KPAD + cc4[i]) * 4,
                     Kg + (size_t)(k1 + cr[i]) * Dd + cc4[i]);
                cp16(sb + (VB_OFF + (b ^ 1) * 64 * VPAD + cr[i] * VPAD + cc4[i]) * 4,
                     Vg + (size_t)(k1 + cr[i]) * Dd + cc4[i]);
            }
            CP_COMMIT();
        }

        // ---- S = Q K^T ----
        float s[8][4];
#pragma unroll
        for (int ni = 0; ni < 8; ni++)
#pragma unroll
            for (int cc = 0; cc < 4; cc++) s[ni][cc] = 0.0f;

#pragma unroll
        for (int ks = 0; ks < 8; ks++) {
#pragma unroll
            for (int ni = 0; ni < 8; ni++) {
                const float* kp = Ks + (ni * 8 + gid) * KPAD + ks * 8 + sub;
                mma8(s[ni], qf[ks], __float_as_uint(kp[0]),
                     __float_as_uint(kp[4]));
            }
        }

        // ---- scale + causal mask + online softmax ----
        const int k0 = kb * 64;
        const bool mt = (kb >= 2 * qt);
        const int r0g = q0 + w * 16 + gid;
        float rmax[2] = {-1e30f, -1e30f};
#pragma unroll
        for (int ni = 0; ni < 8; ni++) {
            int colb = k0 + ni * 8 + 2 * sub;
#pragma unroll
            for (int cc = 0; cc < 4; cc++) {
                float sv = s[ni][cc] * 0.125f;
                if (mt) {
                    int row = r0g + ((cc >> 1) << 3);
                    int col = colb + (cc & 1);
                    if (col > row) sv = -1e30f;
                }
                s[ni][cc] = sv;
                rmax[cc >> 1] = fmaxf(rmax[cc >> 1], sv);
            }
        }
#pragma unroll
        for (int o = 1; o <= 2; o <<= 1) {
            rmax[0] = fmaxf(rmax[0], __shfl_xor_sync(0xffffffffu, rmax[0], o));
            rmax[1] = fmaxf(rmax[1], __shfl_xor_sync(0xffffffffu, rmax[1], o));
        }
        float mnew0 = fmaxf(m_i[0], rmax[0]);
        float mnew1 = fmaxf(m_i[1], rmax[1]);
        float corr0 = __expf(m_i[0] - mnew0);
        float corr1 = __expf(m_i[1] - mnew1);
        m_i[0] = mnew0; m_i[1] = mnew1;

        float rsum[2] = {0.0f, 0.0f};
#pragma unroll
        for (int ni = 0; ni < 8; ni++) {
            s[ni][0] = __expf(s[ni][0] - mnew0);
            s[ni][1] = __expf(s[ni][1] - mnew0);
            s[ni][2] = __expf(s[ni][2] - mnew1);
            s[ni][3] = __expf(s[ni][3] - mnew1);
            rsum[0] += s[ni][0] + s[ni][1];
            rsum[1] += s[ni][2] + s[ni][3];
            acc[ni][0] *= corr0; acc[ni][1] *= corr0;
            acc[ni][2] *= corr1; acc[ni][3] *= corr1;
        }
#pragma unroll
        for (int o = 1; o <= 2; o <<= 1) {
            rsum[0] += __shfl_xor_sync(0xffffffffu, rsum[0], o);
            rsum[1] += __shfl_xor_sync(0xffffffffu, rsum[1], o);
        }
        l_i[0] = l_i[0] * corr0 + rsum[0];
        l_i[1] = l_i[1] * corr1 + rsum[1];

        // ---- P -> warp-private smem (tf32), then A-frags back ----
        {
            float* pp = Pw + gid * QPAD + 2 * sub;
#pragma unroll
            for (int ni = 0; ni < 8; ni++) {
                *(float2*)(pp + ni * 8) = make_float2(
                    __uint_as_float(tf32rn(s[ni][0])),
                    __uint_as_float(tf32rn(s[ni][1])));
                *(float2*)(pp + 8 * QPAD + ni * 8) = make_float2(
                    __uint_as_float(tf32rn(s[ni][2])),
                    __uint_as_float(tf32rn(s[ni][3])));
            }
        }
        __syncwarp();

        // ---- O += P V ----
#pragma unroll
        for (int ks = 0; ks < 8; ks++) {
            uint32_t a[4];
            const float* pr = Pw + gid * QPAD + ks * 8 + sub;
            a[0] = __float_as_uint(pr[0]);
            a[1] = __float_as_uint(pr[8 * QPAD]);
            a[2] = __float_as_uint(pr[4]);
            a[3] = __float_as_uint(pr[8 * QPAD + 4]);
#pragma unroll
            for (int ni = 0; ni < 8; ni++) {
                const float* vp = Vs + (ks * 8 + sub) * VPAD + ni * 8 + gid;
                mma8(acc[ni], a, __float_as_uint(vp[0]),
                     __float_as_uint(vp[4 * VPAD]));
            }
        }
        __syncwarp();   // P reads done before next-iter P store
    }

    // ---- normalize and write O ----
#pragma unroll
    for (int rr = 0; rr < 2; rr++) {
        float inv = 1.0f / l_i[rr];
        int row = q0 + w * 16 + gid + rr * 8;
        float* Og = O + ((size_t)bb * Ss + row) * Dd + hoff + 2 * sub;
#pragma unroll
        for (int ni = 0; ni < 8; ni++)
            *(float2*)(Og + ni * 8) = make_float2(acc[ni][2 * rr] * inv,
                                                  acc[ni][2 * rr + 1] * inv);
    }
}

// ======================================================================
// Launch
// ======================================================================
extern "C" void kernel_launch(void* const* d_in, const int* in_sizes, int n_in,
                              void* d_out, int out_size)
{
    const float* x  = (const float*)d_in[0];
    const float* wq = (const float*)d_in[1];
    const float* wk = (const float*)d_in[2];
    const float* wv = (const float*)d_in[3];
    const float* wo = (const float*)d_in[4];
    float* out = (float*)d_out;

    float *q, *k, *v, *o;
    cudaGetSymbolAddress((void**)&q, g_q);
    cudaGetSymbolAddress((void**)&k, g_k);
    cudaGetSymbolAddress((void**)&v, g_v);
    cudaGetSymbolAddress((void**)&o, g_o);

    cudaFuncSetAttribute(gemm_tc,  cudaFuncAttributeMaxDynamicSharedMemorySize, GEMM_SMEM);
    cudaFuncSetAttribute(flash_tc, cudaFuncAttributeMaxDynamicSharedMemorySize, FA_SMEM);

    // 1) fused q/k/v projections (tf32 mma.sync)
    gemm_tc<<<dim3(Dd / 128, Mm / 128, 3), 256, GEMM_SMEM>>>(x, wq, wk, wv, q, k, v);

    // 2) RoPE + tf32 pre-round of q,k,v
    rope_kernel<<<(Mm * Hh * 32) / 256, 256>>>(q, k, v);

    // 3) causal flash attention (tf32 mma.sync, pipelined)
    flash_tc<<<dim3(Ss / 128, Bb * Hh), 256, FA_SMEM>>>(q, k, v, o);

    // 4) output projection
    gemm_tc<<<dim3(Dd / 128, Mm / 128, 1), 256, GEMM_SMEM>>>(o, wo, wo, wo, out, out, out);
}

// round 5
// speedup vs baseline: 2.2839x; 1.0499x over previous
#include <cuda_runtime.h>
#include <math.h>
#include <stdint.h>

// Problem constants
#define Bb 2
#define Ss 2048
#define Dd 1024
#define Hh 16
#define HDh 64
#define Mm (Bb*Ss)   // 4096

// Scratch (device globals: allocation-free rule)
__device__ float g_q[Mm*Dd];
__device__ float g_k[Mm*Dd];
__device__ float g_v[Mm*Dd];
__device__ float g_o[Mm*Dd];
__device__ float g_xr[Mm*Dd];        // tf32-rounded x
__device__ float g_wr[4*Dd*Dd];      // tf32-rounded wq,wk,wv,wo

// ======================================================================
// Helpers
// ======================================================================
__device__ __forceinline__ uint32_t smem_u32(const void* p) {
    uint32_t a;
    asm("{ .reg .u64 t; cvta.to.shared.u64 t, %1; cvt.u32.u64 %0, t; }"
        : "=r"(a) : "l"(p));
    return a;
}

// fp32 -> tf32 round-to-nearest (bit pattern as u32)
__device__ __forceinline__ uint32_t tf32rn(float x) {
    uint32_t u;
    asm("cvt.rna.tf32.f32 %0, %1;" : "=r"(u) : "f"(x));
    return u;
}
__device__ __forceinline__ float tf32rnf(float x) {
    return __uint_as_float(tf32rn(x));
}

// D += A*B, m16n8k8 tf32 (A row-major 16x8, B col-major 8x8, C fp32)
__device__ __forceinline__ void mma8(float* d, const uint32_t* a,
                                     uint32_t b0, uint32_t b1) {
    asm volatile(
        "mma.sync.aligned.m16n8k8.row.col.f32.tf32.tf32.f32 "
        "{%0,%1,%2,%3}, {%4,%5,%6,%7}, {%8,%9}, {%0,%1,%2,%3};"
        : "+f"(d[0]), "+f"(d[1]), "+f"(d[2]), "+f"(d[3])
        : "r"(a[0]), "r"(a[1]), "r"(a[2]), "r"(a[3]), "r"(b0), "r"(b1));
}

__device__ __forceinline__ void cp16(uint32_t dst, const void* src) {
    asm volatile("cp.async.cg.shared.global [%0], [%1], 16;"
                 :: "r"(dst), "l"(src) : "memory");
}
#define CP_COMMIT() asm volatile("cp.async.commit_group;" ::: "memory")
#define CP_WAIT0()  asm volatile("cp.async.wait_group 0;" ::: "memory")
#define CP_WAIT1()  asm volatile("cp.async.wait_group 1;" ::: "memory")

// ======================================================================
// Pre-round inputs to tf32 (x and the 4 weight matrices)
// ======================================================================
__global__ void round_inputs(
    const float4* __restrict__ x,
    const float4* __restrict__ wq, const float4* __restrict__ wk,
    const float4* __restrict__ wv, const float4* __restrict__ wo,
    float4* __restrict__ xr, float4* __restrict__ wr)
{
    const int XN = (Mm * Dd) / 4;     // 1M float4
    const int WN = (Dd * Dd) / 4;     // 256K float4
    int i = blockIdx.x * blockDim.x + threadIdx.x;
    float4 v;
    float4* dst;
    if (i < XN) {
        v = x[i];
        dst = xr + i;
    } else {
        int j = i - XN;
        int s = j / WN, o = j % WN;
        const float4* src = (s == 0) ? wq : (s == 1) ? wk : (s == 2) ? wv : wo;
        v = src[o];
        dst = wr + j;
    }
    v.x = tf32rnf(v.x); v.y = tf32rnf(v.y);
    v.z = tf32rnf(v.z); v.w = tf32rnf(v.w);
    *dst = v;
}

// ======================================================================
// GEMM: C[m][n] = sum_k A[m][k] * W[n][k]  via tf32 mma.sync
// Inputs already tf32-rounded -> no cvt in the inner loop.
// CTA 128x128, K-tile 32, 256 thr (8 warps, 64x32 warp tiles),
// cp.async double-buffered smem.
// ======================================================================
#define GPAD 36
#define GTW (128*GPAD)
#define GEMM_SMEM (4*GTW*4)

__global__ void __launch_bounds__(256, 2) gemm_tc(
    const float* __restrict__ A,
    const float* __restrict__ W0, const float* __restrict__ W1, const float* __restrict__ W2,
    float* __restrict__ C0, float* __restrict__ C1, float* __restrict__ C2)
{
    extern __shared__ float smf[];
    const uint32_t sb = smem_u32(smf);

    const int tid = threadIdx.x;
    const int w = tid >> 5, lane = tid & 31;
    const int gid = lane >> 2, sub = lane & 3;
    const int wm = (w & 1) * 64, wn = (w >> 1) * 32;

    const float* Wt = (blockIdx.z == 0) ? W0 : (blockIdx.z == 1) ? W1 : W2;
    float*       C  = (blockIdx.z == 0) ? C0 : (blockIdx.z == 1) ? C1 : C2;
    const int row0 = blockIdx.y * 128, col0 = blockIdx.x * 128;

    const float* src[8];
    uint32_t dstw[8];
#pragma unroll
    for (int i = 0; i < 8; i++) {
        int f  = tid + i * 256;
        int r  = (f & 1023) >> 3;
        int c4 = (f & 7) << 2;
        src[i]  = ((i < 4) ? (A + (size_t)(row0 + r) * Dd)
                           : (Wt + (size_t)(col0 + r) * Dd)) + c4;
        dstw[i] = ((i < 4) ? 0u : 2u * GTW) + (uint32_t)(r * GPAD + c4);
    }

    float acc[4][4][4];
#pragma unroll
    for (int mi = 0; mi < 4; mi++)
#pragma unroll
        for (int ni = 0; ni < 4; ni++)
#pragma unroll
            for (int cc = 0; cc < 4; cc++) acc[mi][ni][cc] = 0.0f;

#pragma unroll
    for (int i = 0; i < 8; i++) cp16(sb + dstw[i] * 4, src[i]);
    CP_COMMIT(); CP_WAIT0();
    __syncthreads();

    for (int c = 0; c < 32; c++) {
        const int b = c & 1;
        if (c + 1 < 32) {
#pragma unroll
            for (int i = 0; i < 8; i++)
                cp16(sb + (dstw[i] + (uint32_t)(b ^ 1) * GTW) * 4,
                     src[i] + (c + 1) * 32);
            CP_COMMIT();
        }
        const float* As = smf + b * GTW;
        const float* Ws = smf + (2 + b) * GTW;
#pragma unroll
        for (int ks = 0; ks < 4; ks++) {
            uint32_t a[4][4];
#pragma unroll
            for (int mi = 0; mi < 4; mi++) {
                const float* p = As + (wm + 16 * mi + gid) * GPAD + ks * 8 + sub;
                a[mi][0] = __float_as_uint(p[0]);
                a[mi][1] = __float_as_uint(p[8 * GPAD]);
                a[mi][2] = __float_as_uint(p[4]);
                a[mi][3] = __float_as_uint(p[8 * GPAD + 4]);
            }
#pragma unroll
            for (int ni = 0; ni < 4; ni++) {
                const float* p = Ws + (wn + 8 * ni + gid) * GPAD + ks * 8 + sub;
                uint32_t b0 = __float_as_uint(p[0]);
                uint32_t b1 = __float_as_uint(p[4]);
#pragma unroll
                for (int mi = 0; mi < 4; mi++) mma8(acc[mi][ni], a[mi], b0, b1);
            }
        }
        if (c + 1 < 32) CP_WAIT0();
        __syncthreads();
    }

#pragma unroll
    for (int mi = 0; mi < 4; mi++) {
        int row = row0 + wm + 16 * mi + gid;
#pragma unroll
        for (int ni = 0; ni < 4; ni++) {
            int col = col0 + wn + 8 * ni + 2 * sub;
            *(float2*)(C + (size_t)row * Dd + col) =
                make_float2(acc[mi][ni][0], acc[mi][ni][1]);
            *(float2*)(C + (size_t)(row + 8) * Dd + col) =
                make_float2(acc[mi][ni][2], acc[mi][ni][3]);
        }
    }
}

// ======================================================================
// RoPE on q,k (double-precision angles) + tf32-RN pre-round of q,k,v.
// ======================================================================
__global__ void rope_kernel(float* __restrict__ q, float* __restrict__ k,
                            float* __restrict__ v)
{
    int idx = blockIdx.x * blockDim.x + threadIdx.x;
    int i = idx & 31;
    int h = (idx >> 5) & (Hh - 1);
    int m = idx >> 9;
    int s = m & (Ss - 1);

    double inv = pow(10000.0, -((double)(2 * i)) / (double)HDh);
    double ang = (double)s * inv;
    double sd, cd;
    sincos(ang, &sd, &cd);
    float c  = (float)cd;
    float sn = (float)sd;

    size_t base = (size_t)m * Dd + h * HDh + i;
    float q1 = q[base], q2 = q[base + 32];
    q[base]      = tf32rnf(q1 * c - q2 * sn);
    q[base + 32] = tf32rnf(q2 * c + q1 * sn);
    float k1 = k[base], k2 = k[base + 32];
    k[base]      = tf32rnf(k1 * c - k2 * sn);
    k[base + 32] = tf32rnf(k2 * c + k1 * sn);
    v[base]      = tf32rnf(v[base]);
    v[base + 32] = tf32rnf(v[base + 32]);
}

// ======================================================================
// Flash attention, causal, tf32 mma.sync, pipelined.
// CTA: 128 q-rows of one (b,h); 4 warps (128 thr), each warp owns
// 32 q-rows (2 m16 tiles) x all 64 cols -> 2x B-fragment reuse.
// Q frags in registers; Q smem region reused for P.
// K,V double-buffered via cp.async (prefetch next k-tile).
// Smem: QP[128][68] | K[2][64][68] | V[2][64][72] = 104 KB -> 2 CTA/SM.
// ======================================================================
#define QPAD 68
#define KPAD 68
#define VPAD 72
#define QP_OFF 0
#define KB_OFF (128*QPAD)                 // 8704
#define VB_OFF (KB_OFF + 2*64*KPAD)       // 17408
#define FA_WORDS (VB_OFF + 2*64*VPAD)     // 26624
#define FA_SMEM (FA_WORDS*4)              // 106496

__global__ void __launch_bounds__(128, 2) flash_tc(
    const float* __restrict__ Q, const float* __restrict__ K,
    const float* __restrict__ V, float* __restrict__ O)
{
    extern __shared__ float smf[];
    float* QP = smf + QP_OFF;
    const uint32_t sb = smem_u32(smf);

    const int tid = threadIdx.x;
    const int w = tid >> 5, lane = tid & 31;
    const int gid = lane >> 2, sub = lane & 3;

    const int bh = blockIdx.y;
    const int bb = bh >> 4, h = bh & 15;
    const int qt = gridDim.x - 1 - blockIdx.x;   // heavy tiles first
    const int q0 = qt * 128;
    const size_t hoff = (size_t)h * HDh;

    const float* Qg = Q + ((size_t)bb * Ss + q0) * Dd + hoff;
    const float* Kg = K + (size_t)bb * Ss * Dd + hoff;
    const float* Vg = V + (size_t)bb * Ss * Dd + hoff;
    const int nkt = 2 * qt + 2;

    // ---- prolog: Q tile (group), then K0+V0 (group) ----
#pragma unroll
    for (int i = 0; i < 16; i++) {
        int f = tid + i * 128;
        int r = f >> 4, c4 = (f & 15) << 2;
        cp16(sb + (QP_OFF + r * QPAD + c4) * 4, Qg + (size_t)r * Dd + c4);
    }
    CP_COMMIT();
#pragma unroll
    for (int i = 0; i < 8; i++) {
        int f = tid + i * 128;
        int r = f >> 4, c4 = (f & 15) << 2;
        cp16(sb + (KB_OFF + r * KPAD + c4) * 4, Kg + (size_t)r * Dd + c4);
        cp16(sb + (VB_OFF + r * VPAD + c4) * 4, Vg + (size_t)r * Dd + c4);
    }
    CP_COMMIT();

    CP_WAIT1();          // Q arrived
    __syncthreads();

    // Q fragments -> registers (2 m16 tiles, 64 regs); QP becomes P storage
    uint32_t qf[2][8][4];
#pragma unroll
    for (int mi = 0; mi < 2; mi++)
#pragma unroll
        for (int ks = 0; ks < 8; ks++) {
            const float* qp = QP + (w * 32 + mi * 16 + gid) * QPAD + ks * 8 + sub;
            qf[mi][ks][0] = __float_as_uint(qp[0]);
            qf[mi][ks][1] = __float_as_uint(qp[8 * QPAD]);
            qf[mi][ks][2] = __float_as_uint(qp[4]);
            qf[mi][ks][3] = __float_as_uint(qp[8 * QPAD + 4]);
        }

    float m_i[2][2], l_i[2][2];
    float acc[2][8][4];
#pragma unroll
    for (int mi = 0; mi < 2; mi++) {
        m_i[mi][0] = -1e30f; m_i[mi][1] = -1e30f;
        l_i[mi][0] = 0.0f;   l_i[mi][1] = 0.0f;
#pragma unroll
        for (int ni = 0; ni < 8; ni++)
#pragma unroll
            for (int cc = 0; cc < 4; cc++) acc[mi][ni][cc] = 0.0f;
    }

    float* Pw = QP + (w * 32) * QPAD;     // this warp's private P rows

    for (int kb = 0; kb < nkt; kb++) {
        const int b = kb & 1;
        const float* Ks = smf + KB_OFF + b * 64 * KPAD;
        const float* Vs = smf + VB_OFF + b * 64 * VPAD;

        CP_WAIT0();          // K_b, V_b resident (this thread)
        __syncthreads();     // whole tile visible; b^1 readers done

        // prefetch next tile into b^1
        if (kb + 1 < nkt) {
            const int k1 = (kb + 1) * 64;
#pragma unroll
            for (int i = 0; i < 8; i++) {
                int f = tid + i * 128;
                int r = f >> 4, c4 = (f & 15) << 2;
                cp16(sb + (KB_OFF + (b ^ 1) * 64 * KPAD + r * KPAD + c4) * 4,
                     Kg + (size_t)(k1 + r) * Dd + c4);
                cp16(sb + (VB_OFF + (b ^ 1) * 64 * VPAD + r * VPAD + c4) * 4,
                     Vg + (size_t)(k1 + r) * Dd + c4);
            }
            CP_COMMIT();
        }

        // last diagonal tile: warps 0,1 (rows < k0) are fully masked -> skip
        if (kb == 2 * qt + 1 && w < 2) continue;

        // ---- S = Q K^T ----
        float s[2][8][4];
#pragma unroll
        for (int mi = 0; mi < 2; mi++)
#pragma unroll
            for (int ni = 0; ni < 8; ni++)
#pragma unroll
                for (int cc = 0; cc < 4; cc++) s[mi][ni][cc] = 0.0f;

#pragma unroll
        for (int ks = 0; ks < 8; ks++) {
#pragma unroll
            for (int ni = 0; ni < 8; ni++) {
                const float* kp = Ks + (ni * 8 + gid) * KPAD + ks * 8 + sub;
                uint32_t b0 = __float_as_uint(kp[0]);
                uint32_t b1 = __float_as_uint(kp[4]);
                mma8(s[0][ni], qf[0][ks], b0, b1);
                mma8(s[1][ni], qf[1][ks], b0, b1);
            }
        }

        // ---- scale + causal mask + online softmax ----
        const int k0 = kb * 64;
        const bool mt = (kb >= 2 * qt);
#pragma unroll
        for (int mi = 0; mi < 2; mi++) {
            const int r0g = q0 + w * 32 + mi * 16 + gid;
            float rmax[2] = {-1e30f, -1e30f};
#pragma unroll
            for (int ni = 0; ni < 8; ni++) {
                int colb = k0 + ni * 8 + 2 * sub;
#pragma unroll
                for (int cc = 0; cc < 4; cc++) {
                    float sv = s[mi][ni][cc] * 0.125f;
                    if (mt) {
                        int row = r0g + ((cc >> 1) << 3);
                        int col = colb + (cc & 1);
                        if (col > row) sv = -1e30f;
                    }
                    s[mi][ni][cc] = sv;
                    rmax[cc >> 1] = fmaxf(rmax[cc >> 1], sv);
                }
            }
#pragma unroll
            for (int o = 1; o <= 2; o <<= 1) {
                rmax[0] = fmaxf(rmax[0], __shfl_xor_sync(0xffffffffu, rmax[0], o));
                rmax[1] = fmaxf(rmax[1], __shfl_xor_sync(0xffffffffu, rmax[1], o));
            }
            float mnew0 = fmaxf(m_i[mi][0], rmax[0]);
            float mnew1 = fmaxf(m_i[mi][1], rmax[1]);
            float corr0 = __expf(m_i[mi][0] - mnew0);
            float corr1 = __expf(m_i[mi][1] - mnew1);
            m_i[mi][0] = mnew0; m_i[mi][1] = mnew1;

            float rsum[2] = {0.0f, 0.0f};
#pragma unroll
            for (int ni = 0; ni < 8; ni++) {
                s[mi][ni][0] = __expf(s[mi][ni][0] - mnew0);
                s[mi][ni][1] = __expf(s[mi][ni][1] - mnew0);
                s[mi][ni][2] = __expf(s[mi][ni][2] - mnew1);
                s[mi][ni][3] = __expf(s[mi][ni][3] - mnew1);
                rsum[0] += s[mi][ni][0] + s[mi][ni][1];
                rsum[1] += s[mi][ni][2] + s[mi][ni][3];
                acc[mi][ni][0] *= corr0; acc[mi][ni][1] *= corr0;
                acc[mi][ni][2] *= corr1; acc[mi][ni][3] *= corr1;
            }
#pragma unroll
            for (int o = 1; o <= 2; o <<= 1) {
                rsum[0] += __shfl_xor_sync(0xffffffffu, rsum[0], o);
                rsum[1] += __shfl_xor_sync(0xffffffffu, rsum[1], o);
            }
            l_i[mi][0] = l_i[mi][0] * corr0 + rsum[0];
            l_i[mi][1] = l_i[mi][1] * corr1 + rsum[1];

            // ---- P -> warp-private smem (tf32) ----
            float* pp = Pw + (mi * 16 + gid) * QPAD + 2 * sub;
#pragma unroll
            for (int ni = 0; ni < 8; ni++) {
                *(float2*)(pp + ni * 8) = make_float2(
                    tf32rnf(s[mi][ni][0]), tf32rnf(s[mi][ni][1]));
                *(float2*)(pp + 8 * QPAD + ni * 8) = make_float2(
                    tf32rnf(s[mi][ni][2]), tf32rnf(s[mi][ni][3]));
            }
        }
        __syncwarp();

        // ---- O += P V ----
#pragma unroll
        for (int ks = 0; ks < 8; ks++) {
            uint32_t pa[2][4];
#pragma unroll
            for (int mi = 0; mi < 2; mi++) {
                const float* pr = Pw + (mi * 16 + gid) * QPAD + ks * 8 + sub;
                pa[mi][0] = __float_as_uint(pr[0]);
                pa[mi][1] = __float_as_uint(pr[8 * QPAD]);
                pa[mi][2] = __float_as_uint(pr[4]);
                pa[mi][3] = __float_as_uint(pr[8 * QPAD + 4]);
            }
#pragma unroll
            for (int ni = 0; ni < 8; ni++) {
                const float* vp = Vs + (ks * 8 + sub) * VPAD + ni * 8 + gid;
                uint32_t b0 = __float_as_uint(vp[0]);
                uint32_t b1 = __float_as_uint(vp[4 * VPAD]);
                mma8(acc[0][ni], pa[0], b0, b1);
                mma8(acc[1][ni], pa[1], b0, b1);
            }
        }
        __syncwarp();   // P reads done before next-iter P store
    }

    // ---- normalize and write O (tf32-rounded for the o-projection) ----
#pragma unroll
    for (int mi = 0; mi < 2; mi++)
#pragma unroll
        for (int rr = 0; rr < 2; rr++) {
            float inv = 1.0f / l_i[mi][rr];
            int row = q0 + w * 32 + mi * 16 + gid + rr * 8;
            float* Og = O + ((size_t)bb * Ss + row) * Dd + hoff + 2 * sub;
#pragma unroll
            for (int ni = 0; ni < 8; ni++)
                *(float2*)(Og + ni * 8) = make_float2(
                    tf32rnf(acc[mi][ni][2 * rr] * inv),
                    tf32rnf(acc[mi][ni][2 * rr + 1] * inv));
        }
}

// ======================================================================
// Launch
// ======================================================================
extern "C" void kernel_launch(void* const* d_in, const int* in_sizes, int n_in,
                              void* d_out, int out_size)
{
    const float* x  = (const float*)d_in[0];
    const float* wq = (const float*)d_in[1];
    const float* wk = (const float*)d_in[2];
    const float* wv = (const float*)d_in[3];
    const float* wo = (const float*)d_in[4];
    float* out = (float*)d_out;

    float *q, *k, *v, *o, *xr, *wr;
    cudaGetSymbolAddress((void**)&q,  g_q);
    cudaGetSymbolAddress((void**)&k,  g_k);
    cudaGetSymbolAddress((void**)&v,  g_v);
    cudaGetSymbolAddress((void**)&o,  g_o);
    cudaGetSymbolAddress((void**)&xr, g_xr);
    cudaGetSymbolAddress((void**)&wr, g_wr);

    cudaFuncSetAttribute(gemm_tc,  cudaFuncAttributeMaxDynamicSharedMemorySize, GEMM_SMEM);
    cudaFuncSetAttribute(flash_tc, cudaFuncAttributeMaxDynamicSharedMemorySize, FA_SMEM);

    const int WMAT = Dd * Dd;   // 1M floats per weight

    // 0) pre-round x and weights to tf32
    {
        int total4 = (Mm * Dd + 4 * WMAT) / 4;   // 2M float4
        round_inputs<<<total4 / 256, 256>>>(
            (const float4*)x, (const float4*)wq, (const float4*)wk,
            (const float4*)wv, (const float4*)wo,
            (float4*)xr, (float4*)wr);
    }

    // 1) fused q/k/v projections (tf32 mma.sync, pre-rounded inputs)
    gemm_tc<<<dim3(Dd / 128, Mm / 128, 3), 256, GEMM_SMEM>>>(
        xr, wr, wr + WMAT, wr + 2 * WMAT, q, k, v);

    // 2) RoPE + tf32 pre-round of q,k,v
    rope_kernel<<<(Mm * Hh * 32) / 256, 256>>>(q, k, v);

    // 3) causal flash attention (tf32 mma.sync, pipelined)
    flash_tc<<<dim3(Ss / 128, Bb * Hh), 128, FA_SMEM>>>(q, k, v, o);

    // 4) output projection (O already tf32-rounded by flash epilogue)
    gemm_tc<<<dim3(Dd / 128, Mm / 128, 1), 256, GEMM_SMEM>>>(
        o, wr + 3 * WMAT, wr + 3 * WMAT, wr + 3 * WMAT, out, out, out);
}

// round 6
// speedup vs baseline: 2.5346x; 1.1097x over previous
#include <cuda_runtime.h>
#include <math.h>
#include <stdint.h>

// Problem constants
#define Bb 2
#define Ss 2048
#define Dd 1024
#define Hh 16
#define HDh 64
#define Mm (Bb*Ss)   // 4096

// Scratch (device globals)
__device__ float g_q[Mm*Dd];          // row-major gemm outputs
__device__ float g_k[Mm*Dd];
__device__ float g_v[Mm*Dd];
__device__ float g_xr[Mm*Dd];         // x, A-frag-permuted
__device__ float g_wr[4*Dd*Dd];       // weights, B-frag-permuted
__device__ float g_qp[Mm*Dd];         // Q per (b,h), A-frag-permuted
__device__ float g_kp[Mm*Dd];         // K per (b,h), B-frag-permuted
__device__ float g_vp[Mm*Dd];         // V per (b,h), B-frag-permuted
__device__ float g_op[Mm*Dd];         // attn out, global A-frag-permuted

// ======================================================================
// Helpers
// ======================================================================
__device__ __forceinline__ uint32_t smem_u32(const void* p) {
    uint32_t a;
    asm("{ .reg .u64 t; cvta.to.shared.u64 t, %1; cvt.u32.u64 %0, t; }"
        : "=r"(a) : "l"(p));
    return a;
}
__device__ __forceinline__ uint32_t tf32rn(float x) {
    uint32_t u;
    asm("cvt.rna.tf32.f32 %0, %1;" : "=r"(u) : "f"(x));
    return u;
}
__device__ __forceinline__ float tf32rnf(float x) {
    return __uint_as_float(tf32rn(x));
}
__device__ __forceinline__ void mma8(float* d, const uint32_t* a,
                                     uint32_t b0, uint32_t b1) {
    asm volatile(
        "mma.sync.aligned.m16n8k8.row.col.f32.tf32.tf32.f32 "
        "{%0,%1,%2,%3}, {%4,%5,%6,%7}, {%8,%9}, {%0,%1,%2,%3};"
        : "+f"(d[0]), "+f"(d[1]), "+f"(d[2]), "+f"(d[3])
        : "r"(a[0]), "r"(a[1]), "r"(a[2]), "r"(a[3]), "r"(b0), "r"(b1));
}
__device__ __forceinline__ void cp16(uint32_t dst, const void* src) {
    asm volatile("cp.async.cg.shared.global [%0], [%1], 16;"
                 :: "r"(dst), "l"(src) : "memory");
}
#define CP_COMMIT() asm volatile("cp.async.commit_group;" ::: "memory")
#define CP_WAIT0()  asm volatile("cp.async.wait_group 0;" ::: "memory")
#define CP_WAIT1()  asm volatile("cp.async.wait_group 1;" ::: "memory")

// ======================================================================
// Permute inputs: x -> A-frag layout, weights -> B-frag layout (tf32-RN).
// A layout: [m16][k8] blocks of 128 floats, lane l owns pos l*4+{0..3} =
//   (r=l/4, k=l%4), (r+8, k), (r, k+4), (r+8, k+4).
// B layout: [n8][k8] blocks of 64 floats, lane l owns pos l*2+{0,1} =
//   (k=l%4, n=l/4), (k=l%4+4, n=l/4).
// ======================================================================
__global__ void round_inputs(
    const float* __restrict__ x,
    const float* __restrict__ wq, const float* __restrict__ wk,
    const float* __restrict__ wv, const float* __restrict__ wo,
    float4* __restrict__ xr, float2* __restrict__ wr)
{
    const int XT = (Mm/16)*(Dd/8)*32;        // 1M threads: one float4 each
    int t = blockIdx.x * blockDim.x + threadIdx.x;
    if (t < XT) {
        int blk = t >> 5, l = t & 31;
        int m16 = blk >> 7, k8 = blk & 127;
        int r = m16 * 16 + (l >> 2), k = k8 * 8 + (l & 3);
        const float* p = x + (size_t)r * Dd + k;
        xr[t] = make_float4(tf32rnf(p[0]), tf32rnf(p[8 * Dd]),
                            tf32rnf(p[4]), tf32rnf(p[8 * Dd + 4]));
    } else {
        int j = t - XT;                       // 2M threads: one float2 each
        const int WT = (Dd/8)*(Dd/8)*32;      // 524288 per weight
        int ws = j / WT, rem = j % WT;
        const float* w = (ws == 0) ? wq : (ws == 1) ? wk : (ws == 2) ? wv : wo;
        int blk = rem >> 5, l = rem & 31;
        int n8 = blk >> 7, k8 = blk & 127;
        const float* p = w + (size_t)(n8 * 8 + (l >> 2)) * Dd + k8 * 8 + (l & 3);
        wr[j] = make_float2(tf32rnf(p[0]), tf32rnf(p[4]));
    }
}

// ======================================================================
// GEMM: C[m][n] = sum_k A[m][k] * W[n][k], tf32 mma.sync.
// A in A-frag layout, W in B-frag layout. CTA 128x128, 128 thr (4 warps,
// 64x64 warp tiles), K-chunk 32, cp.async double-buffered.
// smem: A[2][4096] | W[2][4096] = 64 KB -> 2 CTA/SM.
// ======================================================================
#define GA(b) ((b)*4096)
#define GW(b) (8192 + (b)*4096)
#define GEMM_SMEM 65536

__global__ void __launch_bounds__(128, 2) gemm_tc(
    const float* __restrict__ A,
    const float* __restrict__ W0, const float* __restrict__ W1, const float* __restrict__ W2,
    float* __restrict__ C0, float* __restrict__ C1, float* __restrict__ C2)
{
    extern __shared__ float smf[];
    const uint32_t sb = smem_u32(smf);

    const int tid = threadIdx.x;
    const int w = tid >> 5, lane = tid & 31;
    const int gid = lane >> 2, sub = lane & 3;
    const int wm16 = (w >> 1) * 4;            // row-block offset (m16 units)
    const int wn8  = (w & 1) * 8;             // col-block offset (n8 units)

    const float* Wt = (blockIdx.z == 0) ? W0 : (blockIdx.z == 1) ? W1 : W2;
    float*       C  = (blockIdx.z == 0) ? C0 : (blockIdx.z == 1) ? C1 : C2;
    const int row0 = blockIdx.y * 128, col0 = blockIdx.x * 128;

    // cp.async geometry: A tile = 1024 f4 (8 m16 x 4 k8 x 128f),
    // W tile = 1024 f4 (16 n8 x 4 k8 x 64f); 8 f4 each per thread.
    const float* srca[8];
    const float* srcw[8];
#pragma unroll
    for (int i = 0; i < 8; i++) {
        int f = tid + i * 128;
        {   // A: blk = f>>5 (r16l = blk>>2, k8l = blk&3), within = f&31
            int blk = f >> 5, wi = f & 31;
            srca[i] = A + ((size_t)(row0 / 16 + (blk >> 2)) * (Dd / 8) * 128)
                        + (blk & 3) * 128 + wi * 4;
        }
        {   // W: blk = f>>4 (n8l = blk>>2, k8l = blk&3), within = f&15
            int blk = f >> 4, wi = f & 15;
            srcw[i] = Wt + ((size_t)(col0 / 8 + (blk >> 2)) * (Dd / 8) * 64)
                         + (blk & 3) * 64 + wi * 4;
        }
    }
    // per-chunk gmem advance: A +4 k8-blocks*128 = 512 floats; W +256 floats

    float acc[4][8][4];
#pragma unroll
    for (int mi = 0; mi < 4; mi++)
#pragma unroll
        for (int ni = 0; ni < 8; ni++)
#pragma unroll
            for (int cc = 0; cc < 4; cc++) acc[mi][ni][cc] = 0.0f;

#pragma unroll
    for (int i = 0; i < 8; i++) {
        int f = tid + i * 128;
        cp16(sb + (GA(0) + f * 4) * 4, srca[i]);
        cp16(sb + (GW(0) + f * 4) * 4, srcw[i]);
    }
    CP_COMMIT(); CP_WAIT0();
    __syncthreads();

    for (int c = 0; c < 32; c++) {
        const int b = c & 1;
        if (c + 1 < 32) {
#pragma unroll
            for (int i = 0; i < 8; i++) {
                int f = tid + i * 128;
                cp16(sb + (GA(b ^ 1) + f * 4) * 4, srca[i] + (c + 1) * 512);
                cp16(sb + (GW(b ^ 1) + f * 4) * 4, srcw[i] + (c + 1) * 256);
            }
            CP_COMMIT();
        }
        const float* As = smf + GA(b);
        const float* Ws = smf + GW(b);
#pragma unroll
        for (int ks = 0; ks < 4; ks++) {
            uint32_t a[4][4];
#pragma unroll
            for (int mi = 0; mi < 4; mi++) {
                uint4 av = *((const uint4*)(As + ((wm16 + mi) * 4 + ks) * 128) + lane);
                a[mi][0] = av.x; a[mi][1] = av.y; a[mi][2] = av.z; a[mi][3] = av.w;
            }
#pragma unroll
            for (int ni = 0; ni < 8; ni++) {
                uint2 bv = *((const uint2*)(Ws + ((wn8 + ni) * 4 + ks) * 64) + lane);
#pragma unroll
                for (int mi = 0; mi < 4; mi++) mma8(acc[mi][ni], a[mi], bv.x, bv.y);
            }
        }
        if (c + 1 < 32) CP_WAIT0();
        __syncthreads();
    }

    // epilogue: row-major C
#pragma unroll
    for (int mi = 0; mi < 4; mi++) {
        int row = row0 + wm16 * 16 + mi * 16 + gid;
#pragma unroll
        for (int ni = 0; ni < 8; ni++) {
            int col = col0 + (wn8 + ni) * 8 + 2 * sub;
            *(float2*)(C + (size_t)row * Dd + col) =
                make_float2(acc[mi][ni][0], acc[mi][ni][1]);
            *(float2*)(C + (size_t)(row + 8) * Dd + col) =
                make_float2(acc[mi][ni][2], acc[mi][ni][3]);
        }
    }
}

// ======================================================================
// RoPE on q,k + write Qp (A-frag), Kp, Vp (B-frag) per (b,h), tf32-RN.
// Per-(b,h) matrix is [S=2048, 64]; buffers stride 2048*64 per bh.
// ======================================================================
__global__ void rope_kernel(const float* __restrict__ q,
                            const float* __restrict__ k,
                            const float* __restrict__ v,
                            float* __restrict__ Qp, float* __restrict__ Kp,
                            float* __restrict__ Vp)
{
    int idx = blockIdx.x * blockDim.x + threadIdx.x;
    int i = idx & 31;                 // pair index (d=i, d=i+32)
    int h = (idx >> 5) & (Hh - 1);
    int m = idx >> 9;
    int s = m & (Ss - 1);
    int bh = (m >> 11) * Hh + h;      // m/2048 * 16 + h

    double inv = pow(10000.0, -((double)(2 * i)) / (double)HDh);
    double ang = (double)s * inv;
    double sd, cd;
    sincos(ang, &sd, &cd);
    float c = (float)cd, sn = (float)sd;

    size_t base = (size_t)m * Dd + h * HDh + i;
    float q1 = q[base], q2 = q[base + 32];
    float k1 = k[base], k2 = k[base + 32];
    float qa = q1 * c - q2 * sn, qb = q2 * c + q1 * sn;
    float ka = k1 * c - k2 * sn, kb2 = k2 * c + k1 * sn;
    float va = v[base], vb = v[base + 32];

    size_t bho = (size_t)bh * (Ss * HDh);

    // Q: A-frag layout [s16][d8][128]
#pragma unroll
    for (int t = 0; t < 2; t++) {
        int d = i + t * 32;
        float val = t ? qb : qa;
        int l = (s & 7) * 4 + (d & 3);
        int j = ((s >> 3) & 1) + 2 * ((d >> 2) & 1);
        Qp[bho + ((size_t)(s >> 4) * 8 + (d >> 3)) * 128 + l * 4 + j] = tf32rnf(val);
    }
    // K: B-frag layout [s8][d8][64], n = s, k = d
#pragma unroll
    for (int t = 0; t < 2; t++) {
        int d = i + t * 32;
        float val = t ? kb2 : ka;
        int l = (s & 7) * 4 + (d & 3);
        int j = (d >> 2) & 1;
        Kp[bho + ((size_t)(s >> 3) * 8 + (d >> 3)) * 64 + l * 2 + j] = tf32rnf(val);
    }
    // V: B-frag layout [s8][d8][64], k = s, n = d
#pragma unroll
    for (int t = 0; t < 2; t++) {
        int d = i + t * 32;
        float val = t ? vb : va;
        int l = (d & 7) * 4 + (s & 3);
        int j = (s >> 2) & 1;
        Vp[bho + ((size_t)(s >> 3) * 8 + (d >> 3)) * 64 + l * 2 + j] = tf32rnf(val);
    }
}

// ======================================================================
// Flash attention, causal, tf32 mma.sync, fragment-permuted operands.
// CTA: 128 q-rows of one (b,h); 4 warps x (32 q-rows, 64 cols).
// smem: QP 8192 (Q frags, reused as P in A-frag layout) |
//       K[2][4096] | V[2][4096] = 96 KB -> 2 CTA/SM.
// ======================================================================
#define FQP 0
#define FK(b) (8192 + (b)*4096)
#define FV(b) (16384 + (b)*4096)
#define FA_SMEM (24576*4)

__global__ void __launch_bounds__(128, 2) flash_tc(
    const float* __restrict__ Qp, const float* __restrict__ Kp,
    const float* __restrict__ Vp, float* __restrict__ Op)
{
    extern __shared__ float smf[];
    const uint32_t sb = smem_u32(smf);

    const int tid = threadIdx.x;
    const int w = tid >> 5, lane = tid & 31;
    const int gid = lane >> 2, sub = lane & 3;

    const int bh = blockIdx.y;
    const int bb = bh >> 4, h = bh & 15;
    const int qt = gridDim.x - 1 - blockIdx.x;   // heavy tiles first
    const int q0 = qt * 128;

    const size_t bho = (size_t)bh * (Ss * HDh);
    const float* Qg = Qp + bho + (size_t)qt * 8192;
    const float* Kg = Kp + bho;
    const float* Vg = Vp + bho;
    const int nkt = 2 * qt + 2;

    // ---- prolog: Q (8192 floats), then K0+V0 (4096 each) ----
#pragma unroll
    for (int i = 0; i < 16; i++) {
        int f = tid + i * 128;
        cp16(sb + (FQP + f * 4) * 4, Qg + f * 4);
    }
    CP_COMMIT();
#pragma unroll
    for (int i = 0; i < 8; i++) {
        int f = tid + i * 128;
        cp16(sb + (FK(0) + f * 4) * 4, Kg + f * 4);
        cp16(sb + (FV(0) + f * 4) * 4, Vg + f * 4);
    }
    CP_COMMIT();

    CP_WAIT1();
    __syncthreads();

    // Q frags -> regs (A-layout LDS.128); QP region becomes per-warp P
    uint32_t qf[2][8][4];
#pragma unroll
    for (int mi = 0; mi < 2; mi++)
#pragma unroll
        for (int ks = 0; ks < 8; ks++) {
            uint4 av = *((const uint4*)(smf + FQP + ((w * 2 + mi) * 8 + ks) * 128) + lane);
            qf[mi][ks][0] = av.x; qf[mi][ks][1] = av.y;
            qf[mi][ks][2] = av.z; qf[mi][ks][3] = av.w;
        }

    float m_i[2][2], l_i[2][2];
    float acc[2][8][4];
#pragma unroll
    for (int mi = 0; mi < 2; mi++) {
        m_i[mi][0] = -1e30f; m_i[mi][1] = -1e30f;
        l_i[mi][0] = 0.0f;   l_i[mi][1] = 0.0f;
#pragma unroll
        for (int ni = 0; ni < 8; ni++)
#pragma unroll
            for (int cc = 0; cc < 4; cc++) acc[mi][ni][cc] = 0.0f;
    }

    float* Pw = smf + FQP + w * 2048;   // warp-private P (A-frag layout)

    for (int kb = 0; kb < nkt; kb++) {
        const int b = kb & 1;
        const float* Ks = smf + FK(b);
        const float* Vs = smf + FV(b);

        CP_WAIT0();
        __syncthreads();

        if (kb + 1 < nkt) {
            const float* Kn = Kg + (size_t)(kb + 1) * 4096;
            const float* Vn = Vg + (size_t)(kb + 1) * 4096;
#pragma unroll
            for (int i = 0; i < 8; i++) {
                int f = tid + i * 128;
                cp16(sb + (FK(b ^ 1) + f * 4) * 4, Kn + f * 4);
                cp16(sb + (FV(b ^ 1) + f * 4) * 4, Vn + f * 4);
            }
            CP_COMMIT();
        }

        // final diagonal tile: warps 0,1 fully masked -> skip compute
        if (kb == 2 * qt + 1 && w < 2) continue;

        // ---- S = Q K^T ----
        float s[2][8][4];
#pragma unroll
        for (int mi = 0; mi < 2; mi++)
#pragma unroll
            for (int ni = 0; ni < 8; ni++)
#pragma unroll
                for (int cc = 0; cc < 4; cc++) s[mi][ni][cc] = 0.0f;

#pragma unroll
        for (int ks = 0; ks < 8; ks++) {
#pragma unroll
            for (int ni = 0; ni < 8; ni++) {
                uint2 bv = *((const uint2*)(Ks + (ni * 8 + ks) * 64) + lane);
                mma8(s[0][ni], qf[0][ks], bv.x, bv.y);
                mma8(s[1][ni], qf[1][ks], bv.x, bv.y);
            }
        }

        // ---- scale + causal mask + online softmax ----
        const int k0 = kb * 64;
        const bool mt = (kb >= 2 * qt);
#pragma unroll
        for (int mi = 0; mi < 2; mi++) {
            const int r0g = q0 + w * 32 + mi * 16 + gid;
            float rmax[2] = {-1e30f, -1e30f};
#pragma unroll
            for (int ni = 0; ni < 8; ni++) {
                int colb = k0 + ni * 8 + 2 * sub;
#pragma unroll
                for (int cc = 0; cc < 4; cc++) {
                    float sv = s[mi][ni][cc] * 0.125f;
                    if (mt) {
                        int row = r0g + ((cc >> 1) << 3);
                        int col = colb + (cc & 1);
                        if (col > row) sv = -1e30f;
                    }
                    s[mi][ni][cc] = sv;
                    rmax[cc >> 1] = fmaxf(rmax[cc >> 1], sv);
                }
            }
#pragma unroll
            for (int o = 1; o <= 2; o <<= 1) {
                rmax[0] = fmaxf(rmax[0], __shfl_xor_sync(0xffffffffu, rmax[0], o));
                rmax[1] = fmaxf(rmax[1], __shfl_xor_sync(0xffffffffu, rmax[1], o));
            }
            float mnew0 = fmaxf(m_i[mi][0], rmax[0]);
            float mnew1 = fmaxf(m_i[mi][1], rmax[1]);
            float corr0 = __expf(m_i[mi][0] - mnew0);
            float corr1 = __expf(m_i[mi][1] - mnew1);
            m_i[mi][0] = mnew0; m_i[mi][1] = mnew1;

            float rsum[2] = {0.0f, 0.0f};
#pragma unroll
            for (int ni = 0; ni < 8; ni++) {
                s[mi][ni][0] = __expf(s[mi][ni][0] - mnew0);
                s[mi][ni][1] = __expf(s[mi][ni][1] - mnew0);
                s[mi][ni][2] = __expf(s[mi][ni][2] - mnew1);
                s[mi][ni][3] = __expf(s[mi][ni][3] - mnew1);
                rsum[0] += s[mi][ni][0] + s[mi][ni][1];
                rsum[1] += s[mi][ni][2] + s[mi][ni][3];
                acc[mi][ni][0] *= corr0; acc[mi][ni][1] *= corr0;
                acc[mi][ni][2] *= corr1; acc[mi][ni][3] *= corr1;
            }
#pragma unroll
            for (int o = 1; o <= 2; o <<= 1) {
                rsum[0] += __shfl_xor_sync(0xffffffffu, rsum[0], o);
                rsum[1] += __shfl_xor_sync(0xffffffffu, rsum[1], o);
            }
            l_i[mi][0] = l_i[mi][0] * corr0 + rsum[0];
            l_i[mi][1] = l_i[mi][1] * corr1 + rsum[1];

            // ---- P -> warp-private smem in A-frag layout (scatter STS.32) ----
#pragma unroll
            for (int ni = 0; ni < 8; ni++) {
#pragma unroll
                for (int cc = 0; cc < 4; cc++) {
                    int kin = 2 * sub + (cc & 1);
                    int pos = (gid * 4 + (kin & 3)) * 4 + (cc >> 1) + 2 * (sub >> 1);
                    Pw[(mi * 8 + ni) * 128 + pos] = tf32rnf(s[mi][ni][cc]);
                }
            }
        }
        __syncwarp();

        // ---- O += P V ----
#pragma unroll
        for (int ks = 0; ks < 8; ks++) {
            uint32_t pa[2][4];
#pragma unroll
            for (int mi = 0; mi < 2; mi++) {
                uint4 av = *((const uint4*)(Pw + (mi * 8 + ks) * 128) + lane);
                pa[mi][0] = av.x; pa[mi][1] = av.y;
                pa[mi][2] = av.z; pa[mi][3] = av.w;
            }
#pragma unroll
            for (int ni = 0; ni < 8; ni++) {
                uint2 bv = *((const uint2*)(Vs + (ks * 8 + ni) * 64) + lane);
                mma8(acc[0][ni], pa[0], bv.x, bv.y);
                mma8(acc[1][ni], pa[1], bv.x, bv.y);
            }
        }
        __syncwarp();
    }

    // ---- normalize, write Op in the GLOBAL gemm-A-frag layout ----
#pragma unroll
    for (int mi = 0; mi < 2; mi++) {
        int m16 = bb * 128 + qt * 8 + w * 2 + mi;   // global row-block
#pragma unroll
        for (int ni = 0; ni < 8; ni++) {
            float* blkp = Op + ((size_t)m16 * (Dd / 8) + h * 8 + ni) * 128;
#pragma unroll
            for (int cc = 0; cc < 4; cc++) {
                float inv = 1.0f / l_i[mi][cc >> 1];
                int kin = 2 * sub + (cc & 1);
                int pos = (gid * 4 + (kin & 3)) * 4 + (cc >> 1) + 2 * (sub >> 1);
                blkp[pos] = tf32rnf(acc[mi][ni][cc] * inv);
            }
        }
    }
}

// ======================================================================
// Launch
// ======================================================================
extern "C" void kernel_launch(void* const* d_in, const int* in_sizes, int n_in,
                              void* d_out, int out_size)
{
    const float* x  = (const float*)d_in[0];
    const float* wq = (const float*)d_in[1];
    const float* wk = (const float*)d_in[2];
    const float* wv = (const float*)d_in[3];
    const float* wo = (const float*)d_in[4];
    float* out = (float*)d_out;

    float *q, *k, *v, *xr, *wr, *qp, *kp, *vp, *op;
    cudaGetSymbolAddress((void**)&q,  g_q);
    cudaGetSymbolAddress((void**)&k,  g_k);
    cudaGetSymbolAddress((void**)&v,  g_v);
    cudaGetSymbolAddress((void**)&xr, g_xr);
    cudaGetSymbolAddress((void**)&wr, g_wr);
    cudaGetSymbolAddress((void**)&qp, g_qp);
    cudaGetSymbolAddress((void**)&kp, g_kp);
    cudaGetSymbolAddress((void**)&vp, g_vp);
    cudaGetSymbolAddress((void**)&op, g_op);

    cudaFuncSetAttribute(gemm_tc,  cudaFuncAttributeMaxDynamicSharedMemorySize, GEMM_SMEM);
    cudaFuncSetAttribute(flash_tc, cudaFuncAttributeMaxDynamicSharedMemorySize, FA_SMEM);

    const int WMAT = Dd * Dd;   // floats per weight (permuted: same count)

    // 0) permute+round x (A-layout) and weights (B-layout)
    {
        int total = (Mm/16)*(Dd/8)*32 + 4 * ((Dd/8)*(Dd/8)*32);   // 3M threads
        round_inputs<<<total / 256, 256>>>(x, wq, wk, wv, wo,
                                           (float4*)xr, (float2*)wr);
    }

    // 1) fused q/k/v projections
    gemm_tc<<<dim3(Dd / 128, Mm / 128, 3), 128, GEMM_SMEM>>>(
        xr, wr, wr + WMAT, wr + 2 * WMAT, q, k, v);

    // 2) RoPE + permute into frag layouts
    rope_kernel<<<(Mm * Hh * 32) / 256, 256>>>(q, k, v, qp, kp, vp);

    // 3) causal flash attention
    flash_tc<<<dim3(Ss / 128, Bb * Hh), 128, FA_SMEM>>>(qp, kp, vp, op);

    // 4) output projection (Op already in A-frag layout)
    gemm_tc<<<dim3(Dd / 128, Mm / 128, 1), 128, GEMM_SMEM>>>(
        op, wr + 3 * WMAT, wr + 3 * WMAT, wr + 3 * WMAT, out, out, out);
}

// round 7
// speedup vs baseline: 5.0053x; 1.9748x over previous
#include <cuda_runtime.h>
#include <math.h>
#include <stdint.h>

// Problem constants
#define Bb 2
#define Ss 2048
#define Dd 1024
#define Hh 16
#define HDh 64
#define Mm (Bb*Ss)   // 4096

// Scratch (device globals)
__device__ float g_q[Mm*Dd];          // row-major gemm outputs
__device__ float g_k[Mm*Dd];
__device__ float g_v[Mm*Dd];
__device__ float g_xr[Mm*Dd];         // x, A-frag-permuted
__device__ float g_wr[4*Dd*Dd];       // weights, B-frag-permuted
__device__ float g_qp[Mm*Dd];         // Q per (b,h), A-frag-permuted
__device__ float g_kp[Mm*Dd];         // K per (b,h), B-frag-permuted
__device__ float g_vp[Mm*Dd];         // V per (b,h), B-frag-permuted (k=s,n=d)
__device__ float g_op[Mm*Dd];         // attn out, global A-frag-permuted
__device__ float g_cos[Ss*32];
__device__ float g_sin[Ss*32];

// ======================================================================
// Helpers
// ======================================================================
__device__ __forceinline__ uint32_t smem_u32(const void* p) {
    uint32_t a;
    asm("{ .reg .u64 t; cvta.to.shared.u64 t, %1; cvt.u32.u64 %0, t; }"
        : "=r"(a) : "l"(p));
    return a;
}
__device__ __forceinline__ uint32_t tf32rn(float x) {
    uint32_t u;
    asm("cvt.rna.tf32.f32 %0, %1;" : "=r"(u) : "f"(x));
    return u;
}
__device__ __forceinline__ float tf32rnf(float x) {
    return __uint_as_float(tf32rn(x));
}
__device__ __forceinline__ void mma8(float* d, const uint32_t* a,
                                     uint32_t b0, uint32_t b1) {
    asm volatile(
        "mma.sync.aligned.m16n8k8.row.col.f32.tf32.tf32.f32 "
        "{%0,%1,%2,%3}, {%4,%5,%6,%7}, {%8,%9}, {%0,%1,%2,%3};"
        : "+f"(d[0]), "+f"(d[1]), "+f"(d[2]), "+f"(d[3])
        : "r"(a[0]), "r"(a[1]), "r"(a[2]), "r"(a[3]), "r"(b0), "r"(b1));
}
__device__ __forceinline__ void cp16(uint32_t dst, const void* src) {
    asm volatile("cp.async.cg.shared.global [%0], [%1], 16;"
                 :: "r"(dst), "l"(src) : "memory");
}
#define CP_COMMIT() asm volatile("cp.async.commit_group;" ::: "memory")
#define CP_WAIT0()  asm volatile("cp.async.wait_group 0;" ::: "memory")
#define CP_WAIT1()  asm volatile("cp.async.wait_group 1;" ::: "memory")

// ======================================================================
// RoPE cos/sin tables (65536 entries each)
// ======================================================================
__global__ void build_tab(float* __restrict__ ct, float* __restrict__ st)
{
    int idx = blockIdx.x * blockDim.x + threadIdx.x;
    int s = idx >> 5, i = idx & 31;
    double inv = pow(10000.0, -((double)(2 * i)) / (double)HDh);
    double sd, cd;
    sincos((double)s * inv, &sd, &cd);
    ct[idx] = (float)cd;
    st[idx] = (float)sd;
}

// ======================================================================
// permA: x [M,K] row-major -> A-frag layout (tiled, coalesced both sides).
// A block (m16,k8): 128 floats; lane l owns l*4+{0..3} =
//   (r=l/4,k=l%4),(r+8,k),(r,k+4),(r+8,k+4).
// ======================================================================
__global__ __launch_bounds__(256) void permA(
    const float* __restrict__ A, float* __restrict__ D, int K)
{
    __shared__ float ts[64][68];
    const int r0 = blockIdx.x * 64, c0 = blockIdx.y * 64;
    const int tid = threadIdx.x;
#pragma unroll
    for (int i = 0; i < 4; i++) {
        int f = tid + i * 256;
        int r = f >> 4, c4 = (f & 15) << 2;
        *(float4*)&ts[r][c4] = *(const float4*)(A + (size_t)(r0 + r) * K + c0 + c4);
    }
    __syncthreads();
    const int w = tid >> 5, l = tid & 31;
    const int mi = w >> 1;
#pragma unroll
    for (int j = 0; j < 4; j++) {
        int ki = (w & 1) * 4 + j;
        int r = mi * 16 + (l >> 2), k = ki * 8 + (l & 3);
        float4 o = make_float4(tf32rnf(ts[r][k]),     tf32rnf(ts[r + 8][k]),
                               tf32rnf(ts[r][k + 4]), tf32rnf(ts[r + 8][k + 4]));
        *(float4*)(D + ((size_t)(r0 / 16 + mi) * (K / 8) + (c0 / 8 + ki)) * 128 + l * 4) = o;
    }
}

// ======================================================================
// permB: w [N,K] row-major -> B-frag layout. Block (n8,k8): 64 floats;
// lane l owns l*2+{0,1} = (k=l%4,n=l/4),(k+4,n). z selects weight.
// ======================================================================
__global__ __launch_bounds__(256) void permB(
    const float* __restrict__ W0, const float* __restrict__ W1,
    const float* __restrict__ W2, const float* __restrict__ W3,
    float* __restrict__ Dst)
{
    __shared__ float ts[64][68];
    const float* W = (blockIdx.z == 0) ? W0 : (blockIdx.z == 1) ? W1
                   : (blockIdx.z == 2) ? W2 : W3;
    float* D = Dst + (size_t)blockIdx.z * Dd * Dd;
    const int n0 = blockIdx.x * 64, k0 = blockIdx.y * 64;
    const int tid = threadIdx.x;
#pragma unroll
    for (int i = 0; i < 4; i++) {
        int f = tid + i * 256;
        int r = f >> 4, c4 = (f & 15) << 2;
        *(float4*)&ts[r][c4] = *(const float4*)(W + (size_t)(n0 + r) * Dd + k0 + c4);
    }
    __syncthreads();
    const int w = tid >> 5, l = tid & 31;
#pragma unroll
    for (int ki = 0; ki < 8; ki++) {
        int n = w * 8 + (l >> 2), k = ki * 8 + (l & 3);
        float2 o = make_float2(tf32rnf(ts[n][k]), tf32rnf(ts[n][k + 4]));
        *(float2*)(D + ((size_t)(n0 / 8 + w) * (Dd / 8) + (k0 / 8 + ki)) * 64 + l * 2) = o;
    }
}

// ======================================================================
// rope_perm: per (b,h), 64-seq tile. Reads q,k,v row-major tiles
// (coalesced), applies RoPE from tables, writes Qp (A-frag),
// Kp (B-frag, n=s,k=d), Vp (B-frag, k=s,n=d), all coalesced.
// ======================================================================
#define RQ 0
#define RK (64*68)
#define RV (2*64*68)
#define RC (3*64*68)
#define RS (3*64*68 + 64*32)
#define ROPE_SMEM ((3*64*68 + 2*64*32)*4)

__global__ __launch_bounds__(256) void rope_perm(
    const float* __restrict__ q, const float* __restrict__ k,
    const float* __restrict__ v,
    float* __restrict__ Qp, float* __restrict__ Kp, float* __restrict__ Vp)
{
    extern __shared__ float smf[];
    float* qs = smf + RQ;
    float* ks2 = smf + RK;
    float* vs = smf + RV;
    float* ct = smf + RC;
    float* st2 = smf + RS;

    const int bh = blockIdx.y;
    const int bb = bh >> 4, h = bh & 15;
    const int s0 = blockIdx.x * 64;
    const int tid = threadIdx.x;
    const size_t rowb = ((size_t)bb * Ss + s0) * Dd + h * HDh;

#pragma unroll
    for (int i = 0; i < 4; i++) {
        int f = tid + i * 256;
        int r = f >> 4, c4 = (f & 15) << 2;
        size_t g = rowb + (size_t)r * Dd + c4;
        *(float4*)&qs[r * 68 + c4]  = *(const float4*)(q + g);
        *(float4*)&ks2[r * 68 + c4] = *(const float4*)(k + g);
        *(float4*)&vs[r * 68 + c4]  = *(const float4*)(v + g);
    }
#pragma unroll
    for (int i = 0; i < 8; i++) {
        int idx = tid + i * 256;   // [0,2048)
        ct[idx]  = g_cos[(size_t)s0 * 32 + idx];
        st2[idx] = g_sin[(size_t)s0 * 32 + idx];
    }
    __syncthreads();

    const int w = tid >> 5, l = tid & 31;
    const size_t bho = (size_t)bh * (Ss * HDh);

    // rotated value at (s_local, d) from array a
#define ROT(a, s, d) \
    ( (a)[(s) * 68 + (d)] * ct[(s) * 32 + ((d) & 31)] + \
      (((d) < 32) ? -(a)[(s) * 68 + (d) + 32] : (a)[(s) * 68 + (d) - 32]) \
          * st2[(s) * 32 + ((d) & 31)] )

    // Qp: 4 m16 x 8 k8 A-blocks; warp w -> mi=w>>1, ki=(w&1)*4+j
    {
        int mi = w >> 1;
#pragma unroll
        for (int j = 0; j < 4; j++) {
            int ki = (w & 1) * 4 + j;
            int r = mi * 16 + (l >> 2), d = ki * 8 + (l & 3);
            float4 o = make_float4(
                tf32rnf(ROT(qs, r, d)),     tf32rnf(ROT(qs, r + 8, d)),
                tf32rnf(ROT(qs, r, d + 4)), tf32rnf(ROT(qs, r + 8, d + 4)));
            *(float4*)(Qp + bho + ((size_t)(s0 / 16 + mi) * 8 + ki) * 128 + l * 4) = o;
        }
    }
    // Kp: 8 s8 x 8 d8 B-blocks (n=s,k=d); warp w -> si=w
#pragma unroll
    for (int ki = 0; ki < 8; ki++) {
        int s = w * 8 + (l >> 2), d = ki * 8 + (l & 3);
        float2 o = make_float2(tf32rnf(ROT(ks2, s, d)), tf32rnf(ROT(ks2, s, d + 4)));
        *(float2*)(Kp + bho + ((size_t)(s0 / 8 + w) * 8 + ki) * 64 + l * 2) = o;
    }
    // Vp: 8 s8 x 8 d8 B-blocks (k=s,n=d); warp w -> si=w
#pragma unroll
    for (int ki = 0; ki < 8; ki++) {
        int s = w * 8 + (l & 3), d = ki * 8 + (l >> 2);
        float2 o = make_float2(tf32rnf(vs[s * 68 + d]), tf32rnf(vs[(s + 4) * 68 + d]));
        *(float2*)(Vp + bho + ((size_t)(s0 / 8 + w) * 8 + ki) * 64 + l * 2) = o;
    }
#undef ROT
}

// ======================================================================
// GEMM: C[m][n] = sum_k A[m][k]*W[n][k], tf32 mma.sync, frag layouts.
// CTA 128x128, 256 thr (8 warps, 64x32 warp tiles), K-chunk 32,
// cp.async double-buffered. smem 64 KB -> 2 CTA/SM (16 warps).
// ======================================================================
#define GA(b) ((b)*4096)
#define GW(b) (8192 + (b)*4096)
#define GEMM_SMEM 65536

__global__ void __launch_bounds__(256, 2) gemm_tc(
    const float* __restrict__ A,
    const float* __restrict__ W0, const float* __restrict__ W1, const float* __restrict__ W2,
    float* __restrict__ C0, float* __restrict__ C1, float* __restrict__ C2)
{
    extern __shared__ float smf[];
    const uint32_t sb = smem_u32(smf);

    const int tid = threadIdx.x;
    const int w = tid >> 5, lane = tid & 31;
    const int gid = lane >> 2, sub = lane & 3;
    const int wm16 = (w >> 2) * 4;            // 0 or 4
    const int wn8  = (w & 3) * 4;             // 0,4,8,12

    const float* Wt = (blockIdx.z == 0) ? W0 : (blockIdx.z == 1) ? W1 : W2;
    float*       C  = (blockIdx.z == 0) ? C0 : (blockIdx.z == 1) ? C1 : C2;
    const int row0 = blockIdx.y * 128, col0 = blockIdx.x * 128;

    // cp.async: A tile 1024 f4, W tile 1024 f4; 4+4 per thread
    const float* srca[4];
    const float* srcw[4];
#pragma unroll
    for (int i = 0; i < 4; i++) {
        int f = tid + i * 256;
        {   int blk = f >> 5, wi = f & 31;
            srca[i] = A + ((size_t)(row0 / 16 + (blk >> 2)) * (Dd / 8)
                           + (blk & 3)) * 128 + wi * 4; }
        {   int blk = f >> 4, wi = f & 15;
            srcw[i] = Wt + ((size_t)(col0 / 8 + (blk >> 2)) * (Dd / 8)
                            + (blk & 3)) * 64 + wi * 4; }
    }
    // per chunk: A advances 4 blocks*128 = 512 floats; W 4*64 = 256

    float acc[4][4][4];
#pragma unroll
    for (int mi = 0; mi < 4; mi++)
#pragma unroll
        for (int ni = 0; ni < 4; ni++)
#pragma unroll
            for (int cc = 0; cc < 4; cc++) acc[mi][ni][cc] = 0.0f;

#pragma unroll
    for (int i = 0; i < 4; i++) {
        int f = tid + i * 256;
        cp16(sb + (GA(0) + f * 4) * 4, srca[i]);
        cp16(sb + (GW(0) + f * 4) * 4, srcw[i]);
    }
    CP_COMMIT(); CP_WAIT0();
    __syncthreads();

    for (int c = 0; c < 32; c++) {
        const int b = c & 1;
        if (c + 1 < 32) {
#pragma unroll
            for (int i = 0; i < 4; i++) {
                int f = tid + i * 256;
                cp16(sb + (GA(b ^ 1) + f * 4) * 4, srca[i] + (c + 1) * 512);
                cp16(sb + (GW(b ^ 1) + f * 4) * 4, srcw[i] + (c + 1) * 256);
            }
            CP_COMMIT();
        }
        const float* As = smf + GA(b);
        const float* Ws = smf + GW(b);
#pragma unroll
        for (int ks = 0; ks < 4; ks++) {
            uint32_t a[4][4];
#pragma unroll
            for (int mi = 0; mi < 4; mi++) {
                uint4 av = *((const uint4*)(As + ((wm16 + mi) * 4 + ks) * 128) + lane);
                a[mi][0] = av.x; a[mi][1] = av.y; a[mi][2] = av.z; a[mi][3] = av.w;
            }
#pragma unroll
            for (int ni = 0; ni < 4; ni++) {
                uint2 bv = *((const uint2*)(Ws + ((wn8 + ni) * 4 + ks) * 64) + lane);
#pragma unroll
                for (int mi = 0; mi < 4; mi++) mma8(acc[mi][ni], a[mi], bv.x, bv.y);
            }
        }
        if (c + 1 < 32) CP_WAIT0();
        __syncthreads();
    }

#pragma unroll
    for (int mi = 0; mi < 4; mi++) {
        int row = row0 + (wm16 + mi) * 16 + gid;
#pragma unroll
        for (int ni = 0; ni < 4; ni++) {
            int col = col0 + (wn8 + ni) * 8 + 2 * sub;
            *(float2*)(C + (size_t)row * Dd + col) =
                make_float2(acc[mi][ni][0], acc[mi][ni][1]);
            *(float2*)(C + (size_t)(row + 8) * Dd + col) =
                make_float2(acc[mi][ni][2], acc[mi][ni][3]);
        }
    }
}

// ======================================================================
// Flash attention, causal, tf32 mma.sync, frag-permuted operands.
// CTA: 128 q-rows of one (b,h); 4 warps x (32 q-rows, 64 cols).
// Softmax in log2 domain (exp2f). smem 96 KB -> 2 CTA/SM.
// ======================================================================
#define FQP 0
#define FK(b) (8192 + (b)*4096)
#define FV(b) (16384 + (b)*4096)
#define FA_SMEM (24576*4)
#define SCL 0.180336877f    // 0.125 * log2(e)

__global__ void __launch_bounds__(128, 2) flash_tc(
    const float* __restrict__ Qp, const float* __restrict__ Kp,
    const float* __restrict__ Vp, float* __restrict__ Op)
{
    extern __shared__ float smf[];
    const uint32_t sb = smem_u32(smf);

    const int tid = threadIdx.x;
    const int w = tid >> 5, lane = tid & 31;
    const int gid = lane >> 2, sub = lane & 3;

    const int bh = blockIdx.y;
    const int bb = bh >> 4, h = bh & 15;
    const int qt = gridDim.x - 1 - blockIdx.x;
    const int q0 = qt * 128;

    const size_t bho = (size_t)bh * (Ss * HDh);
    const float* Qg = Qp + bho + (size_t)qt * 8192;
    const float* Kg = Kp + bho;
    const float* Vg = Vp + bho;
    const int nkt = 2 * qt + 2;

#pragma unroll
    for (int i = 0; i < 16; i++) {
        int f = tid + i * 128;
        cp16(sb + (FQP + f * 4) * 4, Qg + f * 4);
    }
    CP_COMMIT();
#pragma unroll
    for (int i = 0; i < 8; i++) {
        int f = tid + i * 128;
        cp16(sb + (FK(0) + f * 4) * 4, Kg + f * 4);
        cp16(sb + (FV(0) + f * 4) * 4, Vg + f * 4);
    }
    CP_COMMIT();

    CP_WAIT1();
    __syncthreads();

    uint32_t qf[2][8][4];
#pragma unroll
    for (int mi = 0; mi < 2; mi++)
#pragma unroll
        for (int ks = 0; ks < 8; ks++) {
            uint4 av = *((const uint4*)(smf + FQP + ((w * 2 + mi) * 8 + ks) * 128) + lane);
            qf[mi][ks][0] = av.x; qf[mi][ks][1] = av.y;
            qf[mi][ks][2] = av.z; qf[mi][ks][3] = av.w;
        }

    float m_i[2][2], l_i[2][2];
    float acc[2][8][4];
#pragma unroll
    for (int mi = 0; mi < 2; mi++) {
        m_i[mi][0] = -1e30f; m_i[mi][1] = -1e30f;
        l_i[mi][0] = 0.0f;   l_i[mi][1] = 0.0f;
#pragma unroll
        for (int ni = 0; ni < 8; ni++)
#pragma unroll
            for (int cc = 0; cc < 4; cc++) acc[mi][ni][cc] = 0.0f;
    }

    float* Pw = smf + FQP + w * 2048;

    for (int kb = 0; kb < nkt; kb++) {
        const int b = kb & 1;
        const float* Ks = smf + FK(b);
        const float* Vs = smf + FV(b);

        CP_WAIT0();
        __syncthreads();

        if (kb + 1 < nkt) {
            const float* Kn = Kg + (size_t)(kb + 1) * 4096;
            const float* Vn = Vg + (size_t)(kb + 1) * 4096;
#pragma unroll
            for (int i = 0; i < 8; i++) {
                int f = tid + i * 128;
                cp16(sb + (FK(b ^ 1) + f * 4) * 4, Kn + f * 4);
                cp16(sb + (FV(b ^ 1) + f * 4) * 4, Vn + f * 4);
            }
            CP_COMMIT();
        }

        if (kb == 2 * qt + 1 && w < 2) continue;

        float s[2][8][4];
#pragma unroll
        for (int mi = 0; mi < 2; mi++)
#pragma unroll
            for (int ni = 0; ni < 8; ni++)
#pragma unroll
                for (int cc = 0; cc < 4; cc++) s[mi][ni][cc] = 0.0f;

#pragma unroll
        for (int ks = 0; ks < 8; ks++) {
#pragma unroll
            for (int ni = 0; ni < 8; ni++) {
                uint2 bv = *((const uint2*)(Ks + (ni * 8 + ks) * 64) + lane);
                mma8(s[0][ni], qf[0][ks], bv.x, bv.y);
                mma8(s[1][ni], qf[1][ks], bv.x, bv.y);
            }
        }

        const int k0 = kb * 64;
        const bool mt = (kb >= 2 * qt);
#pragma unroll
        for (int mi = 0; mi < 2; mi++) {
            const int r0g = q0 + w * 32 + mi * 16 + gid;
            float rmax[2] = {-1e30f, -1e30f};
#pragma unroll
            for (int ni = 0; ni < 8; ni++) {
                int colb = k0 + ni * 8 + 2 * sub;
#pragma unroll
                for (int cc = 0; cc < 4; cc++) {
                    float sv = s[mi][ni][cc] * SCL;    // log2 domain
                    if (mt) {
                        int row = r0g + ((cc >> 1) << 3);
                        int col = colb + (cc & 1);
                        if (col > row) sv = -1e30f;
                    }
                    s[mi][ni][cc] = sv;
                    rmax[cc >> 1] = fmaxf(rmax[cc >> 1], sv);
                }
            }
#pragma unroll
            for (int o = 1; o <= 2; o <<= 1) {
                rmax[0] = fmaxf(rmax[0], __shfl_xor_sync(0xffffffffu, rmax[0], o));
                rmax[1] = fmaxf(rmax[1], __shfl_xor_sync(0xffffffffu, rmax[1], o));
            }
            float mnew0 = fmaxf(m_i[mi][0], rmax[0]);
            float mnew1 = fmaxf(m_i[mi][1], rmax[1]);
            float corr0 = exp2f(m_i[mi][0] - mnew0);
            float corr1 = exp2f(m_i[mi][1] - mnew1);
            m_i[mi][0] = mnew0; m_i[mi][1] = mnew1;

            float rsum[2] = {0.0f, 0.0f};
#pragma unroll
            for (int ni = 0; ni < 8; ni++) {
                s[mi][ni][0] = exp2f(s[mi][ni][0] - mnew0);
                s[mi][ni][1] = exp2f(s[mi][ni][1] - mnew0);
                s[mi][ni][2] = exp2f(s[mi][ni][2] - mnew1);
                s[mi][ni][3] = exp2f(s[mi][ni][3] - mnew1);
                rsum[0] += s[mi][ni][0] + s[mi][ni][1];
                rsum[1] += s[mi][ni][2] + s[mi][ni][3];
                acc[mi][ni][0] *= corr0; acc[mi][ni][1] *= corr0;
                acc[mi][ni][2] *= corr1; acc[mi][ni][3] *= corr1;
            }
#pragma unroll
            for (int o = 1; o <= 2; o <<= 1) {
                rsum[0] += __shfl_xor_sync(0xffffffffu, rsum[0], o);
                rsum[1] += __shfl_xor_sync(0xffffffffu, rsum[1], o);
            }
            l_i[mi][0] = l_i[mi][0] * corr0 + rsum[0];
            l_i[mi][1] = l_i[mi][1] * corr1 + rsum[1];

#pragma unroll
            for (int ni = 0; ni < 8; ni++) {
#pragma unroll
                for (int cc = 0; cc < 4; cc++) {
                    int kin = 2 * sub + (cc & 1);
                    int pos = (gid * 4 + (kin & 3)) * 4 + (cc >> 1) + 2 * (sub >> 1);
                    Pw[(mi * 8 + ni) * 128 + pos] = tf32rnf(s[mi][ni][cc]);
                }
            }
        }
        __syncwarp();

#pragma unroll
        for (int ks = 0; ks < 8; ks++) {
            uint32_t pa[2][4];
#pragma unroll
            for (int mi = 0; mi < 2; mi++) {
                uint4 av = *((const uint4*)(Pw + (mi * 8 + ks) * 128) + lane);
                pa[mi][0] = av.x; pa[mi][1] = av.y;
                pa[mi][2] = av.z; pa[mi][3] = av.w;
            }
#pragma unroll
            for (int ni = 0; ni < 8; ni++) {
                uint2 bv = *((const uint2*)(Vs + (ks * 8 + ni) * 64) + lane);
                mma8(acc[0][ni], pa[0], bv.x, bv.y);
                mma8(acc[1][ni], pa[1], bv.x, bv.y);
            }
        }
        __syncwarp();
    }

    // normalize, write Op in the GLOBAL gemm-A-frag layout
#pragma unroll
    for (int mi = 0; mi < 2; mi++) {
        int m16 = bb * 128 + qt * 8 + w * 2 + mi;
#pragma unroll
        for (int ni = 0; ni < 8; ni++) {
            float* blkp = Op + ((size_t)m16 * (Dd / 8) + h * 8 + ni) * 128;
#pragma unroll
            for (int cc = 0; cc < 4; cc++) {
                float inv = 1.0f / l_i[mi][cc >> 1];
                int kin = 2 * sub + (cc & 1);
                int pos = (gid * 4 + (kin & 3)) * 4 + (cc >> 1) + 2 * (sub >> 1);
                blkp[pos] = tf32rnf(acc[mi][ni][cc] * inv);
            }
        }
    }
}

// ======================================================================
// Launch
// ======================================================================
extern "C" void kernel_launch(void* const* d_in, const int* in_sizes, int n_in,
                              void* d_out, int out_size)
{
    const float* x  = (const float*)d_in[0];
    const float* wq = (const float*)d_in[1];
    const float* wk = (const float*)d_in[2];
    const float* wv = (const float*)d_in[3];
    const float* wo = (const float*)d_in[4];
    float* out = (float*)d_out;

    float *q, *k, *v, *xr, *wr, *qp, *kp, *vp, *op, *tc, *ts;
    cudaGetSymbolAddress((void**)&q,  g_q);
    cudaGetSymbolAddress((void**)&k,  g_k);
    cudaGetSymbolAddress((void**)&v,  g_v);
    cudaGetSymbolAddress((void**)&xr, g_xr);
    cudaGetSymbolAddress((void**)&wr, g_wr);
    cudaGetSymbolAddress((void**)&qp, g_qp);
    cudaGetSymbolAddress((void**)&kp, g_kp);
    cudaGetSymbolAddress((void**)&vp, g_vp);
    cudaGetSymbolAddress((void**)&op, g_op);
    cudaGetSymbolAddress((void**)&tc, g_cos);
    cudaGetSymbolAddress((void**)&ts, g_sin);

    cudaFuncSetAttribute(gemm_tc,   cudaFuncAttributeMaxDynamicSharedMemorySize, GEMM_SMEM);
    cudaFuncSetAttribute(flash_tc,  cudaFuncAttributeMaxDynamicSharedMemorySize, FA_SMEM);
    cudaFuncSetAttribute(rope_perm, cudaFuncAttributeMaxDynamicSharedMemorySize, ROPE_SMEM);

    const int WMAT = Dd * Dd;

    // 0) tables + permutes (all coalesced)
    build_tab<<<(Ss * 32) / 256, 256>>>(tc, ts);
    permA<<<dim3(Mm / 64, Dd / 64), 256>>>(x, xr, Dd);
    permB<<<dim3(Dd / 64, Dd / 64, 4), 256>>>(wq, wk, wv, wo, wr);

    // 1) fused q/k/v projections
    gemm_tc<<<dim3(Dd / 128, Mm / 128, 3), 256, GEMM_SMEM>>>(
        xr, wr, wr + WMAT, wr + 2 * WMAT, q, k, v);

    // 2) RoPE + permute into frag layouts (tiled)
    rope_perm<<<dim3(Ss / 64, Bb * Hh), 256, ROPE_SMEM>>>(q, k, v, qp, kp, vp);

    // 3) causal flash attention
    flash_tc<<<dim3(Ss / 128, Bb * Hh), 128, FA_SMEM>>>(qp, kp, vp, op);

    // 4) output projection (Op already A-frag)
    gemm_tc<<<dim3(Dd / 128, Mm / 128, 1), 256, GEMM_SMEM>>>(
        op, wr + 3 * WMAT, wr + 3 * WMAT, wr + 3 * WMAT, out, out, out);
}

// round 8
// speedup vs baseline: 8.6487x; 1.7279x over previous
#include <cuda_runtime.h>
#include <cuda_fp16.h>
#include <math.h>
#include <stdint.h>

// Problem constants
#define Bb 2
#define Ss 2048
#define Dd 1024
#define Hh 16
#define HDh 64
#define Mm (Bb*Ss)   // 4096

// Scratch (device globals)
__device__ float    g_q[Mm*Dd];        // fp32 row-major gemm outputs
__device__ float    g_k[Mm*Dd];
__device__ float    g_v[Mm*Dd];
__device__ uint32_t g_xr[Mm*Dd/2];     // x, A-frag fp16 (packed half2)
__device__ uint32_t g_wr[4*Dd*Dd/2];   // weights, B-frag fp16
__device__ uint32_t g_qp[Mm*Dd/2];     // Q per (b,h), A-frag fp16
__device__ uint32_t g_kp[Mm*Dd/2];     // K per (b,h), B-frag fp16 (n=s,k=d)
__device__ uint32_t g_vp[Mm*Dd/2];     // V per (b,h), B-frag fp16 (k=s,n=d)
__device__ uint32_t g_op[Mm*Dd/2];     // attn out, global A-frag fp16
__device__ float    g_cos[Ss*32];
__device__ float    g_sin[Ss*32];

// ======================================================================
// Helpers
// ======================================================================
__device__ __forceinline__ uint32_t smem_u32(const void* p) {
    uint32_t a;
    asm("{ .reg .u64 t; cvta.to.shared.u64 t, %1; cvt.u32.u64 %0, t; }"
        : "=r"(a) : "l"(p));
    return a;
}
__device__ __forceinline__ uint32_t pk(float a, float b) {
    __half2 h = __floats2half2_rn(a, b);   // a -> low half
    return *reinterpret_cast<uint32_t*>(&h);
}
// D += A*B, m16n8k16 fp16 (A 16x16 row-major, B 16x8 col-major, C fp32)
__device__ __forceinline__ void mma16(float* d, const uint32_t* a,
                                      uint32_t b0, uint32_t b1) {
    asm volatile(
        "mma.sync.aligned.m16n8k16.row.col.f32.f16.f16.f32 "
        "{%0,%1,%2,%3}, {%4,%5,%6,%7}, {%8,%9}, {%0,%1,%2,%3};"
        : "+f"(d[0]), "+f"(d[1]), "+f"(d[2]), "+f"(d[3])
        : "r"(a[0]), "r"(a[1]), "r"(a[2]), "r"(a[3]), "r"(b0), "r"(b1));
}
__device__ __forceinline__ void cp16(uint32_t dst, const void* src) {
    asm volatile("cp.async.cg.shared.global [%0], [%1], 16;"
                 :: "r"(dst), "l"(src) : "memory");
}
#define CP_COMMIT() asm volatile("cp.async.commit_group;" ::: "memory")
#define CP_WAIT0()  asm volatile("cp.async.wait_group 0;" ::: "memory")
#define CP_WAIT1()  asm volatile("cp.async.wait_group 1;" ::: "memory")

// ======================================================================
// RoPE cos/sin tables
// ======================================================================
__global__ void build_tab(float* __restrict__ ct, float* __restrict__ st)
{
    int idx = blockIdx.x * blockDim.x + threadIdx.x;
    int s = idx >> 5, i = idx & 31;
    double inv = pow(10000.0, -((double)(2 * i)) / (double)HDh);
    double sd, cd;
    sincos((double)s * inv, &sd, &cd);
    ct[idx] = (float)cd;
    st[idx] = (float)sd;
}

// ======================================================================
// permA: x [M,K] fp32 row-major -> fp16 A-frag layout.
// A block (m16,k16) = 128 uint32; lane l owns l*4+{0..3}:
//  a0=pk(A[gid][2s],A[gid][2s+1]) a1=rows+8 a2=cols+8 a3=both+8.
// ======================================================================
__global__ __launch_bounds__(256) void permA(
    const float* __restrict__ A, uint32_t* __restrict__ D, int K)
{
    __shared__ float ts[64][68];
    const int r0 = blockIdx.x * 64, c0 = blockIdx.y * 64;
    const int tid = threadIdx.x;
#pragma unroll
    for (int i = 0; i < 4; i++) {
        int f = tid + i * 256;
        int r = f >> 4, c4 = (f & 15) << 2;
        *(float4*)&ts[r][c4] = *(const float4*)(A + (size_t)(r0 + r) * K + c0 + c4);
    }
    __syncthreads();
    const int w = tid >> 5, l = tid & 31;
    const int gid = l >> 2, sub = l & 3;
    const int mi = w >> 1;
#pragma unroll
    for (int jj = 0; jj < 2; jj++) {
        int j = (w & 1) * 2 + jj;
        int r = mi * 16 + gid, d = j * 16 + 2 * sub;
        uint4 o = make_uint4(
            pk(ts[r][d],         ts[r][d + 1]),
            pk(ts[r + 8][d],     ts[r + 8][d + 1]),
            pk(ts[r][d + 8],     ts[r][d + 9]),
            pk(ts[r + 8][d + 8], ts[r + 8][d + 9]));
        *(uint4*)(D + ((size_t)(r0 / 16 + mi) * (K / 16) + (c0 / 16 + j)) * 128 + l * 4) = o;
    }
}

// ======================================================================
// permB: w [N,K] fp32 row-major -> fp16 B-frag layout.
// B block (n8,k16) = 64 uint32; lane l owns l*2+{0,1}:
//  b0=pk(W[gid][2s],W[gid][2s+1]) b1=pk(W[gid][2s+8],W[gid][2s+9]).
// ======================================================================
__global__ __launch_bounds__(256) void permB(
    const float* __restrict__ W0, const float* __restrict__ W1,
    const float* __restrict__ W2, const float* __restrict__ W3,
    uint32_t* __restrict__ Dst)
{
    __shared__ float ts[64][68];
    const float* W = (blockIdx.z == 0) ? W0 : (blockIdx.z == 1) ? W1
                   : (blockIdx.z == 2) ? W2 : W3;
    uint32_t* D = Dst + (size_t)blockIdx.z * (Dd * Dd / 2);
    const int n0 = blockIdx.x * 64, k0 = blockIdx.y * 64;
    const int tid = threadIdx.x;
#pragma unroll
    for (int i = 0; i < 4; i++) {
        int f = tid + i * 256;
        int r = f >> 4, c4 = (f & 15) << 2;
        *(float4*)&ts[r][c4] = *(const float4*)(W + (size_t)(n0 + r) * Dd + k0 + c4);
    }
    __syncthreads();
    const int w = tid >> 5, l = tid & 31;
    const int gid = l >> 2, sub = l & 3;
#pragma unroll
    for (int j = 0; j < 4; j++) {
        int n = w * 8 + gid, d = j * 16 + 2 * sub;
        uint2 o = make_uint2(pk(ts[n][d],     ts[n][d + 1]),
                             pk(ts[n][d + 8], ts[n][d + 9]));
        *(uint2*)(D + ((size_t)(n0 / 8 + w) * (Dd / 16) + (k0 / 16 + j)) * 64 + l * 2) = o;
    }
}

// ======================================================================
// rope_perm: per (b,h), 64-seq tile. RoPE q,k then write fp16 frag
// layouts: Qp A-frag [s16][d16]x128, Kp B-frag (n=s,k=d) [s8][d16]x64,
// Vp B-frag (k=s,n=d) [s16][d8]x64. Per-bh stride 65536 uint32.
// ======================================================================
#define RQ 0
#define RK (64*68)
#define RV (2*64*68)
#define RC (3*64*68)
#define RS (3*64*68 + 64*32)
#define ROPE_SMEM ((3*64*68 + 2*64*32)*4)

__global__ __launch_bounds__(256) void rope_perm(
    const float* __restrict__ q, const float* __restrict__ k,
    const float* __restrict__ v,
    uint32_t* __restrict__ Qp, uint32_t* __restrict__ Kp,
    uint32_t* __restrict__ Vp)
{
    extern __shared__ float smf[];
    float* qs = smf + RQ;
    float* ks2 = smf + RK;
    float* vs = smf + RV;
    float* ct = smf + RC;
    float* st2 = smf + RS;

    const int bh = blockIdx.y;
    const int bb = bh >> 4, h = bh & 15;
    const int s0 = blockIdx.x * 64;
    const int tid = threadIdx.x;
    const size_t rowb = ((size_t)bb * Ss + s0) * Dd + h * HDh;

#pragma unroll
    for (int i = 0; i < 4; i++) {
        int f = tid + i * 256;
        int r = f >> 4, c4 = (f & 15) << 2;
        size_t g = rowb + (size_t)r * Dd + c4;
        *(float4*)&qs[r * 68 + c4]  = *(const float4*)(q + g);
        *(float4*)&ks2[r * 68 + c4] = *(const float4*)(k + g);
        *(float4*)&vs[r * 68 + c4]  = *(const float4*)(v + g);
    }
#pragma unroll
    for (int i = 0; i < 8; i++) {
        int idx = tid + i * 256;
        ct[idx]  = g_cos[(size_t)s0 * 32 + idx];
        st2[idx] = g_sin[(size_t)s0 * 32 + idx];
    }
    __syncthreads();

    const int w = tid >> 5, l = tid & 31;
    const int gid = l >> 2, sub = l & 3;
    const size_t bho = (size_t)bh * 65536;

#define ROT(a, s, d) \
    ( (a)[(s) * 68 + (d)] * ct[(s) * 32 + ((d) & 31)] + \
      (((d) < 32) ? -(a)[(s) * 68 + (d) + 32] : (a)[(s) * 68 + (d) - 32]) \
          * st2[(s) * 32 + ((d) & 31)] )

    // Qp: 4 s16 x 4 d16 A-blocks; warp w -> mi=w>>1, j=(w&1)*2+jj
    {
        int mi = w >> 1;
#pragma unroll
        for (int jj = 0; jj < 2; jj++) {
            int j = (w & 1) * 2 + jj;
            int r = mi * 16 + gid, d = j * 16 + 2 * sub;
            uint4 o = make_uint4(
                pk(ROT(qs, r, d),         ROT(qs, r, d + 1)),
                pk(ROT(qs, r + 8, d),     ROT(qs, r + 8, d + 1)),
                pk(ROT(qs, r, d + 8),     ROT(qs, r, d + 9)),
                pk(ROT(qs, r + 8, d + 8), ROT(qs, r + 8, d + 9)));
            *(uint4*)(Qp + bho + ((size_t)(s0 / 16 + mi) * 4 + j) * 128 + l * 4) = o;
        }
    }
    // Kp: 8 s8 x 4 d16 B-blocks; warp w -> si=w, j 0..3
#pragma unroll
    for (int j = 0; j < 4; j++) {
        int sI = w * 8 + gid, d = j * 16 + 2 * sub;
        uint2 o = make_uint2(pk(ROT(ks2, sI, d),     ROT(ks2, sI, d + 1)),
                             pk(ROT(ks2, sI, d + 8), ROT(ks2, sI, d + 9)));
        *(uint2*)(Kp + bho + ((size_t)(s0 / 8 + w) * 4 + j) * 64 + l * 2) = o;
    }
    // Vp: 4 s16 x 8 d8 B-blocks (k=s,n=d); warp w -> dj=w, si 0..3
#pragma unroll
    for (int si = 0; si < 4; si++) {
        int sI = si * 16 + 2 * sub, d = w * 8 + gid;
        uint2 o = make_uint2(pk(vs[sI * 68 + d],       vs[(sI + 1) * 68 + d]),
                             pk(vs[(sI + 8) * 68 + d], vs[(sI + 9) * 68 + d]));
        *(uint2*)(Vp + bho + ((size_t)(s0 / 16 + si) * 8 + w) * 64 + l * 2) = o;
    }
#undef ROT
}

// ======================================================================
// GEMM: C[m][n] = sum_k A[m][k]*W[n][k], fp16 m16n8k16 mma.sync.
// CTA 128x128, 256 thr (8 warps, 64x32), K-chunk 64 (4 k16 blocks),
// cp.async double-buffered. smem 64 KB -> 2 CTA/SM. C fp32 row-major.
// ======================================================================
#define GA(b) ((b)*4096)
#define GW(b) (8192 + (b)*4096)
#define GEMM_SMEM 65536

__global__ void __launch_bounds__(256, 2) gemm_tc(
    const uint32_t* __restrict__ A,
    const uint32_t* __restrict__ W0, const uint32_t* __restrict__ W1,
    const uint32_t* __restrict__ W2,
    float* __restrict__ C0, float* __restrict__ C1, float* __restrict__ C2)
{
    extern __shared__ uint32_t smu[];
    const uint32_t sb = smem_u32(smu);

    const int tid = threadIdx.x;
    const int w = tid >> 5, lane = tid & 31;
    const int gid = lane >> 2, sub = lane & 3;
    const int wm16 = (w >> 2) * 4;
    const int wn8  = (w & 3) * 4;

    const uint32_t* Wt = (blockIdx.z == 0) ? W0 : (blockIdx.z == 1) ? W1 : W2;
    float*          C  = (blockIdx.z == 0) ? C0 : (blockIdx.z == 1) ? C1 : C2;
    const int row0 = blockIdx.y * 128, col0 = blockIdx.x * 128;

    const uint32_t* srca[4];
    const uint32_t* srcw[4];
#pragma unroll
    for (int i = 0; i < 4; i++) {
        int f = tid + i * 256;
        {   int blk = f >> 5, wi = f & 31;
            srca[i] = A + ((size_t)(row0 / 16 + (blk >> 2)) * (Dd / 16)
                           + (blk & 3)) * 128 + wi * 4; }
        {   int blk = f >> 4, wi = f & 15;
            srcw[i] = Wt + ((size_t)(col0 / 8 + (blk >> 2)) * (Dd / 16)
                            + (blk & 3)) * 64 + wi * 4; }
    }
    // per chunk: A advances 4 k16-blocks*128 = 512 words; W 4*64 = 256

    float acc[4][4][4];
#pragma unroll
    for (int mi = 0; mi < 4; mi++)
#pragma unroll
        for (int ni = 0; ni < 4; ni++)
#pragma unroll
            for (int cc = 0; cc < 4; cc++) acc[mi][ni][cc] = 0.0f;

#pragma unroll
    for (int i = 0; i < 4; i++) {
        int f = tid + i * 256;
        cp16(sb + (GA(0) + f * 4) * 4, srca[i]);
        cp16(sb + (GW(0) + f * 4) * 4, srcw[i]);
    }
    CP_COMMIT(); CP_WAIT0();
    __syncthreads();

    for (int c = 0; c < 16; c++) {
        const int b = c & 1;
        if (c + 1 < 16) {
#pragma unroll
            for (int i = 0; i < 4; i++) {
                int f = tid + i * 256;
                cp16(sb + (GA(b ^ 1) + f * 4) * 4, srca[i] + (c + 1) * 512);
                cp16(sb + (GW(b ^ 1) + f * 4) * 4, srcw[i] + (c + 1) * 256);
            }
            CP_COMMIT();
        }
        const uint32_t* As = smu + GA(b);
        const uint32_t* Ws = smu + GW(b);
#pragma unroll
        for (int ks = 0; ks < 4; ks++) {
            uint32_t a[4][4];
#pragma unroll
            for (int mi = 0; mi < 4; mi++) {
                uint4 av = *((const uint4*)(As + ((wm16 + mi) * 4 + ks) * 128) + lane);
                a[mi][0] = av.x; a[mi][1] = av.y; a[mi][2] = av.z; a[mi][3] = av.w;
            }
#pragma unroll
            for (int ni = 0; ni < 4; ni++) {
                uint2 bv = *((const uint2*)(Ws + ((wn8 + ni) * 4 + ks) * 64) + lane);
#pragma unroll
                for (int mi = 0; mi < 4; mi++) mma16(acc[mi][ni], a[mi], bv.x, bv.y);
            }
        }
        if (c + 1 < 16) CP_WAIT0();
        __syncthreads();
    }

#pragma unroll
    for (int mi = 0; mi < 4; mi++) {
        int row = row0 + (wm16 + mi) * 16 + gid;
#pragma unroll
        for (int ni = 0; ni < 4; ni++) {
            int col = col0 + (wn8 + ni) * 8 + 2 * sub;
            *(float2*)(C + (size_t)row * Dd + col) =
                make_float2(acc[mi][ni][0], acc[mi][ni][1]);
            *(float2*)(C + (size_t)(row + 8) * Dd + col) =
                make_float2(acc[mi][ni][2], acc[mi][ni][3]);
        }
    }
}

// ======================================================================
// Flash attention, causal, fp16 m16n8k16, frag-permuted operands.
// CTA: 128 q-rows of one (b,h); 4 warps x (32 q-rows, 64 cols).
// P packs directly from registers into MMA A-fragments (no smem trip).
// smem: Q 4096 | K[2][2048] | V[2][2048] = 48 KB.
// ======================================================================
#define FQ 0
#define FK(b) (4096 + (b)*2048)
#define FV(b) (8192 + (b)*2048)
#define FA_SMEM (12288*4)
#define SCL 0.180336877f    // 0.125 * log2(e)

__global__ void __launch_bounds__(128, 2) flash_tc(
    const uint32_t* __restrict__ Qp, const uint32_t* __restrict__ Kp,
    const uint32_t* __restrict__ Vp, uint32_t* __restrict__ Op)
{
    extern __shared__ uint32_t smu[];
    const uint32_t sb = smem_u32(smu);

    const int tid = threadIdx.x;
    const int w = tid >> 5, lane = tid & 31;
    const int gid = lane >> 2, sub = lane & 3;

    const int bh = blockIdx.y;
    const int bb = bh >> 4, h = bh & 15;
    const int qt = gridDim.x - 1 - blockIdx.x;
    const int q0 = qt * 128;

    const size_t bho = (size_t)bh * 65536;
    const uint32_t* Qg = Qp + bho + (size_t)qt * 4096;
    const uint32_t* Kg = Kp + bho;
    const uint32_t* Vg = Vp + bho;
    const int nkt = 2 * qt + 2;

#pragma unroll
    for (int i = 0; i < 8; i++) {
        int f = tid + i * 128;
        cp16(sb + (FQ + f * 4) * 4, Qg + f * 4);
    }
    CP_COMMIT();
#pragma unroll
    for (int i = 0; i < 4; i++) {
        int f = tid + i * 128;
        cp16(sb + (FK(0) + f * 4) * 4, Kg + f * 4);
        cp16(sb + (FV(0) + f * 4) * 4, Vg + f * 4);
    }
    CP_COMMIT();

    CP_WAIT1();
    __syncthreads();

    // Q frags -> regs: 2 m16 x 4 k16, LDS.128 each
    uint32_t qf[2][4][4];
#pragma unroll
    for (int mi = 0; mi < 2; mi++)
#pragma unroll
        for (int ks = 0; ks < 4; ks++) {
            uint4 av = *((const uint4*)(smu + FQ + ((w * 2 + mi) * 4 + ks) * 128) + lane);
            qf[mi][ks][0] = av.x; qf[mi][ks][1] = av.y;
            qf[mi][ks][2] = av.z; qf[mi][ks][3] = av.w;
        }

    float m_i[2][2], l_i[2][2];
    float acc[2][8][4];
#pragma unroll
    for (int mi = 0; mi < 2; mi++) {
        m_i[mi][0] = -1e30f; m_i[mi][1] = -1e30f;
        l_i[mi][0] = 0.0f;   l_i[mi][1] = 0.0f;
#pragma unroll
        for (int ni = 0; ni < 8; ni++)
#pragma unroll
            for (int cc = 0; cc < 4; cc++) acc[mi][ni][cc] = 0.0f;
    }

    for (int kb = 0; kb < nkt; kb++) {
        const int b = kb & 1;
        const uint32_t* Ks = smu + FK(b);
        const uint32_t* Vs = smu + FV(b);

        CP_WAIT0();
        __syncthreads();

        if (kb + 1 < nkt) {
            const uint32_t* Kn = Kg + (size_t)(kb + 1) * 2048;
            const uint32_t* Vn = Vg + (size_t)(kb + 1) * 2048;
#pragma unroll
            for (int i = 0; i < 4; i++) {
                int f = tid + i * 128;
                cp16(sb + (FK(b ^ 1) + f * 4) * 4, Kn + f * 4);
                cp16(sb + (FV(b ^ 1) + f * 4) * 4, Vn + f * 4);
            }
            CP_COMMIT();
        }

        if (kb == 2 * qt + 1 && w < 2) continue;   // fully-masked warps

        // ---- S = Q K^T ----
        float s[2][8][4];
#pragma unroll
        for (int mi = 0; mi < 2; mi++)
#pragma unroll
            for (int ni = 0; ni < 8; ni++)
#pragma unroll
                for (int cc = 0; cc < 4; cc++) s[mi][ni][cc] = 0.0f;

#pragma unroll
        for (int ks = 0; ks < 4; ks++) {
#pragma unroll
            for (int ni = 0; ni < 8; ni++) {
                uint2 bv = *((const uint2*)(Ks + (ni * 4 + ks) * 64) + lane);
                mma16(s[0][ni], qf[0][ks], bv.x, bv.y);
                mma16(s[1][ni], qf[1][ks], bv.x, bv.y);
            }
        }

        // ---- scale + causal mask + online softmax (log2 domain) ----
        const int k0 = kb * 64;
        const bool mt = (kb >= 2 * qt);
        uint32_t pa[2][4][4];
#pragma unroll
        for (int mi = 0; mi < 2; mi++) {
            const int r0g = q0 + w * 32 + mi * 16 + gid;
            float rmax[2] = {-1e30f, -1e30f};
#pragma unroll
            for (int ni = 0; ni < 8; ni++) {
                int colb = k0 + ni * 8 + 2 * sub;
#pragma unroll
                for (int cc = 0; cc < 4; cc++) {
                    float sv = s[mi][ni][cc] * SCL;
                    if (mt) {
                        int row = r0g + ((cc >> 1) << 3);
                        int col = colb + (cc & 1);
                        if (col > row) sv = -1e30f;
                    }
                    s[mi][ni][cc] = sv;
                    rmax[cc >> 1] = fmaxf(rmax[cc >> 1], sv);
                }
            }
#pragma unroll
            for (int o = 1; o <= 2; o <<= 1) {
                rmax[0] = fmaxf(rmax[0], __shfl_xor_sync(0xffffffffu, rmax[0], o));
                rmax[1] = fmaxf(rmax[1], __shfl_xor_sync(0xffffffffu, rmax[1], o));
            }
            float mnew0 = fmaxf(m_i[mi][0], rmax[0]);
            float mnew1 = fmaxf(m_i[mi][1], rmax[1]);
            float corr0 = exp2f(m_i[mi][0] - mnew0);
            float corr1 = exp2f(m_i[mi][1] - mnew1);
            m_i[mi][0] = mnew0; m_i[mi][1] = mnew1;

            float rsum[2] = {0.0f, 0.0f};
#pragma unroll
            for (int ni = 0; ni < 8; ni++) {
                s[mi][ni][0] = exp2f(s[mi][ni][0] - mnew0);
                s[mi][ni][1] = exp2f(s[mi][ni][1] - mnew0);
                s[mi][ni][2] = exp2f(s[mi][ni][2] - mnew1);
                s[mi][ni][3] = exp2f(s[mi][ni][3] - mnew1);
                rsum[0] += s[mi][ni][0] + s[mi][ni][1];
                rsum[1] += s[mi][ni][2] + s[mi][ni][3];
                acc[mi][ni][0] *= corr0; acc[mi][ni][1] *= corr0;
                acc[mi][ni][2] *= corr1; acc[mi][ni][3] *= corr1;
            }
#pragma unroll
            for (int o = 1; o <= 2; o <<= 1) {
                rsum[0] += __shfl_xor_sync(0xffffffffu, rsum[0], o);
                rsum[1] += __shfl_xor_sync(0xffffffffu, rsum[1], o);
            }
            l_i[mi][0] = l_i[mi][0] * corr0 + rsum[0];
            l_i[mi][1] = l_i[mi][1] * corr1 + rsum[1];

            // ---- P -> A-fragments directly in registers ----
#pragma unroll
            for (int j = 0; j < 4; j++) {
                pa[mi][j][0] = pk(s[mi][2 * j][0],     s[mi][2 * j][1]);
                pa[mi][j][1] = pk(s[mi][2 * j][2],     s[mi][2 * j][3]);
                pa[mi][j][2] = pk(s[mi][2 * j + 1][0], s[mi][2 * j + 1][1]);
                pa[mi][j][3] = pk(s[mi][2 * j + 1][2], s[mi][2 * j + 1][3]);
            }
        }

        // ---- O += P V ----
#pragma unroll
        for (int j = 0; j < 4; j++) {
#pragma unroll
            for (int ni = 0; ni < 8; ni++) {
                uint2 bv = *((const uint2*)(Vs + (j * 8 + ni) * 64) + lane);
                mma16(acc[0][ni], pa[0][j], bv.x, bv.y);
                mma16(acc[1][ni], pa[1][j], bv.x, bv.y);
            }
        }
    }

    // ---- normalize, write Op in GLOBAL fp16 A-frag layout ----
#pragma unroll
    for (int mi = 0; mi < 2; mi++) {
        int m16 = bb * 128 + qt * 8 + w * 2 + mi;
        float inv0 = 1.0f / l_i[mi][0];
        float inv1 = 1.0f / l_i[mi][1];
#pragma unroll
        for (int j = 0; j < 4; j++) {
            uint4 o = make_uint4(
                pk(acc[mi][2 * j][0] * inv0,     acc[mi][2 * j][1] * inv0),
                pk(acc[mi][2 * j][2] * inv1,     acc[mi][2 * j][3] * inv1),
                pk(acc[mi][2 * j + 1][0] * inv0, acc[mi][2 * j + 1][1] * inv0),
                pk(acc[mi][2 * j + 1][2] * inv1, acc[mi][2 * j + 1][3] * inv1));
            *(uint4*)(Op + ((size_t)m16 * (Dd / 16) + h * 4 + j) * 128 + lane * 4) = o;
        }
    }
}

// ======================================================================
// Launch
// ======================================================================
extern "C" void kernel_launch(void* const* d_in, const int* in_sizes, int n_in,
                              void* d_out, int out_size)
{
    const float* x  = (const float*)d_in[0];
    const float* wq = (const float*)d_in[1];
    const float* wk = (const float*)d_in[2];
    const float* wv = (const float*)d_in[3];
    const float* wo = (const float*)d_in[4];
    float* out = (float*)d_out;

    float *q, *k, *v, *tc, *ts;
    uint32_t *xr, *wr, *qp, *kp, *vp, *op;
    cudaGetSymbolAddress((void**)&q,  g_q);
    cudaGetSymbolAddress((void**)&k,  g_k);
    cudaGetSymbolAddress((void**)&v,  g_v);
    cudaGetSymbolAddress((void**)&xr, g_xr);
    cudaGetSymbolAddress((void**)&wr, g_wr);
    cudaGetSymbolAddress((void**)&qp, g_qp);
    cudaGetSymbolAddress((void**)&kp, g_kp);
    cudaGetSymbolAddress((void**)&vp, g_vp);
    cudaGetSymbolAddress((void**)&op, g_op);
    cudaGetSymbolAddress((void**)&tc, g_cos);
    cudaGetSymbolAddress((void**)&ts, g_sin);

    cudaFuncSetAttribute(gemm_tc,   cudaFuncAttributeMaxDynamicSharedMemorySize, GEMM_SMEM);
    cudaFuncSetAttribute(flash_tc,  cudaFuncAttributeMaxDynamicSharedMemorySize, FA_SMEM);
    cudaFuncSetAttribute(rope_perm, cudaFuncAttributeMaxDynamicSharedMemorySize, ROPE_SMEM);

    const int WMAT = Dd * Dd / 2;   // uint32 words per permuted weight

    // 0) tables + permutes
    build_tab<<<(Ss * 32) / 256, 256>>>(tc, ts);
    permA<<<dim3(Mm / 64, Dd / 64), 256>>>(x, xr, Dd);
    permB<<<dim3(Dd / 64, Dd / 64, 4), 256>>>(wq, wk, wv, wo, wr);

    // 1) fused q/k/v projections (fp16 mma)
    gemm_tc<<<dim3(Dd / 128, Mm / 128, 3), 256, GEMM_SMEM>>>(
        xr, wr, wr + WMAT, wr + 2 * WMAT, q, k, v);

    // 2) RoPE + permute into fp16 frag layouts
    rope_perm<<<dim3(Ss / 64, Bb * Hh), 256, ROPE_SMEM>>>(q, k, v, qp, kp, vp);

    // 3) causal flash attention (fp16 mma)
    flash_tc<<<dim3(Ss / 128, Bb * Hh), 128, FA_SMEM>>>(qp, kp, vp, op);

    // 4) output projection (Op already fp16 A-frag)
    gemm_tc<<<dim3(Dd / 128, Mm / 128, 1), 256, GEMM_SMEM>>>(
        op, wr + 3 * WMAT, wr + 3 * WMAT, wr + 3 * WMAT, out, out, out);
}

// round 9
// speedup vs baseline: 8.7309x; 1.0095x over previous
#include <cuda_runtime.h>
#include <cuda_fp16.h>
#include <math.h>
#include <stdint.h>

// Problem constants
#define Bb 2
#define Ss 2048
#define Dd 1024
#define Hh 16
#define HDh 64
#define Mm (Bb*Ss)   // 4096

// Scratch (device globals), all fp16-packed uint32 unless noted
__device__ uint32_t g_xA[Mm*Dd/2];     // x, A-frag
__device__ uint32_t g_xB[Mm*Dd/2];     // x, B-frag (n=s)
__device__ uint32_t g_wqB[Dd*Dd/2];
__device__ uint32_t g_wkB[Dd*Dd/2];
__device__ uint32_t g_woB[Dd*Dd/2];
__device__ uint32_t g_wvA[Dd*Dd/2];    // wv, A-frag (for transposed V gemm)
__device__ uint32_t g_qp[Mm*Dd/2];     // Q per (b,h), A-frag
__device__ uint32_t g_kp[Mm*Dd/2];     // K per (b,h), B-frag (n=s,k=d)
__device__ uint32_t g_vp[Mm*Dd/2];     // V per (b,h), B-frag (k=s,n=d)
__device__ uint32_t g_op[Mm*Dd/2];     // attn out, global A-frag
__device__ float    g_cos[Ss*32];
__device__ float    g_sin[Ss*32];

// ======================================================================
// Helpers
// ======================================================================
__device__ __forceinline__ uint32_t smem_u32(const void* p) {
    uint32_t a;
    asm("{ .reg .u64 t; cvta.to.shared.u64 t, %1; cvt.u32.u64 %0, t; }"
        : "=r"(a) : "l"(p));
    return a;
}
__device__ __forceinline__ uint32_t pk(float a, float b) {
    __half2 h = __floats2half2_rn(a, b);
    return *reinterpret_cast<uint32_t*>(&h);
}
__device__ __forceinline__ void mma16(float* d, const uint32_t* a,
                                      uint32_t b0, uint32_t b1) {
    asm volatile(
        "mma.sync.aligned.m16n8k16.row.col.f32.f16.f16.f32 "
        "{%0,%1,%2,%3}, {%4,%5,%6,%7}, {%8,%9}, {%0,%1,%2,%3};"
        : "+f"(d[0]), "+f"(d[1]), "+f"(d[2]), "+f"(d[3])
        : "r"(a[0]), "r"(a[1]), "r"(a[2]), "r"(a[3]), "r"(b0), "r"(b1));
}
__device__ __forceinline__ void cp16(uint32_t dst, const void* src) {
    asm volatile("cp.async.cg.shared.global [%0], [%1], 16;"
                 :: "r"(dst), "l"(src) : "memory");
}
#define CP_COMMIT() asm volatile("cp.async.commit_group;" ::: "memory")
#define CP_WAIT0()  asm volatile("cp.async.wait_group 0;" ::: "memory")
#define CP_WAIT1()  asm volatile("cp.async.wait_group 1;" ::: "memory")
#define CP_WAIT2()  asm volatile("cp.async.wait_group 2;" ::: "memory")

// ======================================================================
// RoPE cos/sin tables
// ======================================================================
__global__ void build_tab(float* __restrict__ ct, float* __restrict__ st)
{
    int idx = blockIdx.x * blockDim.x + threadIdx.x;
    int s = idx >> 5, i = idx & 31;
    double inv = pow(10000.0, -((double)(2 * i)) / (double)HDh);
    double sd, cd;
    sincos((double)s * inv, &sd, &cd);
    ct[idx] = (float)cd;
    st[idx] = (float)sd;
}

// ======================================================================
// permA: src [M,K] fp32 row-major -> fp16 A-frag layout.
// ======================================================================
__global__ __launch_bounds__(256) void permA(
    const float* __restrict__ A, uint32_t* __restrict__ D, int K)
{
    __shared__ float ts[64][68];
    const int r0 = blockIdx.x * 64, c0 = blockIdx.y * 64;
    const int tid = threadIdx.x;
#pragma unroll
    for (int i = 0; i < 4; i++) {
        int f = tid + i * 256;
        int r = f >> 4, c4 = (f & 15) << 2;
        *(float4*)&ts[r][c4] = *(const float4*)(A + (size_t)(r0 + r) * K + c0 + c4);
    }
    __syncthreads();
    const int w = tid >> 5, l = tid & 31;
    const int gid = l >> 2, sub = l & 3;
    const int mi = w >> 1;
#pragma unroll
    for (int jj = 0; jj < 2; jj++) {
        int j = (w & 1) * 2 + jj;
        int r = mi * 16 + gid, d = j * 16 + 2 * sub;
        uint4 o = make_uint4(
            pk(ts[r][d],         ts[r][d + 1]),
            pk(ts[r + 8][d],     ts[r + 8][d + 1]),
            pk(ts[r][d + 8],     ts[r][d + 9]),
            pk(ts[r + 8][d + 8], ts[r + 8][d + 9]));
        *(uint4*)(D + ((size_t)(r0 / 16 + mi) * (K / 16) + (c0 / 16 + j)) * 128 + l * 4) = o;
    }
}

// ======================================================================
// permB: src [N,K=Dd] fp32 row-major -> fp16 B-frag layout.
// ======================================================================
__global__ __launch_bounds__(256) void permB(
    const float* __restrict__ W, uint32_t* __restrict__ D)
{
    __shared__ float ts[64][68];
    const int n0 = blockIdx.x * 64, k0 = blockIdx.y * 64;
    const int tid = threadIdx.x;
#pragma unroll
    for (int i = 0; i < 4; i++) {
        int f = tid + i * 256;
        int r = f >> 4, c4 = (f & 15) << 2;
        *(float4*)&ts[r][c4] = *(const float4*)(W + (size_t)(n0 + r) * Dd + k0 + c4);
    }
    __syncthreads();
    const int w = tid >> 5, l = tid & 31;
    const int gid = l >> 2, sub = l & 3;
#pragma unroll
    for (int j = 0; j < 4; j++) {
        int n = w * 8 + gid, d = j * 16 + 2 * sub;
        uint2 o = make_uint2(pk(ts[n][d],     ts[n][d + 1]),
                             pk(ts[n][d + 8], ts[n][d + 9]));
        *(uint2*)(D + ((size_t)(n0 / 8 + w) * (Dd / 16) + (k0 / 16 + j)) * 64 + l * 2) = o;
    }
}

// ======================================================================
// GEMM mainloop: CTA 128x128, 256 thr, 8 warps of 32x64 (warp tile
// aligned to a 64-col head). K = Dd, 16 chunks of 64, 3-stage cp.async.
// smem: A[3][4096] | B[3][4096] words = 96 KB.
// ======================================================================
#define GEMM_SMEM 98304

__device__ __forceinline__ void gemm_main(
    const uint32_t* __restrict__ Ab, const uint32_t* __restrict__ Bp,
    uint32_t* smu, float acc[2][8][4])
{
    const uint32_t sb = smem_u32(smu);
    const int tid = threadIdx.x;
    const int w = tid >> 5, lane = tid & 31;
    const int wm = w >> 1, wn = w & 1;

    const uint32_t* srca[4];
    const uint32_t* srcw[4];
#pragma unroll
    for (int i = 0; i < 4; i++) {
        int f = tid + i * 256;
        int ba = f >> 5, wa = f & 31;
        srca[i] = Ab + ((size_t)(ba >> 2) * (Dd / 16) + (ba & 3)) * 128 + wa * 4;
        int bw = f >> 4, wb = f & 15;
        srcw[i] = Bp + ((size_t)(bw >> 2) * (Dd / 16) + (bw & 3)) * 64 + wb * 4;
    }
#pragma unroll
    for (int mi = 0; mi < 2; mi++)
#pragma unroll
        for (int ni = 0; ni < 8; ni++)
#pragma unroll
            for (int cc = 0; cc < 4; cc++) acc[mi][ni][cc] = 0.0f;

#define GISSUE(c) do { int _b = (c) % 3; \
    _Pragma("unroll") \
    for (int i = 0; i < 4; i++) { int f = tid + i * 256; \
        cp16(sb + (_b * 4096 + f * 4) * 4, srca[i] + (size_t)(c) * 512); \
        cp16(sb + (12288 + _b * 4096 + f * 4) * 4, srcw[i] + (size_t)(c) * 256); } \
    CP_COMMIT(); } while (0)

    GISSUE(0);
    GISSUE(1);
    for (int c = 0; c < 16; c++) {
        if (c + 1 < 16) { CP_WAIT1(); } else { CP_WAIT0(); }
        __syncthreads();
        if (c + 2 < 16) GISSUE(c + 2);
        const uint32_t* As = smu + (c % 3) * 4096;
        const uint32_t* Ws = smu + 12288 + (c % 3) * 4096;
#pragma unroll
        for (int ks = 0; ks < 4; ks++) {
            uint32_t a[2][4];
#pragma unroll
            for (int mi = 0; mi < 2; mi++) {
                uint4 av = *((const uint4*)(As + ((wm * 2 + mi) * 4 + ks) * 128) + lane);
                a[mi][0] = av.x; a[mi][1] = av.y; a[mi][2] = av.z; a[mi][3] = av.w;
            }
#pragma unroll
            for (int ni = 0; ni < 8; ni++) {
                uint2 bv = *((const uint2*)(Ws + ((wn * 8 + ni) * 4 + ks) * 64) + lane);
                mma16(acc[0][ni], a[0], bv.x, bv.y);
                mma16(acc[1][ni], a[1], bv.x, bv.y);
            }
        }
    }
#undef GISSUE
}

// ======================================================================
// Fused qkv projections. z=0: Q = x@wq^T + RoPE -> Qp (A-frag per bh).
// z=1: K likewise -> Kp (B-frag). z=2: V computed TRANSPOSED
// (A=wv A-frag, B=x B-frag) -> Vp (B-frag, k=s, n=d) lane-locally.
// ======================================================================
__global__ void __launch_bounds__(256, 2) gemm_qkv()
{
    extern __shared__ uint32_t smu[];
    const int z = blockIdx.z;
    int row0, col0;
    const uint32_t *Ab, *Bp;
    if (z == 2) {
        row0 = blockIdx.x * 128;                 // over Dd (V out-dim)
        col0 = blockIdx.y * 128;                 // over Mm (s)
        Ab = g_wvA + (size_t)(row0 >> 4) * (Dd / 16) * 128;
        Bp = g_xB  + (size_t)(col0 >> 3) * (Dd / 16) * 64;
    } else {
        row0 = blockIdx.y * 128;                 // over Mm (s)
        col0 = blockIdx.x * 128;                 // over Dd
        Ab = g_xA + (size_t)(row0 >> 4) * (Dd / 16) * 128;
        Bp = ((z == 0) ? g_wqB : g_wkB) + (size_t)(col0 >> 3) * (Dd / 16) * 64;
    }

    float acc[2][8][4];
    gemm_main(Ab, Bp, smu, acc);

    const int tid = threadIdx.x;
    const int w = tid >> 5, lane = tid & 31;
    const int gid = lane >> 2, sub = lane & 3;
    const int wm = w >> 1, wn = w & 1;

    if (z == 2) {
        // Vp: lane-local packing of the transposed accumulator
        const int bb = col0 >> 11;
        const int sB = (col0 & 2047) + wn * 64;
        const int dW = row0 + wm * 32;
        const int bh = bb * 16 + (dW >> 6);
        const int hd8b = (dW & 63) >> 3;
        uint32_t* dst = g_vp + (size_t)bh * 65536;
#pragma unroll
        for (int d8 = 0; d8 < 4; d8++) {
            int mi = d8 >> 1, hh = d8 & 1;
#pragma unroll
            for (int s16 = 0; s16 < 4; s16++) {
                uint2 o = make_uint2(
                    pk(acc[mi][2 * s16][2 * hh],     acc[mi][2 * s16][2 * hh + 1]),
                    pk(acc[mi][2 * s16 + 1][2 * hh], acc[mi][2 * s16 + 1][2 * hh + 1]));
                *(uint2*)(dst + ((size_t)((sB >> 4) + s16) * 8 + hd8b + d8) * 64 + lane * 2) = o;
            }
        }
        return;
    }

    // z 0/1: RoPE in registers (pair d, d+32 = acc[..][ni], acc[..][ni+4])
    const int bb = row0 >> 11;
    const int sB = (row0 & 2047) + wm * 32;
    const int bh = bb * 16 + (col0 >> 6) + wn;
#pragma unroll
    for (int mi = 0; mi < 2; mi++) {
#pragma unroll
        for (int hh = 0; hh < 2; hh++) {
            int s = sB + mi * 16 + gid + 8 * hh;
#pragma unroll
            for (int ni = 0; ni < 4; ni++) {
                float2 c2 = *(const float2*)&g_cos[s * 32 + ni * 8 + 2 * sub];
                float2 s2 = *(const float2*)&g_sin[s * 32 + ni * 8 + 2 * sub];
                {
                    int cc = 2 * hh;
                    float x1 = acc[mi][ni][cc], x2 = acc[mi][ni + 4][cc];
                    acc[mi][ni][cc]     = x1 * c2.x - x2 * s2.x;
                    acc[mi][ni + 4][cc] = x2 * c2.x + x1 * s2.x;
                }
                {
                    int cc = 2 * hh + 1;
                    float x1 = acc[mi][ni][cc], x2 = acc[mi][ni + 4][cc];
                    acc[mi][ni][cc]     = x1 * c2.y - x2 * s2.y;
                    acc[mi][ni + 4][cc] = x2 * c2.y + x1 * s2.y;
                }
            }
        }
    }

    if (z == 0) {
        uint32_t* dst = g_qp + (size_t)bh * 65536;
#pragma unroll
        for (int mi = 0; mi < 2; mi++) {
#pragma unroll
            for (int j = 0; j < 4; j++) {
                uint4 o = make_uint4(
                    pk(acc[mi][2 * j][0],     acc[mi][2 * j][1]),
                    pk(acc[mi][2 * j][2],     acc[mi][2 * j][3]),
                    pk(acc[mi][2 * j + 1][0], acc[mi][2 * j + 1][1]),
                    pk(acc[mi][2 * j + 1][2], acc[mi][2 * j + 1][3]));
                *(uint4*)(dst + ((size_t)((sB >> 4) + mi) * 4 + j) * 128 + lane * 4) = o;
            }
        }
    } else {
        uint32_t* dst = g_kp + (size_t)bh * 65536;
#pragma unroll
        for (int s8 = 0; s8 < 4; s8++) {
            int mi = s8 >> 1, hh = s8 & 1;
#pragma unroll
            for (int j = 0; j < 4; j++) {
                uint2 o = make_uint2(
                    pk(acc[mi][2 * j][2 * hh],     acc[mi][2 * j][2 * hh + 1]),
                    pk(acc[mi][2 * j + 1][2 * hh], acc[mi][2 * j + 1][2 * hh + 1]));
                *(uint2*)(dst + ((size_t)((sB >> 3) + s8) * 4 + j) * 64 + lane * 2) = o;
            }
        }
    }
}

// ======================================================================
// Output projection: out = Op @ wo^T (fp32 row-major result)
// ======================================================================
__global__ void __launch_bounds__(256, 2) gemm_o(float* __restrict__ C)
{
    extern __shared__ uint32_t smu[];
    const int row0 = blockIdx.y * 128, col0 = blockIdx.x * 128;
    const uint32_t* Ab = g_op  + (size_t)(row0 >> 4) * (Dd / 16) * 128;
    const uint32_t* Bp = g_woB + (size_t)(col0 >> 3) * (Dd / 16) * 64;

    float acc[2][8][4];
    gemm_main(Ab, Bp, smu, acc);

    const int tid = threadIdx.x;
    const int w = tid >> 5, lane = tid & 31;
    const int gid = lane >> 2, sub = lane & 3;
    const int wm = w >> 1, wn = w & 1;
#pragma unroll
    for (int mi = 0; mi < 2; mi++) {
        int row = row0 + wm * 32 + mi * 16 + gid;
#pragma unroll
        for (int ni = 0; ni < 8; ni++) {
            int col = col0 + wn * 64 + ni * 8 + 2 * sub;
            *(float2*)(C + (size_t)row * Dd + col) =
                make_float2(acc[mi][ni][0], acc[mi][ni][1]);
            *(float2*)(C + (size_t)(row + 8) * Dd + col) =
                make_float2(acc[mi][ni][2], acc[mi][ni][3]);
        }
    }
}

// ======================================================================
// Flash attention, causal, fp16 m16n8k16, frag-permuted operands.
// CTA: 128 q-rows of one (b,h); 4 warps x (32 q-rows, 64 cols).
// 3-stage cp.async on K,V. smem: Q 4096 | K[3][2048] | V[3][2048] = 64KB.
// ======================================================================
#define FQ 0
#define FK(b) (4096 + (b)*2048)
#define FV(b) (10240 + (b)*2048)
#define FA_SMEM (16384*4)
#define SCL 0.180336877f    // 0.125 * log2(e)

__global__ void __launch_bounds__(128, 2) flash_tc()
{
    extern __shared__ uint32_t smu[];
    const uint32_t sb = smem_u32(smu);

    const int tid = threadIdx.x;
    const int w = tid >> 5, lane = tid & 31;
    const int gid = lane >> 2, sub = lane & 3;

    const int bh = blockIdx.y;
    const int bb = bh >> 4, h = bh & 15;
    const int qt = gridDim.x - 1 - blockIdx.x;
    const int q0 = qt * 128;

    const size_t bho = (size_t)bh * 65536;
    const uint32_t* Qg = g_qp + bho + (size_t)qt * 4096;
    const uint32_t* Kg = g_kp + bho;
    const uint32_t* Vg = g_vp + bho;
    const int nkt = 2 * qt + 2;

#pragma unroll
    for (int i = 0; i < 8; i++) {
        int f = tid + i * 128;
        cp16(sb + (FQ + f * 4) * 4, Qg + f * 4);
    }
    CP_COMMIT();
#pragma unroll
    for (int i = 0; i < 4; i++) {
        int f = tid + i * 128;
        cp16(sb + (FK(0) + f * 4) * 4, Kg + f * 4);
        cp16(sb + (FV(0) + f * 4) * 4, Vg + f * 4);
    }
    CP_COMMIT();
#pragma unroll
    for (int i = 0; i < 4; i++) {
        int f = tid + i * 128;
        cp16(sb + (FK(1) + f * 4) * 4, Kg + 2048 + f * 4);
        cp16(sb + (FV(1) + f * 4) * 4, Vg + 2048 + f * 4);
    }
    CP_COMMIT();

    CP_WAIT2();          // Q resident
    __syncthreads();

    uint32_t qf[2][4][4];
#pragma unroll
    for (int mi = 0; mi < 2; mi++)
#pragma unroll
        for (int ks = 0; ks < 4; ks++) {
            uint4 av = *((const uint4*)(smu + FQ + ((w * 2 + mi) * 4 + ks) * 128) + lane);
            qf[mi][ks][0] = av.x; qf[mi][ks][1] = av.y;
            qf[mi][ks][2] = av.z; qf[mi][ks][3] = av.w;
        }

    float m_i[2][2], l_i[2][2];
    float acc[2][8][4];
#pragma unroll
    for (int mi = 0; mi < 2; mi++) {
        m_i[mi][0] = -1e30f; m_i[mi][1] = -1e30f;
        l_i[mi][0] = 0.0f;   l_i[mi][1] = 0.0f;
#pragma unroll
        for (int ni = 0; ni < 8; ni++)
#pragma unroll
            for (int cc = 0; cc < 4; cc++) acc[mi][ni][cc] = 0.0f;
    }

    for (int kb = 0; kb < nkt; kb++) {
        const int b = kb % 3;
        const uint32_t* Ks = smu + FK(b);
        const uint32_t* Vs = smu + FV(b);

        if (kb + 1 < nkt) { CP_WAIT1(); } else { CP_WAIT0(); }
        __syncthreads();

        if (kb + 2 < nkt) {
            const int b2 = (kb + 2) % 3;
            const uint32_t* Kn = Kg + (size_t)(kb + 2) * 2048;
            const uint32_t* Vn = Vg + (size_t)(kb + 2) * 2048;
#pragma unroll
            for (int i = 0; i < 4; i++) {
                int f = tid + i * 128;
                cp16(sb + (FK(b2) + f * 4) * 4, Kn + f * 4);
                cp16(sb + (FV(b2) + f * 4) * 4, Vn + f * 4);
            }
            CP_COMMIT();
        }

        if (kb == 2 * qt + 1 && w < 2) continue;   // fully-masked warps

        // ---- S = Q K^T ----
        float s[2][8][4];
#pragma unroll
        for (int mi = 0; mi < 2; mi++)
#pragma unroll
            for (int ni = 0; ni < 8; ni++)
#pragma unroll
                for (int cc = 0; cc < 4; cc++) s[mi][ni][cc] = 0.0f;

#pragma unroll
        for (int ks = 0; ks < 4; ks++) {
#pragma unroll
            for (int ni = 0; ni < 8; ni++) {
                uint2 bv = *((const uint2*)(Ks + (ni * 4 + ks) * 64) + lane);
                mma16(s[0][ni], qf[0][ks], bv.x, bv.y);
                mma16(s[1][ni], qf[1][ks], bv.x, bv.y);
            }
        }

        // ---- scale + causal mask + online softmax (log2 domain) ----
        const int k0 = kb * 64;
        const bool mt = (kb >= 2 * qt);
        uint32_t pa[2][4][4];
#pragma unroll
        for (int mi = 0; mi < 2; mi++) {
            const int r0g = q0 + w * 32 + mi * 16 + gid;
            float rmax[2] = {-1e30f, -1e30f};
#pragma unroll
            for (int ni = 0; ni < 8; ni++) {
                int colb = k0 + ni * 8 + 2 * sub;
#pragma unroll
                for (int cc = 0; cc < 4; cc++) {
                    float sv = s[mi][ni][cc] * SCL;
                    if (mt) {
                        int row = r0g + ((cc >> 1) << 3);
                        int col = colb + (cc & 1);
                        if (col > row) sv = -1e30f;
                    }
                    s[mi][ni][cc] = sv;
                    rmax[cc >> 1] = fmaxf(rmax[cc >> 1], sv);
                }
            }
#pragma unroll
            for (int o = 1; o <= 2; o <<= 1) {
                rmax[0] = fmaxf(rmax[0], __shfl_xor_sync(0xffffffffu, rmax[0], o));
                rmax[1] = fmaxf(rmax[1], __shfl_xor_sync(0xffffffffu, rmax[1], o));
            }
            float mnew0 = fmaxf(m_i[mi][0], rmax[0]);
            float mnew1 = fmaxf(m_i[mi][1], rmax[1]);
            float corr0 = exp2f(m_i[mi][0] - mnew0);
            float corr1 = exp2f(m_i[mi][1] - mnew1);
            m_i[mi][0] = mnew0; m_i[mi][1] = mnew1;

            float rsum[2] = {0.0f, 0.0f};
#pragma unroll
            for (int ni = 0; ni < 8; ni++) {
                s[mi][ni][0] = exp2f(s[mi][ni][0] - mnew0);
                s[mi][ni][1] = exp2f(s[mi][ni][1] - mnew0);
                s[mi][ni][2] = exp2f(s[mi][ni][2] - mnew1);
                s[mi][ni][3] = exp2f(s[mi][ni][3] - mnew1);
                rsum[0] += s[mi][ni][0] + s[mi][ni][1];
                rsum[1] += s[mi][ni][2] + s[mi][ni][3];
                acc[mi][ni][0] *= corr0; acc[mi][ni][1] *= corr0;
                acc[mi][ni][2] *= corr1; acc[mi][ni][3] *= corr1;
            }
#pragma unroll
            for (int o = 1; o <= 2; o <<= 1) {
                rsum[0] += __shfl_xor_sync(0xffffffffu, rsum[0], o);
                rsum[1] += __shfl_xor_sync(0xffffffffu, rsum[1], o);
            }
            l_i[mi][0] = l_i[mi][0] * corr0 + rsum[0];
            l_i[mi][1] = l_i[mi][1] * corr1 + rsum[1];

            // P -> A-fragments directly in registers
#pragma unroll
            for (int j = 0; j < 4; j++) {
                pa[mi][j][0] = pk(s[mi][2 * j][0],     s[mi][2 * j][1]);
                pa[mi][j][1] = pk(s[mi][2 * j][2],     s[mi][2 * j][3]);
                pa[mi][j][2] = pk(s[mi][2 * j + 1][0], s[mi][2 * j + 1][1]);
                pa[mi][j][3] = pk(s[mi][2 * j + 1][2], s[mi][2 * j + 1][3]);
            }
        }

        // ---- O += P V ----
#pragma unroll
        for (int j = 0; j < 4; j++) {
#pragma unroll
            for (int ni = 0; ni < 8; ni++) {
                uint2 bv = *((const uint2*)(Vs + (j * 8 + ni) * 64) + lane);
                mma16(acc[0][ni], pa[0][j], bv.x, bv.y);
                mma16(acc[1][ni], pa[1][j], bv.x, bv.y);
            }
        }
    }

    // ---- normalize, write Op in GLOBAL fp16 A-frag layout ----
#pragma unroll
    for (int mi = 0; mi < 2; mi++) {
        int m16 = bb * 128 + qt * 8 + w * 2 + mi;
        float inv0 = 1.0f / l_i[mi][0];
        float inv1 = 1.0f / l_i[mi][1];
#pragma unroll
        for (int j = 0; j < 4; j++) {
            uint4 o = make_uint4(
                pk(acc[mi][2 * j][0] * inv0,     acc[mi][2 * j][1] * inv0),
                pk(acc[mi][2 * j][2] * inv1,     acc[mi][2 * j][3] * inv1),
                pk(acc[mi][2 * j + 1][0] * inv0, acc[mi][2 * j + 1][1] * inv0),
                pk(acc[mi][2 * j + 1][2] * inv1, acc[mi][2 * j + 1][3] * inv1));
            *(uint4*)(g_op + ((size_t)m16 * (Dd / 16) + h * 4 + j) * 128 + lane * 4) = o;
        }
    }
}

// ======================================================================
// Launch
// ======================================================================
extern "C" void kernel_launch(void* const* d_in, const int* in_sizes, int n_in,
                              void* d_out, int out_size)
{
    const float* x  = (const float*)d_in[0];
    const float* wq = (const float*)d_in[1];
    const float* wk = (const float*)d_in[2];
    const float* wv = (const float*)d_in[3];
    const float* wo = (const float*)d_in[4];
    float* out = (float*)d_out;

    float *tc, *ts;
    uint32_t *xA, *xB, *wqB, *wkB, *woB, *wvA;
    cudaGetSymbolAddress((void**)&xA,  g_xA);
    cudaGetSymbolAddress((void**)&xB,  g_xB);
    cudaGetSymbolAddress((void**)&wqB, g_wqB);
    cudaGetSymbolAddress((void**)&wkB, g_wkB);
    cudaGetSymbolAddress((void**)&woB, g_woB);
    cudaGetSymbolAddress((void**)&wvA, g_wvA);
    cudaGetSymbolAddress((void**)&tc,  g_cos);
    cudaGetSymbolAddress((void**)&ts,  g_sin);

    cudaFuncSetAttribute(gemm_qkv, cudaFuncAttributeMaxDynamicSharedMemorySize, GEMM_SMEM);
    cudaFuncSetAttribute(gemm_o,   cudaFuncAttributeMaxDynamicSharedMemorySize, GEMM_SMEM);
    cudaFuncSetAttribute(flash_tc, cudaFuncAttributeMaxDynamicSharedMemorySize, FA_SMEM);

    // 0) tables + operand permutes (all coalesced, tf-free fp16 RN)
    build_tab<<<(Ss * 32) / 256, 256>>>(tc, ts);
    permA<<<dim3(Mm / 64, Dd / 64), 256>>>(x,  xA,  Dd);
    permA<<<dim3(Dd / 64, Dd / 64), 256>>>(wv, wvA, Dd);
    permB<<<dim3(Mm / 64, Dd / 64), 256>>>(x,  xB);
    permB<<<dim3(Dd / 64, Dd / 64), 256>>>(wq, wqB);
    permB<<<dim3(Dd / 64, Dd / 64), 256>>>(wk, wkB);
    permB<<<dim3(Dd / 64, Dd / 64), 256>>>(wo, woB);

    // 1) fused q/k/v projections + RoPE + frag-permute epilogues
    gemm_qkv<<<dim3(Dd / 128, Mm / 128, 3), 256, GEMM_SMEM>>>();

    // 2) causal flash attention
    flash_tc<<<dim3(Ss / 128, Bb * Hh), 128, FA_SMEM>>>();

    // 3) output projection
    gemm_o<<<dim3(Dd / 128, Mm / 128), 256, GEMM_SMEM>>>(out);
}

// round 10
// speedup vs baseline: 9.6173x; 1.1015x over previous
#include <cuda_runtime.h>
#include <cuda_fp16.h>
#include <math.h>
#include <stdint.h>

// Problem constants
#define Bb 2
#define Ss 2048
#define Dd 1024
#define Hh 16
#define HDh 64
#define Mm (Bb*Ss)   // 4096

// Scratch (device globals), all fp16-packed uint32 unless noted
__device__ uint32_t g_xA[Mm*Dd/2];     // x, A-frag
__device__ uint32_t g_xB[Mm*Dd/2];     // x, B-frag (n=s)
__device__ uint32_t g_wqB[Dd*Dd/2];
__device__ uint32_t g_wkB[Dd*Dd/2];
__device__ uint32_t g_woB[Dd*Dd/2];
__device__ uint32_t g_wvA[Dd*Dd/2];    // wv, A-frag (for transposed V gemm)
__device__ uint32_t g_qp[Mm*Dd/2];     // Q per (b,h), A-frag
__device__ uint32_t g_kp[Mm*Dd/2];     // K per (b,h), B-frag (n=s,k=d)
__device__ uint32_t g_vp[Mm*Dd/2];     // V per (b,h), B-frag (k=s,n=d)
__device__ uint32_t g_op[Mm*Dd/2];     // attn out, global A-frag
__device__ float    g_cos[Ss*32];
__device__ float    g_sin[Ss*32];

// ======================================================================
// Helpers
// ======================================================================
__device__ __forceinline__ uint32_t smem_u32(const void* p) {
    uint32_t a;
    asm("{ .reg .u64 t; cvta.to.shared.u64 t, %1; cvt.u32.u64 %0, t; }"
        : "=r"(a) : "l"(p));
    return a;
}
__device__ __forceinline__ uint32_t pk(float a, float b) {
    __half2 h = __floats2half2_rn(a, b);
    return *reinterpret_cast<uint32_t*>(&h);
}
__device__ __forceinline__ void mma16(float* d, const uint32_t* a,
                                      uint32_t b0, uint32_t b1) {
    asm volatile(
        "mma.sync.aligned.m16n8k16.row.col.f32.f16.f16.f32 "
        "{%0,%1,%2,%3}, {%4,%5,%6,%7}, {%8,%9}, {%0,%1,%2,%3};"
        : "+f"(d[0]), "+f"(d[1]), "+f"(d[2]), "+f"(d[3])
        : "r"(a[0]), "r"(a[1]), "r"(a[2]), "r"(a[3]), "r"(b0), "r"(b1));
}
__device__ __forceinline__ void cp16(uint32_t dst, const void* src) {
    asm volatile("cp.async.cg.shared.global [%0], [%1], 16;"
                 :: "r"(dst), "l"(src) : "memory");
}
#define CP_COMMIT() asm volatile("cp.async.commit_group;" ::: "memory")
#define CP_WAIT0()  asm volatile("cp.async.wait_group 0;" ::: "memory")
#define CP_WAIT1()  asm volatile("cp.async.wait_group 1;" ::: "memory")
#define CP_WAIT2()  asm volatile("cp.async.wait_group 2;" ::: "memory")

// ======================================================================
// RoPE cos/sin tables
// ======================================================================
__global__ void build_tab(float* __restrict__ ct, float* __restrict__ st)
{
    int idx = blockIdx.x * blockDim.x + threadIdx.x;
    int s = idx >> 5, i = idx & 31;
    double inv = pow(10000.0, -((double)(2 * i)) / (double)HDh);
    double sd, cd;
    sincos((double)s * inv, &sd, &cd);
    ct[idx] = (float)cd;
    st[idx] = (float)sd;
}

// ======================================================================
// permA: src [M,K] fp32 row-major -> fp16 A-frag layout.
// ======================================================================
__global__ __launch_bounds__(256) void permA(
    const float* __restrict__ A, uint32_t* __restrict__ D, int K)
{
    __shared__ float ts[64][68];
    const int r0 = blockIdx.x * 64, c0 = blockIdx.y * 64;
    const int tid = threadIdx.x;
#pragma unroll
    for (int i = 0; i < 4; i++) {
        int f = tid + i * 256;
        int r = f >> 4, c4 = (f & 15) << 2;
        *(float4*)&ts[r][c4] = *(const float4*)(A + (size_t)(r0 + r) * K + c0 + c4);
    }
    __syncthreads();
    const int w = tid >> 5, l = tid & 31;
    const int gid = l >> 2, sub = l & 3;
    const int mi = w >> 1;
#pragma unroll
    for (int jj = 0; jj < 2; jj++) {
        int j = (w & 1) * 2 + jj;
        int r = mi * 16 + gid, d = j * 16 + 2 * sub;
        uint4 o = make_uint4(
            pk(ts[r][d],         ts[r][d + 1]),
            pk(ts[r + 8][d],     ts[r + 8][d + 1]),
            pk(ts[r][d + 8],     ts[r][d + 9]),
            pk(ts[r + 8][d + 8], ts[r + 8][d + 9]));
        *(uint4*)(D + ((size_t)(r0 / 16 + mi) * (K / 16) + (c0 / 16 + j)) * 128 + l * 4) = o;
    }
}

// ======================================================================
// permB: src [N,K=Dd] fp32 row-major -> fp16 B-frag layout.
// z selects {wq, wk, wo}.
// ======================================================================
__global__ __launch_bounds__(256) void permBw(
    const float* __restrict__ W0, const float* __restrict__ W1,
    const float* __restrict__ W2,
    uint32_t* __restrict__ D0, uint32_t* __restrict__ D1,
    uint32_t* __restrict__ D2)
{
    __shared__ float ts[64][68];
    const float* W = (blockIdx.z == 0) ? W0 : (blockIdx.z == 1) ? W1 : W2;
    uint32_t*    D = (blockIdx.z == 0) ? D0 : (blockIdx.z == 1) ? D1 : D2;
    const int n0 = blockIdx.x * 64, k0 = blockIdx.y * 64;
    const int tid = threadIdx.x;
#pragma unroll
    for (int i = 0; i < 4; i++) {
        int f = tid + i * 256;
        int r = f >> 4, c4 = (f & 15) << 2;
        *(float4*)&ts[r][c4] = *(const float4*)(W + (size_t)(n0 + r) * Dd + k0 + c4);
    }
    __syncthreads();
    const int w = tid >> 5, l = tid & 31;
    const int gid = l >> 2, sub = l & 3;
#pragma unroll
    for (int j = 0; j < 4; j++) {
        int n = w * 8 + gid, d = j * 16 + 2 * sub;
        uint2 o = make_uint2(pk(ts[n][d],     ts[n][d + 1]),
                             pk(ts[n][d + 8], ts[n][d + 9]));
        *(uint2*)(D + ((size_t)(n0 / 8 + w) * (Dd / 16) + (k0 / 16 + j)) * 64 + l * 2) = o;
    }
}

__global__ __launch_bounds__(256) void permBx(
    const float* __restrict__ W, uint32_t* __restrict__ D)
{
    __shared__ float ts[64][68];
    const int n0 = blockIdx.x * 64, k0 = blockIdx.y * 64;
    const int tid = threadIdx.x;
#pragma unroll
    for (int i = 0; i < 4; i++) {
        int f = tid + i * 256;
        int r = f >> 4, c4 = (f & 15) << 2;
        *(float4*)&ts[r][c4] = *(const float4*)(W + (size_t)(n0 + r) * Dd + k0 + c4);
    }
    __syncthreads();
    const int w = tid >> 5, l = tid & 31;
    const int gid = l >> 2, sub = l & 3;
#pragma unroll
    for (int j = 0; j < 4; j++) {
        int n = w * 8 + gid, d = j * 16 + 2 * sub;
        uint2 o = make_uint2(pk(ts[n][d],     ts[n][d + 1]),
                             pk(ts[n][d + 8], ts[n][d + 9]));
        *(uint2*)(D + ((size_t)(n0 / 8 + w) * (Dd / 16) + (k0 / 16 + j)) * 64 + l * 2) = o;
    }
}

// ======================================================================
// GEMM mainloop: CTA 128x128, 256 thr, 8 warps of 32x64 (warp tile
// aligned to a 64-col head). K = Dd, 16 chunks of 64, 3-stage cp.async.
// smem: A[3][4096] | B[3][4096] words = 96 KB.
// ======================================================================
#define GEMM_SMEM 98304

__device__ __forceinline__ void gemm_main(
    const uint32_t* __restrict__ Ab, const uint32_t* __restrict__ Bp,
    uint32_t* smu, float acc[2][8][4])
{
    const uint32_t sb = smem_u32(smu);
    const int tid = threadIdx.x;
    const int w = tid >> 5, lane = tid & 31;
    const int wm = w >> 1, wn = w & 1;

    const uint32_t* srca[4];
    const uint32_t* srcw[4];
#pragma unroll
    for (int i = 0; i < 4; i++) {
        int f = tid + i * 256;
        int ba = f >> 5, wa = f & 31;
        srca[i] = Ab + ((size_t)(ba >> 2) * (Dd / 16) + (ba & 3)) * 128 + wa * 4;
        int bw = f >> 4, wb = f & 15;
        srcw[i] = Bp + ((size_t)(bw >> 2) * (Dd / 16) + (bw & 3)) * 64 + wb * 4;
    }
#pragma unroll
    for (int mi = 0; mi < 2; mi++)
#pragma unroll
        for (int ni = 0; ni < 8; ni++)
#pragma unroll
            for (int cc = 0; cc < 4; cc++) acc[mi][ni][cc] = 0.0f;

#define GISSUE(c) do { int _b = (c) % 3; \
    _Pragma("unroll") \
    for (int i = 0; i < 4; i++) { int f = tid + i * 256; \
        cp16(sb + (_b * 4096 + f * 4) * 4, srca[i] + (size_t)(c) * 512); \
        cp16(sb + (12288 + _b * 4096 + f * 4) * 4, srcw[i] + (size_t)(c) * 256); } \
    CP_COMMIT(); } while (0)

    GISSUE(0);
    GISSUE(1);
    for (int c = 0; c < 16; c++) {
        if (c + 1 < 16) { CP_WAIT1(); } else { CP_WAIT0(); }
        __syncthreads();
        if (c + 2 < 16) GISSUE(c + 2);
        const uint32_t* As = smu + (c % 3) * 4096;
        const uint32_t* Ws = smu + 12288 + (c % 3) * 4096;
#pragma unroll
        for (int ks = 0; ks < 4; ks++) {
            uint32_t a[2][4];
#pragma unroll
            for (int mi = 0; mi < 2; mi++) {
                uint4 av = *((const uint4*)(As + ((wm * 2 + mi) * 4 + ks) * 128) + lane);
                a[mi][0] = av.x; a[mi][1] = av.y; a[mi][2] = av.z; a[mi][3] = av.w;
            }
#pragma unroll
            for (int ni = 0; ni < 8; ni++) {
                uint2 bv = *((const uint2*)(Ws + ((wn * 8 + ni) * 4 + ks) * 64) + lane);
                mma16(acc[0][ni], a[0], bv.x, bv.y);
                mma16(acc[1][ni], a[1], bv.x, bv.y);
            }
        }
    }
#undef GISSUE
}

// ======================================================================
// Fused qkv projections. z=0: Q = x@wq^T + RoPE -> Qp (A-frag per bh).
// z=1: K likewise -> Kp (B-frag). z=2: V computed TRANSPOSED
// (A=wv A-frag, B=x B-frag) -> Vp (B-frag, k=s, n=d) lane-locally.
// ======================================================================
__global__ void __launch_bounds__(256, 2) gemm_qkv()
{
    extern __shared__ uint32_t smu[];
    const int z = blockIdx.z;
    int row0, col0;
    const uint32_t *Ab, *Bp;
    if (z == 2) {
        row0 = blockIdx.x * 128;                 // over Dd (V out-dim)
        col0 = blockIdx.y * 128;                 // over Mm (s)
        Ab = g_wvA + (size_t)(row0 >> 4) * (Dd / 16) * 128;
        Bp = g_xB  + (size_t)(col0 >> 3) * (Dd / 16) * 64;
    } else {
        row0 = blockIdx.y * 128;                 // over Mm (s)
        col0 = blockIdx.x * 128;                 // over Dd
        Ab = g_xA + (size_t)(row0 >> 4) * (Dd / 16) * 128;
        Bp = ((z == 0) ? g_wqB : g_wkB) + (size_t)(col0 >> 3) * (Dd / 16) * 64;
    }

    float acc[2][8][4];
    gemm_main(Ab, Bp, smu, acc);

    const int tid = threadIdx.x;
    const int w = tid >> 5, lane = tid & 31;
    const int gid = lane >> 2, sub = lane & 3;
    const int wm = w >> 1, wn = w & 1;

    if (z == 2) {
        const int bb = col0 >> 11;
        const int sB = (col0 & 2047) + wn * 64;
        const int dW = row0 + wm * 32;
        const int bh = bb * 16 + (dW >> 6);
        const int hd8b = (dW & 63) >> 3;
        uint32_t* dst = g_vp + (size_t)bh * 65536;
#pragma unroll
        for (int d8 = 0; d8 < 4; d8++) {
            int mi = d8 >> 1, hh = d8 & 1;
#pragma unroll
            for (int s16 = 0; s16 < 4; s16++) {
                uint2 o = make_uint2(
                    pk(acc[mi][2 * s16][2 * hh],     acc[mi][2 * s16][2 * hh + 1]),
                    pk(acc[mi][2 * s16 + 1][2 * hh], acc[mi][2 * s16 + 1][2 * hh + 1]));
                *(uint2*)(dst + ((size_t)((sB >> 4) + s16) * 8 + hd8b + d8) * 64 + lane * 2) = o;
            }
        }
        return;
    }

    // z 0/1: RoPE in registers (pair d, d+32 = acc[..][ni], acc[..][ni+4])
    const int bb = row0 >> 11;
    const int sB = (row0 & 2047) + wm * 32;
    const int bh = bb * 16 + (col0 >> 6) + wn;
#pragma unroll
    for (int mi = 0; mi < 2; mi++) {
#pragma unroll
        for (int hh = 0; hh < 2; hh++) {
            int s = sB + mi * 16 + gid + 8 * hh;
#pragma unroll
            for (int ni = 0; ni < 4; ni++) {
                float2 c2 = *(const float2*)&g_cos[s * 32 + ni * 8 + 2 * sub];
                float2 s2 = *(const float2*)&g_sin[s * 32 + ni * 8 + 2 * sub];
                {
                    int cc = 2 * hh;
                    float x1 = acc[mi][ni][cc], x2 = acc[mi][ni + 4][cc];
                    acc[mi][ni][cc]     = x1 * c2.x - x2 * s2.x;
                    acc[mi][ni + 4][cc] = x2 * c2.x + x1 * s2.x;
                }
                {
                    int cc = 2 * hh + 1;
                    float x1 = acc[mi][ni][cc], x2 = acc[mi][ni + 4][cc];
                    acc[mi][ni][cc]     = x1 * c2.y - x2 * s2.y;
                    acc[mi][ni + 4][cc] = x2 * c2.y + x1 * s2.y;
                }
            }
        }
    }

    if (z == 0) {
        uint32_t* dst = g_qp + (size_t)bh * 65536;
#pragma unroll
        for (int mi = 0; mi < 2; mi++) {
#pragma unroll
            for (int j = 0; j < 4; j++) {
                uint4 o = make_uint4(
                    pk(acc[mi][2 * j][0],     acc[mi][2 * j][1]),
                    pk(acc[mi][2 * j][2],     acc[mi][2 * j][3]),
                    pk(acc[mi][2 * j + 1][0], acc[mi][2 * j + 1][1]),
                    pk(acc[mi][2 * j + 1][2], acc[mi][2 * j + 1][3]));
                *(uint4*)(dst + ((size_t)((sB >> 4) + mi) * 4 + j) * 128 + lane * 4) = o;
            }
        }
    } else {
        uint32_t* dst = g_kp + (size_t)bh * 65536;
#pragma unroll
        for (int s8 = 0; s8 < 4; s8++) {
            int mi = s8 >> 1, hh = s8 & 1;
#pragma unroll
            for (int j = 0; j < 4; j++) {
                uint2 o = make_uint2(
                    pk(acc[mi][2 * j][2 * hh],     acc[mi][2 * j][2 * hh + 1]),
                    pk(acc[mi][2 * j + 1][2 * hh], acc[mi][2 * j + 1][2 * hh + 1]));
                *(uint2*)(dst + ((size_t)((sB >> 3) + s8) * 4 + j) * 64 + lane * 2) = o;
            }
        }
    }
}

// ======================================================================
// Output projection: out = Op @ wo^T (fp32 row-major result)
// ======================================================================
__global__ void __launch_bounds__(256, 2) gemm_o(float* __restrict__ C)
{
    extern __shared__ uint32_t smu[];
    const int row0 = blockIdx.y * 128, col0 = blockIdx.x * 128;
    const uint32_t* Ab = g_op  + (size_t)(row0 >> 4) * (Dd / 16) * 128;
    const uint32_t* Bp = g_woB + (size_t)(col0 >> 3) * (Dd / 16) * 64;

    float acc[2][8][4];
    gemm_main(Ab, Bp, smu, acc);

    const int tid = threadIdx.x;
    const int w = tid >> 5, lane = tid & 31;
    const int gid = lane >> 2, sub = lane & 3;
    const int wm = w >> 1, wn = w & 1;
#pragma unroll
    for (int mi = 0; mi < 2; mi++) {
        int row = row0 + wm * 32 + mi * 16 + gid;
#pragma unroll
        for (int ni = 0; ni < 8; ni++) {
            int col = col0 + wn * 64 + ni * 8 + 2 * sub;
            *(float2*)(C + (size_t)row * Dd + col) =
                make_float2(acc[mi][ni][0], acc[mi][ni][1]);
            *(float2*)(C + (size_t)(row + 8) * Dd + col) =
                make_float2(acc[mi][ni][2], acc[mi][ni][3]);
        }
    }
}

// ======================================================================
// Flash attention, causal, fp16 m16n8k16, frag-permuted operands.
// PAIRED q-tiles: each CTA processes tiles {NT-1-bx, bx} -> constant
// 34 iterations per CTA (perfect balance). 4 warps x (32 rows, 64 cols).
// 3-stage cp.async on K,V. smem: Q 4096 | K[3][2048] | V[3][2048] = 64KB.
// ======================================================================
#define FQ 0
#define FK(b) (4096 + (b)*2048)
#define FV(b) (10240 + (b)*2048)
#define FA_SMEM (16384*4)
#define SCL 0.180336877f    // 0.125 * log2(e)
#define NT (Ss/128)         // 16 q-tiles per (b,h)

__global__ void __launch_bounds__(128, 2) flash_tc()
{
    extern __shared__ uint32_t smu[];
    const uint32_t sb = smem_u32(smu);

    const int tid = threadIdx.x;
    const int w = tid >> 5, lane = tid & 31;
    const int gid = lane >> 2, sub = lane & 3;

    const int bh = blockIdx.y;
    const int bb = bh >> 4, h = bh & 15;

    const size_t bho = (size_t)bh * 65536;
    const uint32_t* Kg = g_kp + bho;
    const uint32_t* Vg = g_vp + bho;

#pragma unroll
    for (int t = 0; t < 2; t++) {
        const int qt = t ? (int)blockIdx.x : (NT - 1 - (int)blockIdx.x);
        const int q0 = qt * 128;
        const uint32_t* Qg = g_qp + bho + (size_t)qt * 4096;
        const int nkt = 2 * qt + 2;

        // ---- prolog: Q, then K0/V0, K1/V1 ----
#pragma unroll
        for (int i = 0; i < 8; i++) {
            int f = tid + i * 128;
            cp16(sb + (FQ + f * 4) * 4, Qg + f * 4);
        }
        CP_COMMIT();
#pragma unroll
        for (int i = 0; i < 4; i++) {
            int f = tid + i * 128;
            cp16(sb + (FK(0) + f * 4) * 4, Kg + f * 4);
            cp16(sb + (FV(0) + f * 4) * 4, Vg + f * 4);
        }
        CP_COMMIT();
#pragma unroll
        for (int i = 0; i < 4; i++) {
            int f = tid + i * 128;
            cp16(sb + (FK(1) + f * 4) * 4, Kg + 2048 + f * 4);
            cp16(sb + (FV(1) + f * 4) * 4, Vg + 2048 + f * 4);
        }
        CP_COMMIT();

        CP_WAIT2();          // Q resident
        __syncthreads();

        uint32_t qf[2][4][4];
#pragma unroll
        for (int mi = 0; mi < 2; mi++)
#pragma unroll
            for (int ks = 0; ks < 4; ks++) {
                uint4 av = *((const uint4*)(smu + FQ + ((w * 2 + mi) * 4 + ks) * 128) + lane);
                qf[mi][ks][0] = av.x; qf[mi][ks][1] = av.y;
                qf[mi][ks][2] = av.z; qf[mi][ks][3] = av.w;
            }

        float m_i[2][2], l_i[2][2];
        float acc[2][8][4];
#pragma unroll
        for (int mi = 0; mi < 2; mi++) {
            m_i[mi][0] = -1e30f; m_i[mi][1] = -1e30f;
            l_i[mi][0] = 0.0f;   l_i[mi][1] = 0.0f;
#pragma unroll
            for (int ni = 0; ni < 8; ni++)
#pragma unroll
                for (int cc = 0; cc < 4; cc++) acc[mi][ni][cc] = 0.0f;
        }

        for (int kb = 0; kb < nkt; kb++) {
            const int b = kb % 3;
            const uint32_t* Ks = smu + FK(b);
            const uint32_t* Vs = smu + FV(b);

            if (kb + 1 < nkt) { CP_WAIT1(); } else { CP_WAIT0(); }
            __syncthreads();

            if (kb + 2 < nkt) {
                const int b2 = (kb + 2) % 3;
                const uint32_t* Kn = Kg + (size_t)(kb + 2) * 2048;
                const uint32_t* Vn = Vg + (size_t)(kb + 2) * 2048;
#pragma unroll
                for (int i = 0; i < 4; i++) {
                    int f = tid + i * 128;
                    cp16(sb + (FK(b2) + f * 4) * 4, Kn + f * 4);
                    cp16(sb + (FV(b2) + f * 4) * 4, Vn + f * 4);
                }
                CP_COMMIT();
            }

            if (kb == 2 * qt + 1 && w < 2) continue;   // fully-masked warps

            // ---- S = Q K^T ----
            float s[2][8][4];
#pragma unroll
            for (int mi = 0; mi < 2; mi++)
#pragma unroll
                for (int ni = 0; ni < 8; ni++)
#pragma unroll
                    for (int cc = 0; cc < 4; cc++) s[mi][ni][cc] = 0.0f;

#pragma unroll
            for (int ks = 0; ks < 4; ks++) {
#pragma unroll
                for (int ni = 0; ni < 8; ni++) {
                    uint2 bv = *((const uint2*)(Ks + (ni * 4 + ks) * 64) + lane);
                    mma16(s[0][ni], qf[0][ks], bv.x, bv.y);
                    mma16(s[1][ni], qf[1][ks], bv.x, bv.y);
                }
            }

            // ---- scale + causal mask + online softmax (log2 domain) ----
            const int k0 = kb * 64;
            const bool mt = (kb >= 2 * qt);
            uint32_t pa[2][4][4];
#pragma unroll
            for (int mi = 0; mi < 2; mi++) {
                const int r0g = q0 + w * 32 + mi * 16 + gid;
                float rmax[2] = {-1e30f, -1e30f};
#pragma unroll
                for (int ni = 0; ni < 8; ni++) {
                    int colb = k0 + ni * 8 + 2 * sub;
#pragma unroll
                    for (int cc = 0; cc < 4; cc++) {
                        float sv = s[mi][ni][cc] * SCL;
                        if (mt) {
                            int row = r0g + ((cc >> 1) << 3);
                            int col = colb + (cc & 1);
                            if (col > row) sv = -1e30f;
                        }
                        s[mi][ni][cc] = sv;
                        rmax[cc >> 1] = fmaxf(rmax[cc >> 1], sv);
                    }
                }
#pragma unroll
                for (int o = 1; o <= 2; o <<= 1) {
                    rmax[0] = fmaxf(rmax[0], __shfl_xor_sync(0xffffffffu, rmax[0], o));
                    rmax[1] = fmaxf(rmax[1], __shfl_xor_sync(0xffffffffu, rmax[1], o));
                }
                float mnew0 = fmaxf(m_i[mi][0], rmax[0]);
                float mnew1 = fmaxf(m_i[mi][1], rmax[1]);
                float corr0 = exp2f(m_i[mi][0] - mnew0);
                float corr1 = exp2f(m_i[mi][1] - mnew1);
                m_i[mi][0] = mnew0; m_i[mi][1] = mnew1;

                float rsum[2] = {0.0f, 0.0f};
#pragma unroll
                for (int ni = 0; ni < 8; ni++) {
                    s[mi][ni][0] = exp2f(s[mi][ni][0] - mnew0);
                    s[mi][ni][1] = exp2f(s[mi][ni][1] - mnew0);
                    s[mi][ni][2] = exp2f(s[mi][ni][2] - mnew1);
                    s[mi][ni][3] = exp2f(s[mi][ni][3] - mnew1);
                    rsum[0] += s[mi][ni][0] + s[mi][ni][1];
                    rsum[1] += s[mi][ni][2] + s[mi][ni][3];
                    acc[mi][ni][0] *= corr0; acc[mi][ni][1] *= corr0;
                    acc[mi][ni][2] *= corr1; acc[mi][ni][3] *= corr1;
                }
#pragma unroll
                for (int o = 1; o <= 2; o <<= 1) {
                    rsum[0] += __shfl_xor_sync(0xffffffffu, rsum[0], o);
                    rsum[1] += __shfl_xor_sync(0xffffffffu, rsum[1], o);
                }
                l_i[mi][0] = l_i[mi][0] * corr0 + rsum[0];
                l_i[mi][1] = l_i[mi][1] * corr1 + rsum[1];

                // P -> A-fragments directly in registers
#pragma unroll
                for (int j = 0; j < 4; j++) {
                    pa[mi][j][0] = pk(s[mi][2 * j][0],     s[mi][2 * j][1]);
                    pa[mi][j][1] = pk(s[mi][2 * j][2],     s[mi][2 * j][3]);
                    pa[mi][j][2] = pk(s[mi][2 * j + 1][0], s[mi][2 * j + 1][1]);
                    pa[mi][j][3] = pk(s[mi][2 * j + 1][2], s[mi][2 * j + 1][3]);
                }
            }

            // ---- O += P V ----
#pragma unroll
            for (int j = 0; j < 4; j++) {
#pragma unroll
                for (int ni = 0; ni < 8; ni++) {
                    uint2 bv = *((const uint2*)(Vs + (j * 8 + ni) * 64) + lane);
                    mma16(acc[0][ni], pa[0][j], bv.x, bv.y);
                    mma16(acc[1][ni], pa[1][j], bv.x, bv.y);
                }
            }
        }

        // ---- normalize, write Op in GLOBAL fp16 A-frag layout ----
#pragma unroll
        for (int mi = 0; mi < 2; mi++) {
            int m16 = bb * 128 + qt * 8 + w * 2 + mi;
            float inv0 = 1.0f / l_i[mi][0];
            float inv1 = 1.0f / l_i[mi][1];
#pragma unroll
            for (int j = 0; j < 4; j++) {
                uint4 o = make_uint4(
                    pk(acc[mi][2 * j][0] * inv0,     acc[mi][2 * j][1] * inv0),
                    pk(acc[mi][2 * j][2] * inv1,     acc[mi][2 * j][3] * inv1),
                    pk(acc[mi][2 * j + 1][0] * inv0, acc[mi][2 * j + 1][1] * inv0),
                    pk(acc[mi][2 * j + 1][2] * inv1, acc[mi][2 * j + 1][3] * inv1));
                *(uint4*)(g_op + ((size_t)m16 * (Dd / 16) + h * 4 + j) * 128 + lane * 4) = o;
            }
        }
        __syncthreads();   // smem reuse safe before next tile's prolog
    }
}

// ======================================================================
// Launch
// ======================================================================
extern "C" void kernel_launch(void* const* d_in, const int* in_sizes, int n_in,
                              void* d_out, int out_size)
{
    const float* x  = (const float*)d_in[0];
    const float* wq = (const float*)d_in[1];
    const float* wk = (const float*)d_in[2];
    const float* wv = (const float*)d_in[3];
    const float* wo = (const float*)d_in[4];
    float* out = (float*)d_out;

    float *tc, *ts;
    uint32_t *xA, *xB, *wqB, *wkB, *woB, *wvA;
    cudaGetSymbolAddress((void**)&xA,  g_xA);
    cudaGetSymbolAddress((void**)&xB,  g_xB);
    cudaGetSymbolAddress((void**)&wqB, g_wqB);
    cudaGetSymbolAddress((void**)&wkB, g_wkB);
    cudaGetSymbolAddress((void**)&woB, g_woB);
    cudaGetSymbolAddress((void**)&wvA, g_wvA);
    cudaGetSymbolAddress((void**)&tc,  g_cos);
    cudaGetSymbolAddress((void**)&ts,  g_sin);

    cudaFuncSetAttribute(gemm_qkv, cudaFuncAttributeMaxDynamicSharedMemorySize, GEMM_SMEM);
    cudaFuncSetAttribute(gemm_o,   cudaFuncAttributeMaxDynamicSharedMemorySize, GEMM_SMEM);
    cudaFuncSetAttribute(flash_tc, cudaFuncAttributeMaxDynamicSharedMemorySize, FA_SMEM);

    // 0) tables + operand permutes
    build_tab<<<(Ss * 32) / 256, 256>>>(tc, ts);
    permA<<<dim3(Mm / 64, Dd / 64), 256>>>(x,  xA,  Dd);
    permA<<<dim3(Dd / 64, Dd / 64), 256>>>(wv, wvA, Dd);
    permBx<<<dim3(Mm / 64, Dd / 64), 256>>>(x, xB);
    permBw<<<dim3(Dd / 64, Dd / 64, 3), 256>>>(wq, wk, wo, wqB, wkB, woB);

    // 1) fused q/k/v projections + RoPE + frag-permute epilogues
    gemm_qkv<<<dim3(Dd / 128, Mm / 128, 3), 256, GEMM_SMEM>>>();

    // 2) causal flash attention (balanced paired q-tiles)
    flash_tc<<<dim3(NT / 2, Bb * Hh), 128, FA_SMEM>>>();

    // 3) output projection
    gemm_o<<<dim3(Dd / 128, Mm / 128), 256, GEMM_SMEM>>>(out);
}